// round 11
// baseline (speedup 1.0000x reference)
#include <cuda_runtime.h>
#include <cuda_bf16.h>
#include <math.h>
#include <stdint.h>

typedef __nv_bfloat16 bf16;

#define NTOK 16384
#define CDIM 256
#define HID  1024

// -------- scratch (__device__ globals; no allocations allowed) --------
__device__ float g_xn     [NTOK * CDIM];
__device__ float g_offattn[NTOK * 256];
__device__ float g_xres   [NTOK * CDIM];
__device__ bf16  g_xnb    [NTOK * CDIM];
__device__ bf16  g_vb     [NTOK * CDIM];
__device__ bf16  g_aggb   [NTOK * CDIM];
__device__ bf16  g_yb     [NTOK * CDIM];
__device__ bf16  g_hb     [NTOK * HID];
__device__ bf16  g_h2b    [NTOK * HID];
__device__ bf16  g_wvb    [256 * 256];
__device__ bf16  g_woutb  [256 * 256];
__device__ bf16  g_w1b    [256 * 1024];
__device__ bf16  g_w2b    [1024 * 256];
__device__ float g_wcat   [256 * 256];
__device__ float g_bcat   [256];

__device__ __forceinline__ float gelu_f(float v) {
    return 0.5f * v * (1.0f + erff(v * 0.7071067811865476f));
}

__device__ __forceinline__ uint32_t smem_u32(const void* p) {
    uint32_t a;
    asm("{ .reg .u64 t; cvta.to.shared.u64 t, %1; cvt.u32.u64 %0, t; }" : "=r"(a) : "l"(p));
    return a;
}

__device__ __forceinline__ uint32_t f2tf32(float f) {
    uint32_t r;
    asm("cvt.rna.tf32.f32 %0, %1;" : "=r"(r) : "f"(f));
    return r;
}

// ---------------- merged weight prep (wcat pre-rounded to tf32) --------------
__global__ void prep_kernel(const float* wv, const float* wout, const float* w1,
                            const float* w2, const float* w_off, const float* w_attn,
                            const float* b_off, const float* b_attn,
                            bf16* wvb, bf16* woutb, bf16* w1b, bf16* w2b,
                            float* wcat, float* bcat) {
    int i = blockIdx.x * 256 + threadIdx.x;
    if (i < 65536) { wvb[i] = __float2bfloat16(wv[i]); return; }
    i -= 65536;
    if (i < 65536) { woutb[i] = __float2bfloat16(wout[i]); return; }
    i -= 65536;
    if (i < 262144) { w1b[i] = __float2bfloat16(w1[i]); return; }
    i -= 262144;
    if (i < 262144) { w2b[i] = __float2bfloat16(w2[i]); return; }
    i -= 262144;
    if (i < 65536) {
        int k = i >> 8, col = i & 255;
        float v = (col < 144) ? w_off[k * 144 + col]
                : (col < 216) ? w_attn[k * 72 + (col - 144)] : 0.f;
        wcat[i] = __uint_as_float(f2tf32(v));
        if (k == 0)
            bcat[col] = (col < 144) ? b_off[col]
                      : (col < 216) ? b_attn[col - 144] : 0.f;
    }
}

// ---------------- LayerNorm1: one block per token, dual output ---------------
__global__ void ln1_kernel(const float* __restrict__ x, const float* __restrict__ g,
                           const float* __restrict__ b, float* __restrict__ yf,
                           bf16* __restrict__ yb) {
    int tok = blockIdx.x;
    int c = threadIdx.x;
    float v = x[(size_t)tok * CDIM + c];
    __shared__ float sh[8];
    float s = v;
    #pragma unroll
    for (int o = 16; o; o >>= 1) s += __shfl_xor_sync(0xffffffffu, s, o);
    if ((c & 31) == 0) sh[c >> 5] = s;
    __syncthreads();
    float tot = 0.f;
    #pragma unroll
    for (int i = 0; i < 8; ++i) tot += sh[i];
    float mean = tot * (1.0f / CDIM);
    __syncthreads();
    float d = v - mean;
    float s2 = d * d;
    #pragma unroll
    for (int o = 16; o; o >>= 1) s2 += __shfl_xor_sync(0xffffffffu, s2, o);
    if ((c & 31) == 0) sh[c >> 5] = s2;
    __syncthreads();
    float v2 = 0.f;
    #pragma unroll
    for (int i = 0; i < 8; ++i) v2 += sh[i];
    float var = v2 * (1.0f / CDIM);
    float out = d * rsqrtf(var + 1e-5f) * g[c] + b[c];
    yf[(size_t)tok * CDIM + c] = __uint_as_float(f2tf32(out));
    yb[(size_t)tok * CDIM + c] = __float2bfloat16(out);
}

// ---------------- tf32 GEMM off/attn: 64x128x16 tile, 3-stage ----------------
#define TFA_STR 20
#define TFB_STR 136
#define TFA_SZ  (64 * TFA_STR * 4)          // 5120
#define TFB_SZ  (16 * TFB_STR * 4)          // 8704
#define TF_STG  (TFA_SZ + TFB_SZ)           // 13824
#define TF_SMEM (3 * TF_STG)                // 41472

__global__ __launch_bounds__(256)
void tgemm_offattn(const float* __restrict__ A, const float* __restrict__ Bw,
                   const float* __restrict__ bias, float* __restrict__ C) {
    extern __shared__ char sm_[];
    uint32_t S0 = smem_u32(sm_);
    int t = threadIdx.x;
    int lane = t & 31, warp = t >> 5;
    int wm = (warp & 1) * 32;
    int wn = (warp >> 1) * 32;
    int m0 = blockIdx.y * 64;
    int n0 = blockIdx.x * 128;

    int a_row = t >> 2, a_c4 = (t & 3) * 4;
    const float* Ag = A + (size_t)(m0 + a_row) * 256 + a_c4;
    uint32_t a_s = S0 + (a_row * TFA_STR + a_c4) * 4;

    auto prefetch = [&](int it) {
        int st = it % 3;
        asm volatile("cp.async.cg.shared.global [%0], [%1], 16;"
                     :: "r"(a_s + st * TF_STG), "l"(Ag + it * 16));
        #pragma unroll
        for (int i = 0; i < 2; ++i) {
            int idx = t + i * 256;
            int row = idx >> 5, c4 = (idx & 31) * 4;
            const float* bg = Bw + (size_t)(it * 16 + row) * 256 + n0 + c4;
            uint32_t dst = S0 + TFA_SZ + (row * TFB_STR + c4) * 4 + st * TF_STG;
            asm volatile("cp.async.cg.shared.global [%0], [%1], 16;" :: "r"(dst), "l"(bg));
        }
        asm volatile("cp.async.commit_group;");
    };

    float acc[2][4][4];
    #pragma unroll
    for (int mi = 0; mi < 2; ++mi)
        #pragma unroll
        for (int nj = 0; nj < 4; ++nj)
            #pragma unroll
            for (int r = 0; r < 4; ++r) acc[mi][nj][r] = 0.f;

    const int niter = 16;
    prefetch(0); prefetch(1);

    int lr = lane >> 2, lc = lane & 3;
    for (int it = 0; it < niter; ++it) {
        if (it + 1 < niter) asm volatile("cp.async.wait_group 1;");
        else                asm volatile("cp.async.wait_group 0;");
        __syncthreads();
        if (it + 2 < niter) prefetch(it + 2);

        const uint32_t* As = (const uint32_t*)(sm_ + (it % 3) * TF_STG);
        const uint32_t* Bs = (const uint32_t*)(sm_ + (it % 3) * TF_STG + TFA_SZ);

        #pragma unroll
        for (int kk = 0; kk < 2; ++kk) {
            uint32_t af[2][4];
            #pragma unroll
            for (int mi = 0; mi < 2; ++mi) {
                int rb = wm + mi * 16 + lr;
                af[mi][0] = As[rb * TFA_STR + kk * 8 + lc];
                af[mi][1] = As[(rb + 8) * TFA_STR + kk * 8 + lc];
                af[mi][2] = As[rb * TFA_STR + kk * 8 + lc + 4];
                af[mi][3] = As[(rb + 8) * TFA_STR + kk * 8 + lc + 4];
            }
            #pragma unroll
            for (int nj = 0; nj < 4; ++nj) {
                uint32_t b0 = Bs[(kk * 8 + lc) * TFB_STR + wn + nj * 8 + lr];
                uint32_t b1 = Bs[(kk * 8 + lc + 4) * TFB_STR + wn + nj * 8 + lr];
                #pragma unroll
                for (int mi = 0; mi < 2; ++mi)
                    asm volatile(
                        "mma.sync.aligned.m16n8k8.row.col.f32.tf32.tf32.f32 "
                        "{%0,%1,%2,%3}, {%4,%5,%6,%7}, {%8,%9}, {%0,%1,%2,%3};"
                        : "+f"(acc[mi][nj][0]), "+f"(acc[mi][nj][1]),
                          "+f"(acc[mi][nj][2]), "+f"(acc[mi][nj][3])
                        : "r"(af[mi][0]), "r"(af[mi][1]), "r"(af[mi][2]), "r"(af[mi][3]),
                          "r"(b0), "r"(b1));
            }
        }
    }

    #pragma unroll
    for (int mi = 0; mi < 2; ++mi) {
        #pragma unroll
        for (int nj = 0; nj < 4; ++nj) {
            int r = m0 + wm + mi * 16 + lr;
            int c = n0 + wn + nj * 8 + lc * 2;
            float bx = bias[c], by = bias[c + 1];
            float2 v0 = {acc[mi][nj][0] + bx, acc[mi][nj][1] + by};
            float2 v1 = {acc[mi][nj][2] + bx, acc[mi][nj][3] + by};
            *(float2*)(C + (size_t)r * 256 + c) = v0;
            *(float2*)(C + (size_t)(r + 8) * 256 + c) = v1;
        }
    }
}

// ---------------- bf16 GEMM 128x128x32 (fc1 only), 3-stage -------------------
#define PBM 128
#define PBN 128
#define PBK 32
#define PASTR 80
#define PBSTR 272
#define PA_ST (PBM * PASTR)
#define PB_ST (PBK * PBSTR)
#define PSTG  (PA_ST + PB_ST)
#define PSMEM (3 * PSTG)

template<int EPI>
__global__ __launch_bounds__(256)
void hgemm_kernel(const bf16* __restrict__ A, const bf16* __restrict__ B,
                  const float* __restrict__ bias, const float* __restrict__ resid,
                  void* __restrict__ Cp, int N, int K) {
    extern __shared__ char sm_[];
    uint32_t S0 = smem_u32(sm_);

    int t = threadIdx.x;
    int lane = t & 31, warp = t >> 5;
    int wm = (warp & 3) * 32;
    int wn = (warp >> 2) * 64;
    int m0 = blockIdx.y * PBM;
    int n0 = blockIdx.x * PBN;

    int a_row = t >> 1;
    int a_c16 = (t & 1) * 2;
    const bf16* Ag = A + (size_t)(m0 + a_row) * K + a_c16 * 8;
    uint32_t a_s = S0 + a_row * PASTR + a_c16 * 16;
    int b_row = t >> 3;
    int b_c16 = (t & 7) * 2;
    const bf16* Bg = B + (size_t)b_row * N + n0 + b_c16 * 8;
    uint32_t b_s = S0 + PA_ST + b_row * PBSTR + b_c16 * 16;

    auto prefetch = [&](int chunk) {
        int st = chunk % 3;
        const bf16* ag = Ag + chunk * PBK;
        const bf16* bg = Bg + (size_t)chunk * PBK * N;
        uint32_t sa = a_s + st * PSTG;
        uint32_t sb = b_s + st * PSTG;
        asm volatile("cp.async.cg.shared.global [%0], [%1], 16;" :: "r"(sa), "l"(ag));
        asm volatile("cp.async.cg.shared.global [%0], [%1], 16;" :: "r"(sa + 16), "l"(ag + 8));
        asm volatile("cp.async.cg.shared.global [%0], [%1], 16;" :: "r"(sb), "l"(bg));
        asm volatile("cp.async.cg.shared.global [%0], [%1], 16;" :: "r"(sb + 16), "l"(bg + 8));
        asm volatile("cp.async.commit_group;");
    };

    uint32_t aoff[2], boff[4];
    #pragma unroll
    for (int mi = 0; mi < 2; ++mi)
        aoff[mi] = (wm + mi * 16 + (lane & 15)) * PASTR + (lane >> 4) * 16;
    int tile = lane >> 3;
    #pragma unroll
    for (int ni = 0; ni < 4; ++ni)
        boff[ni] = PA_ST + ((tile & 1) * 8 + (lane & 7)) * PBSTR
                 + (wn + ni * 16 + (tile >> 1) * 8) * 2;

    float acc[2][8][4];
    #pragma unroll
    for (int mi = 0; mi < 2; ++mi)
        #pragma unroll
        for (int nj = 0; nj < 8; ++nj)
            #pragma unroll
            for (int r = 0; r < 4; ++r) acc[mi][nj][r] = 0.f;

    int niter = K / PBK;
    prefetch(0);
    prefetch(1);

    for (int it = 0; it < niter; ++it) {
        if (it + 1 < niter) asm volatile("cp.async.wait_group 1;");
        else                asm volatile("cp.async.wait_group 0;");
        __syncthreads();
        if (it + 2 < niter) prefetch(it + 2);

        uint32_t Sb = S0 + (it % 3) * PSTG;
        #pragma unroll
        for (int kk = 0; kk < 2; ++kk) {
            uint32_t a[2][4];
            #pragma unroll
            for (int mi = 0; mi < 2; ++mi) {
                uint32_t addr = Sb + aoff[mi] + kk * 32;
                asm volatile("ldmatrix.sync.aligned.m8n8.x4.shared.b16 {%0,%1,%2,%3}, [%4];"
                    : "=r"(a[mi][0]), "=r"(a[mi][1]), "=r"(a[mi][2]), "=r"(a[mi][3]) : "r"(addr));
            }
            uint32_t bq[4][4];
            #pragma unroll
            for (int ni = 0; ni < 4; ++ni) {
                uint32_t addr = Sb + boff[ni] + kk * 16 * PBSTR;
                asm volatile("ldmatrix.sync.aligned.m8n8.x4.trans.shared.b16 {%0,%1,%2,%3}, [%4];"
                    : "=r"(bq[ni][0]), "=r"(bq[ni][1]), "=r"(bq[ni][2]), "=r"(bq[ni][3]) : "r"(addr));
            }
            #pragma unroll
            for (int mi = 0; mi < 2; ++mi)
                #pragma unroll
                for (int nj = 0; nj < 8; ++nj) {
                    uint32_t b0 = bq[nj >> 1][(nj & 1) * 2];
                    uint32_t b1 = bq[nj >> 1][(nj & 1) * 2 + 1];
                    asm volatile(
                        "mma.sync.aligned.m16n8k16.row.col.f32.bf16.bf16.f32 "
                        "{%0,%1,%2,%3}, {%4,%5,%6,%7}, {%8,%9}, {%0,%1,%2,%3};"
                        : "+f"(acc[mi][nj][0]), "+f"(acc[mi][nj][1]),
                          "+f"(acc[mi][nj][2]), "+f"(acc[mi][nj][3])
                        : "r"(a[mi][0]), "r"(a[mi][1]), "r"(a[mi][2]), "r"(a[mi][3]),
                          "r"(b0), "r"(b1));
                }
        }
    }

    int r_base = m0 + wm + (lane >> 2);
    int c_base = n0 + wn + (lane & 3) * 2;
    #pragma unroll
    for (int mi = 0; mi < 2; ++mi) {
        #pragma unroll
        for (int nj = 0; nj < 8; ++nj) {
            int r = r_base + mi * 16;
            int c = c_base + nj * 8;
            float bx = bias[c], by = bias[c + 1];
            float o00 = acc[mi][nj][0] + bx;
            float o01 = acc[mi][nj][1] + by;
            float o10 = acc[mi][nj][2] + bx;
            float o11 = acc[mi][nj][3] + by;
            if (EPI == 1) {
                o00 = gelu_f(o00); o01 = gelu_f(o01);
                o10 = gelu_f(o10); o11 = gelu_f(o11);
            }
            if (EPI == 2) {
                const float* rp0 = resid + (size_t)r * N + c;
                const float* rp1 = resid + (size_t)(r + 8) * N + c;
                float* Cf = (float*)Cp;
                float2 v0 = {o00 + rp0[0], o01 + rp0[1]};
                float2 v1 = {o10 + rp1[0], o11 + rp1[1]};
                *(float2*)(Cf + (size_t)r * N + c) = v0;
                *(float2*)(Cf + (size_t)(r + 8) * N + c) = v1;
            } else {
                bf16* Cb = (bf16*)Cp;
                __nv_bfloat162 v0 = {__float2bfloat16(o00), __float2bfloat16(o01)};
                __nv_bfloat162 v1 = {__float2bfloat16(o10), __float2bfloat16(o11)};
                *(__nv_bfloat162*)(Cb + (size_t)r * N + c) = v0;
                *(__nv_bfloat162*)(Cb + (size_t)(r + 8) * N + c) = v1;
            }
        }
    }
}

// ---------------- bf16 GEMM 64x128x32 (v-proj, fc2), 3-stage -----------------
#define H64_A  (64 * PASTR)          // 5120
#define H64_B  (PBK * PBSTR)         // 8704
#define H64_STG (H64_A + H64_B)      // 13824
#define H64_SMEM (3 * H64_STG)       // 41472

template<int EPI>
__global__ __launch_bounds__(256)
void hgemm64_kernel(const bf16* __restrict__ A, const bf16* __restrict__ B,
                    const float* __restrict__ bias, const float* __restrict__ resid,
                    void* __restrict__ Cp, int N, int K) {
    extern __shared__ char sm_[];
    uint32_t S0 = smem_u32(sm_);
    int t = threadIdx.x;
    int lane = t & 31, warp = t >> 5;
    int wm = (warp & 1) * 32;       // 2 warps along M
    int wn = (warp >> 1) * 32;      // 4 warps along N
    int m0 = blockIdx.y * 64;
    int n0 = blockIdx.x * 128;

    // A: 64x32 bf16 -> 1 chunk/thread
    int a_row = t >> 2, a_c16 = t & 3;
    const bf16* Ag = A + (size_t)(m0 + a_row) * K + a_c16 * 8;
    uint32_t a_s = S0 + a_row * PASTR + a_c16 * 16;
    // B: 32x128 bf16 -> 2 chunks/thread
    int b_row = t >> 3;
    int b_c16 = (t & 7) * 2;
    const bf16* Bg = B + (size_t)b_row * N + n0 + b_c16 * 8;
    uint32_t b_s = S0 + H64_A + b_row * PBSTR + b_c16 * 16;

    auto prefetch = [&](int chunk) {
        int st = chunk % 3;
        const bf16* bg = Bg + (size_t)chunk * PBK * N;
        asm volatile("cp.async.cg.shared.global [%0], [%1], 16;"
                     :: "r"(a_s + st * H64_STG), "l"(Ag + chunk * PBK));
        asm volatile("cp.async.cg.shared.global [%0], [%1], 16;" :: "r"(b_s + st * H64_STG), "l"(bg));
        asm volatile("cp.async.cg.shared.global [%0], [%1], 16;" :: "r"(b_s + st * H64_STG + 16), "l"(bg + 8));
        asm volatile("cp.async.commit_group;");
    };

    uint32_t aoff[2], boff[2];
    #pragma unroll
    for (int mi = 0; mi < 2; ++mi)
        aoff[mi] = (wm + mi * 16 + (lane & 15)) * PASTR + (lane >> 4) * 16;
    int tile = lane >> 3;
    #pragma unroll
    for (int ni = 0; ni < 2; ++ni)
        boff[ni] = H64_A + ((tile & 1) * 8 + (lane & 7)) * PBSTR
                 + (wn + ni * 16 + (tile >> 1) * 8) * 2;

    float acc[2][4][4];
    #pragma unroll
    for (int mi = 0; mi < 2; ++mi)
        #pragma unroll
        for (int nj = 0; nj < 4; ++nj)
            #pragma unroll
            for (int r = 0; r < 4; ++r) acc[mi][nj][r] = 0.f;

    int niter = K / PBK;
    prefetch(0); prefetch(1);

    for (int it = 0; it < niter; ++it) {
        if (it + 1 < niter) asm volatile("cp.async.wait_group 1;");
        else                asm volatile("cp.async.wait_group 0;");
        __syncthreads();
        if (it + 2 < niter) prefetch(it + 2);

        uint32_t Sb = S0 + (it % 3) * H64_STG;
        #pragma unroll
        for (int kk = 0; kk < 2; ++kk) {
            uint32_t a[2][4];
            #pragma unroll
            for (int mi = 0; mi < 2; ++mi) {
                uint32_t addr = Sb + aoff[mi] + kk * 32;
                asm volatile("ldmatrix.sync.aligned.m8n8.x4.shared.b16 {%0,%1,%2,%3}, [%4];"
                    : "=r"(a[mi][0]), "=r"(a[mi][1]), "=r"(a[mi][2]), "=r"(a[mi][3]) : "r"(addr));
            }
            uint32_t bq[2][4];
            #pragma unroll
            for (int ni = 0; ni < 2; ++ni) {
                uint32_t addr = Sb + boff[ni] + kk * 16 * PBSTR;
                asm volatile("ldmatrix.sync.aligned.m8n8.x4.trans.shared.b16 {%0,%1,%2,%3}, [%4];"
                    : "=r"(bq[ni][0]), "=r"(bq[ni][1]), "=r"(bq[ni][2]), "=r"(bq[ni][3]) : "r"(addr));
            }
            #pragma unroll
            for (int mi = 0; mi < 2; ++mi)
                #pragma unroll
                for (int nj = 0; nj < 4; ++nj) {
                    uint32_t b0 = bq[nj >> 1][(nj & 1) * 2];
                    uint32_t b1 = bq[nj >> 1][(nj & 1) * 2 + 1];
                    asm volatile(
                        "mma.sync.aligned.m16n8k16.row.col.f32.bf16.bf16.f32 "
                        "{%0,%1,%2,%3}, {%4,%5,%6,%7}, {%8,%9}, {%0,%1,%2,%3};"
                        : "+f"(acc[mi][nj][0]), "+f"(acc[mi][nj][1]),
                          "+f"(acc[mi][nj][2]), "+f"(acc[mi][nj][3])
                        : "r"(a[mi][0]), "r"(a[mi][1]), "r"(a[mi][2]), "r"(a[mi][3]),
                          "r"(b0), "r"(b1));
                }
        }
    }

    int r_base = m0 + wm + (lane >> 2);
    int c_base = n0 + wn + (lane & 3) * 2;
    #pragma unroll
    for (int mi = 0; mi < 2; ++mi) {
        #pragma unroll
        for (int nj = 0; nj < 4; ++nj) {
            int r = r_base + mi * 16;
            int c = c_base + nj * 8;
            float bx = bias[c], by = bias[c + 1];
            float o00 = acc[mi][nj][0] + bx;
            float o01 = acc[mi][nj][1] + by;
            float o10 = acc[mi][nj][2] + bx;
            float o11 = acc[mi][nj][3] + by;
            if (EPI == 2) {
                const float* rp0 = resid + (size_t)r * N + c;
                const float* rp1 = resid + (size_t)(r + 8) * N + c;
                float* Cf = (float*)Cp;
                float2 v0 = {o00 + rp0[0], o01 + rp0[1]};
                float2 v1 = {o10 + rp1[0], o11 + rp1[1]};
                *(float2*)(Cf + (size_t)r * N + c) = v0;
                *(float2*)(Cf + (size_t)(r + 8) * N + c) = v1;
            } else {
                bf16* Cb = (bf16*)Cp;
                __nv_bfloat162 v0 = {__float2bfloat16(o00), __float2bfloat16(o01)};
                __nv_bfloat162 v1 = {__float2bfloat16(o10), __float2bfloat16(o11)};
                *(__nv_bfloat162*)(Cb + (size_t)r * N + c) = v0;
                *(__nv_bfloat162*)(Cb + (size_t)(r + 8) * N + c) = v1;
            }
        }
    }
}

// ======== fused wout GEMM + residual + LN2: 64x256 tile, LN in epilogue ======
#define QBM 64
#define QASTR 80
#define QBSTR 528
#define QA_SZ (QBM * QASTR)
#define QB_SZ (32 * QBSTR)
#define QSTG  (QA_SZ + QB_SZ)
#define QLN_SZ (64 * 264 * 4)
#define QSMEM (QLN_SZ > 3 * QSTG ? QLN_SZ : 3 * QSTG)

__global__ __launch_bounds__(256)
void hgemm_wout_ln(const bf16* __restrict__ A, const bf16* __restrict__ B,
                   const float* __restrict__ bias, const float* __restrict__ resid,
                   float* __restrict__ xres, const float* __restrict__ g2,
                   const float* __restrict__ b2g, bf16* __restrict__ yb) {
    extern __shared__ char sm_[];
    uint32_t S0 = smem_u32(sm_);
    int t = threadIdx.x;
    int lane = t & 31, warp = t >> 5;
    int wm = (warp & 1) * 32;
    int wn = (warp >> 1) * 64;
    int m0 = blockIdx.x * QBM;

    int a_row = t >> 2, a_c16 = t & 3;
    const bf16* Ag = A + (size_t)(m0 + a_row) * 256 + a_c16 * 8;
    uint32_t a_s = S0 + a_row * QASTR + a_c16 * 16;

    auto prefetch = [&](int ck) {
        int st = ck % 3;
        asm volatile("cp.async.cg.shared.global [%0], [%1], 16;"
                     :: "r"(a_s + st * QSTG), "l"(Ag + ck * 32));
        #pragma unroll
        for (int i = 0; i < 4; ++i) {
            int idx = t + i * 256;
            int row = idx >> 5, c16 = idx & 31;
            const bf16* bg = B + (size_t)(ck * 32 + row) * 256 + c16 * 8;
            uint32_t dst = S0 + st * QSTG + QA_SZ + row * QBSTR + c16 * 16;
            asm volatile("cp.async.cg.shared.global [%0], [%1], 16;" :: "r"(dst), "l"(bg));
        }
        asm volatile("cp.async.commit_group;");
    };

    uint32_t aoff[2], boff[4];
    #pragma unroll
    for (int mi = 0; mi < 2; ++mi)
        aoff[mi] = (wm + mi * 16 + (lane & 15)) * QASTR + (lane >> 4) * 16;
    int tile = lane >> 3;
    #pragma unroll
    for (int ni = 0; ni < 4; ++ni)
        boff[ni] = QA_SZ + ((tile & 1) * 8 + (lane & 7)) * QBSTR
                 + (wn + ni * 16 + (tile >> 1) * 8) * 2;

    float acc[2][8][4];
    #pragma unroll
    for (int mi = 0; mi < 2; ++mi)
        #pragma unroll
        for (int nj = 0; nj < 8; ++nj)
            #pragma unroll
            for (int r = 0; r < 4; ++r) acc[mi][nj][r] = 0.f;

    const int niter = 8;
    prefetch(0); prefetch(1);

    for (int it = 0; it < niter; ++it) {
        if (it + 1 < niter) asm volatile("cp.async.wait_group 1;");
        else                asm volatile("cp.async.wait_group 0;");
        __syncthreads();
        if (it + 2 < niter) prefetch(it + 2);

        uint32_t Sb = S0 + (it % 3) * QSTG;
        #pragma unroll
        for (int kk = 0; kk < 2; ++kk) {
            uint32_t a[2][4];
            #pragma unroll
            for (int mi = 0; mi < 2; ++mi) {
                uint32_t addr = Sb + aoff[mi] + kk * 32;
                asm volatile("ldmatrix.sync.aligned.m8n8.x4.shared.b16 {%0,%1,%2,%3}, [%4];"
                    : "=r"(a[mi][0]), "=r"(a[mi][1]), "=r"(a[mi][2]), "=r"(a[mi][3]) : "r"(addr));
            }
            uint32_t bq[4][4];
            #pragma unroll
            for (int ni = 0; ni < 4; ++ni) {
                uint32_t addr = Sb + boff[ni] + kk * 16 * QBSTR;
                asm volatile("ldmatrix.sync.aligned.m8n8.x4.trans.shared.b16 {%0,%1,%2,%3}, [%4];"
                    : "=r"(bq[ni][0]), "=r"(bq[ni][1]), "=r"(bq[ni][2]), "=r"(bq[ni][3]) : "r"(addr));
            }
            #pragma unroll
            for (int mi = 0; mi < 2; ++mi)
                #pragma unroll
                for (int nj = 0; nj < 8; ++nj) {
                    uint32_t b0 = bq[nj >> 1][(nj & 1) * 2];
                    uint32_t b1 = bq[nj >> 1][(nj & 1) * 2 + 1];
                    asm volatile(
                        "mma.sync.aligned.m16n8k16.row.col.f32.bf16.bf16.f32 "
                        "{%0,%1,%2,%3}, {%4,%5,%6,%7}, {%8,%9}, {%0,%1,%2,%3};"
                        : "+f"(acc[mi][nj][0]), "+f"(acc[mi][nj][1]),
                          "+f"(acc[mi][nj][2]), "+f"(acc[mi][nj][3])
                        : "r"(a[mi][0]), "r"(a[mi][1]), "r"(a[mi][2]), "r"(a[mi][3]),
                          "r"(b0), "r"(b1));
                }
        }
    }

    __syncthreads();
    float* lt = (float*)sm_;

    int lr0 = wm + (lane >> 2);
    int cb = wn + (lane & 3) * 2;
    #pragma unroll
    for (int mi = 0; mi < 2; ++mi) {
        #pragma unroll
        for (int nj = 0; nj < 8; ++nj) {
            int rl = lr0 + mi * 16;
            int c = cb + nj * 8;
            float bx = bias[c], by = bias[c + 1];
            const float* rp0 = resid + (size_t)(m0 + rl) * 256 + c;
            const float* rp1 = resid + (size_t)(m0 + rl + 8) * 256 + c;
            float2 v0 = {acc[mi][nj][0] + bx + rp0[0], acc[mi][nj][1] + by + rp0[1]};
            float2 v1 = {acc[mi][nj][2] + bx + rp1[0], acc[mi][nj][3] + by + rp1[1]};
            *(float2*)(xres + (size_t)(m0 + rl) * 256 + c) = v0;
            *(float2*)(xres + (size_t)(m0 + rl + 8) * 256 + c) = v1;
            lt[rl * 264 + c] = v0.x;       lt[rl * 264 + c + 1] = v0.y;
            lt[(rl + 8) * 264 + c] = v1.x; lt[(rl + 8) * 264 + c + 1] = v1.y;
        }
    }
    __syncthreads();

    int colb = lane * 8;
    float gg[8], bb[8];
    #pragma unroll
    for (int j = 0; j < 8; ++j) { gg[j] = g2[colb + j]; bb[j] = b2g[colb + j]; }

    for (int i = 0; i < 8; ++i) {
        int rr = warp * 8 + i;
        const float* rowp = lt + rr * 264 + colb;
        float v[8];
        float s = 0.f;
        #pragma unroll
        for (int j = 0; j < 8; ++j) { v[j] = rowp[j]; s += v[j]; }
        #pragma unroll
        for (int o = 16; o; o >>= 1) s += __shfl_xor_sync(0xffffffffu, s, o);
        float mean = s * (1.0f / 256.0f);
        float s2 = 0.f;
        #pragma unroll
        for (int j = 0; j < 8; ++j) { float d = v[j] - mean; s2 += d * d; }
        #pragma unroll
        for (int o = 16; o; o >>= 1) s2 += __shfl_xor_sync(0xffffffffu, s2, o);
        float inv = rsqrtf(s2 * (1.0f / 256.0f) + 1e-5f);
        bf16 ob[8];
        #pragma unroll
        for (int j = 0; j < 8; ++j)
            ob[j] = __float2bfloat16((v[j] - mean) * inv * gg[j] + bb[j]);
        *(uint4*)(yb + (size_t)(m0 + rr) * 256 + colb) = *(uint4*)ob;
    }
}

// ---------------- Deformable sampling: one warp = (token, head-pair) ---------
__global__ void sample_kernel(const bf16* __restrict__ v, const float* __restrict__ offattn,
                              const float* __restrict__ rp, bf16* __restrict__ agg) {
    int gw = blockIdx.x * 8 + (threadIdx.x >> 5);
    int lane = threadIdx.x & 31;
    int tg = gw >> 2;
    int head = ((gw & 3) << 1) + (lane >> 4);
    int l16 = lane & 15;
    int bb = tg >> 13;
    int pos = tg & 8191;

    const float* lg = offattn + (size_t)tg * 256 + 144 + head * 9;
    float w[9];
    float mx = -1e30f;
    #pragma unroll
    for (int k = 0; k < 9; ++k) { w[k] = lg[k]; mx = fmaxf(mx, w[k]); }
    float sum = 0.f;
    #pragma unroll
    for (int k = 0; k < 9; ++k) { w[k] = expf(w[k] - mx); sum += w[k]; }
    float inv = 1.0f / sum;

    const float* rpp  = rp + (size_t)pos * 18;
    const float* offp = offattn + (size_t)tg * 256 + head * 18;
    const __nv_bfloat162* vc = (const __nv_bfloat162*)v + head * 16 + l16;
    int base = bb << 13;
    float a0 = 0.f, a1 = 0.f;
    #pragma unroll
    for (int k = 0; k < 9; ++k) {
        float cx = (rpp[k * 2 + 0] + offp[k * 2 + 0] + 1.0f) * 0.5f * 127.0f;
        float cy = (rpp[k * 2 + 1] + offp[k * 2 + 1] + 1.0f) * 0.5f * 63.0f;
        float fx = floorf(cx), fy = floorf(cy);
        float wx = cx - fx, wy = cy - fy;
        int x0 = min(max((int)fx, 0), 127);
        int x1 = min(max((int)fx + 1, 0), 127);
        int y0 = min(max((int)fy, 0), 63);
        int y1 = min(max((int)fy + 1, 0), 63);
        float2 v00 = __bfloat1622float2(vc[(size_t)(base + y0 * 128 + x0) * 128]);
        float2 v01 = __bfloat1622float2(vc[(size_t)(base + y0 * 128 + x1) * 128]);
        float2 v10 = __bfloat1622float2(vc[(size_t)(base + y1 * 128 + x0) * 128]);
        float2 v11 = __bfloat1622float2(vc[(size_t)(base + y1 * 128 + x1) * 128]);
        float w00 = (1.f - wy) * (1.f - wx), w01 = (1.f - wy) * wx;
        float w10 = wy * (1.f - wx),         w11 = wy * wx;
        float wk = w[k] * inv;
        a0 += (v00.x * w00 + v01.x * w01 + v10.x * w10 + v11.x * w11) * wk;
        a1 += (v00.y * w00 + v01.y * w01 + v10.y * w10 + v11.y * w11) * wk;
    }
    __nv_bfloat162 ov = {__float2bfloat16(a0), __float2bfloat16(a1)};
    *(__nv_bfloat162*)(agg + (size_t)tg * 256 + head * 32 + l16 * 2) = ov;
}

// ---------------- Depthwise 3x3 conv: sliding window, 4-way x-split ----------
__global__ void dwconv_kernel(const bf16* __restrict__ h, const float* __restrict__ wdw,
                              const float* __restrict__ bdw, bf16* __restrict__ o) {
    int c2 = blockIdx.x * 256 + threadIdx.x;
    int y = blockIdx.y & 63;
    int seg = blockIdx.y >> 6;
    int bb = blockIdx.z;
    int c = c2 * 2;
    int x0 = seg * 32;

    float w0[9], w1[9];
    #pragma unroll
    for (int i = 0; i < 9; ++i) { w0[i] = wdw[c * 9 + i]; w1[i] = wdw[(c + 1) * 9 + i]; }
    float bb0 = bdw[c], bb1 = bdw[c + 1];

    const __nv_bfloat162* hp = (const __nv_bfloat162*)h;
    size_t base = ((size_t)(bb << 13) + y * 128) * 512 + c2;
    bool hu = (y > 0), hd = (y < 63);
    __nv_bfloat162 zero = __float2bfloat162_rn(0.f);

    __nv_bfloat162 cm[3], cc[3], cn[3];
    {
        size_t p = base + ((x0 + 127) & 127) * 512;
        cm[0] = hu ? hp[p - 65536] : zero; cm[1] = hp[p]; cm[2] = hd ? hp[p + 65536] : zero;
        p = base + x0 * 512;
        cc[0] = hu ? hp[p - 65536] : zero; cc[1] = hp[p]; cc[2] = hd ? hp[p + 65536] : zero;
    }
    bf16* op = o + ((size_t)(bb << 13) + y * 128) * 1024 + c;

    for (int x = x0; x < x0 + 32; ++x) {
        size_t p = base + ((x + 1) & 127) * 512;
        cn[0] = hu ? hp[p - 65536] : zero; cn[1] = hp[p]; cn[2] = hd ? hp[p + 65536] : zero;

        float a0 = bb0, a1 = bb1;
        #pragma unroll
        for (int dy = 0; dy < 3; ++dy) {
            float2 vm = __bfloat1622float2(cm[dy]);
            float2 vc = __bfloat1622float2(cc[dy]);
            float2 vp = __bfloat1622float2(cn[dy]);
            a0 += vm.x * w0[dy * 3 + 0] + vc.x * w0[dy * 3 + 1] + vp.x * w0[dy * 3 + 2];
            a1 += vm.y * w1[dy * 3 + 0] + vc.y * w1[dy * 3 + 1] + vp.y * w1[dy * 3 + 2];
        }
        __nv_bfloat162 ov = {__float2bfloat16(gelu_f(a0)), __float2bfloat16(gelu_f(a1))};
        *(__nv_bfloat162*)(op + (size_t)x * 1024) = ov;

        #pragma unroll
        for (int i = 0; i < 3; ++i) { cm[i] = cc[i]; cc[i] = cn[i]; }
    }
}

// ---------------- launch ----------------
extern "C" void kernel_launch(void* const* d_in, const int* in_sizes, int n_in,
                              void* d_out, int out_size) {
    const float* x      = (const float*)d_in[0];
    const float* rp     = (const float*)d_in[1];
    const float* ln1_g  = (const float*)d_in[2];
    const float* ln1_b  = (const float*)d_in[3];
    const float* w_v    = (const float*)d_in[4];
    const float* b_v    = (const float*)d_in[5];
    const float* w_off  = (const float*)d_in[6];
    const float* b_off  = (const float*)d_in[7];
    const float* w_attn = (const float*)d_in[8];
    const float* b_attn = (const float*)d_in[9];
    const float* w_out  = (const float*)d_in[10];
    const float* b_out  = (const float*)d_in[11];
    const float* ln2_g  = (const float*)d_in[12];
    const float* ln2_b  = (const float*)d_in[13];
    const float* w1     = (const float*)d_in[14];
    const float* b1     = (const float*)d_in[15];
    const float* w_dw   = (const float*)d_in[16];
    const float* b_dw   = (const float*)d_in[17];
    const float* w2     = (const float*)d_in[18];
    const float* b2     = (const float*)d_in[19];
    float* out = (float*)d_out;

    float *xn, *offattn, *xres, *wcat, *bcat;
    bf16 *xnb, *vb, *aggb, *yb, *hb, *h2b, *wvb, *woutb, *w1b, *w2b;
    cudaGetSymbolAddress((void**)&xn,      g_xn);
    cudaGetSymbolAddress((void**)&offattn, g_offattn);
    cudaGetSymbolAddress((void**)&xres,    g_xres);
    cudaGetSymbolAddress((void**)&wcat,    g_wcat);
    cudaGetSymbolAddress((void**)&bcat,    g_bcat);
    cudaGetSymbolAddress((void**)&xnb,     g_xnb);
    cudaGetSymbolAddress((void**)&vb,      g_vb);
    cudaGetSymbolAddress((void**)&aggb,    g_aggb);
    cudaGetSymbolAddress((void**)&yb,      g_yb);
    cudaGetSymbolAddress((void**)&hb,      g_hb);
    cudaGetSymbolAddress((void**)&h2b,     g_h2b);
    cudaGetSymbolAddress((void**)&wvb,     g_wvb);
    cudaGetSymbolAddress((void**)&woutb,   g_woutb);
    cudaGetSymbolAddress((void**)&w1b,     g_w1b);
    cudaGetSymbolAddress((void**)&w2b,     g_w2b);

    cudaFuncSetAttribute(hgemm_kernel<1>,   cudaFuncAttributeMaxDynamicSharedMemorySize, PSMEM);
    cudaFuncSetAttribute(hgemm64_kernel<0>, cudaFuncAttributeMaxDynamicSharedMemorySize, H64_SMEM);
    cudaFuncSetAttribute(hgemm64_kernel<2>, cudaFuncAttributeMaxDynamicSharedMemorySize, H64_SMEM);
    cudaFuncSetAttribute(tgemm_offattn,     cudaFuncAttributeMaxDynamicSharedMemorySize, TF_SMEM);
    cudaFuncSetAttribute(hgemm_wout_ln,     cudaFuncAttributeMaxDynamicSharedMemorySize, QSMEM);

    // weight prep
    prep_kernel<<<(655360 + 65536 + 255) / 256, 256>>>(
        w_v, w_out, w1, w2, w_off, w_attn, b_off, b_attn,
        wvb, woutb, w1b, w2b, wcat, bcat);

    // 1. LN1 -> xn (tf32-rounded f32) + xnb (bf16)
    ln1_kernel<<<NTOK, 256>>>(x, ln1_g, ln1_b, xn, xnb);
    // 2. v projection (bf16 TC, 64x128 tile)
    hgemm64_kernel<0><<<dim3(2, NTOK / 64), 256, H64_SMEM>>>(xnb, wvb, b_v, nullptr, vb, 256, 256);
    // 3. offsets+attn combined (tf32 TC, 64x128 tile)
    tgemm_offattn<<<dim3(2, NTOK / 64), 256, TF_SMEM>>>(xn, wcat, bcat, offattn);
    // 4. softmax + bilinear sampling + aggregation (head-pair warps)
    sample_kernel<<<NTOK / 2, 256>>>(vb, offattn, rp, aggb);
    // 5. output proj + residual + LN2 fused -> xres (f32) + yb (bf16)
    hgemm_wout_ln<<<NTOK / QBM, 256, QSMEM>>>(aggb, woutb, b_out, x, xres, ln2_g, ln2_b, yb);
    // 6. fc1 + GELU (bf16 TC, 128x128)
    hgemm_kernel<1><<<dim3(HID / PBN, NTOK / PBM), 256, PSMEM>>>(yb, w1b, b1, nullptr, hb, HID, 256);
    // 7. depthwise conv + GELU
    dwconv_kernel<<<dim3(2, 256, 2), 256>>>(hb, w_dw, b_dw, h2b);
    // 8. fc2 + residual -> out (f32, 64x128 tile)
    hgemm64_kernel<2><<<dim3(2, NTOK / 64), 256, H64_SMEM>>>(h2b, w2b, b2, xres, out, 256, 1024);
}

// round 12
// speedup vs baseline: 1.0132x; 1.0132x over previous
#include <cuda_runtime.h>
#include <cuda_bf16.h>
#include <math.h>
#include <stdint.h>

typedef __nv_bfloat16 bf16;

#define NTOK 16384
#define CDIM 256
#define HID  1024

// -------- scratch (__device__ globals; no allocations allowed) --------
__device__ float g_xn     [NTOK * CDIM];
__device__ float g_offattn[NTOK * 256];
__device__ float g_xres   [NTOK * CDIM];
__device__ bf16  g_xnb    [NTOK * CDIM];
__device__ bf16  g_vb     [NTOK * CDIM];
__device__ bf16  g_aggb   [NTOK * CDIM];
__device__ bf16  g_yb     [NTOK * CDIM];
__device__ bf16  g_hb     [NTOK * HID];
__device__ bf16  g_h2b    [NTOK * HID];
__device__ bf16  g_wvb    [256 * 256];
__device__ bf16  g_woutb  [256 * 256];
__device__ bf16  g_w1b    [256 * 1024];
__device__ bf16  g_w2b    [1024 * 256];
__device__ float g_wcat   [256 * 256];
__device__ float g_bcat   [256];

__device__ __forceinline__ float gelu_f(float v) {
    return 0.5f * v * (1.0f + erff(v * 0.7071067811865476f));
}

__device__ __forceinline__ uint32_t smem_u32(const void* p) {
    uint32_t a;
    asm("{ .reg .u64 t; cvta.to.shared.u64 t, %1; cvt.u32.u64 %0, t; }" : "=r"(a) : "l"(p));
    return a;
}

__device__ __forceinline__ uint32_t f2tf32(float f) {
    uint32_t r;
    asm("cvt.rna.tf32.f32 %0, %1;" : "=r"(r) : "f"(f));
    return r;
}

// ================= K1: fused prep + LN1 (block-range dispatch) =================
__global__ void prep_ln_kernel(
    const float* __restrict__ x, const float* __restrict__ g, const float* __restrict__ b,
    float* __restrict__ xn, bf16* __restrict__ xnb,
    const float* wv, const float* wout, const float* w1, const float* w2,
    const float* w_off, const float* w_attn, const float* b_off, const float* b_attn,
    bf16* wvb, bf16* woutb, bf16* w1b, bf16* w2b, float* wcat, float* bcat) {
    if (blockIdx.x < NTOK) {
        int tok = blockIdx.x;
        int c = threadIdx.x;
        float v = x[(size_t)tok * CDIM + c];
        __shared__ float sh[8];
        float s = v;
        #pragma unroll
        for (int o = 16; o; o >>= 1) s += __shfl_xor_sync(0xffffffffu, s, o);
        if ((c & 31) == 0) sh[c >> 5] = s;
        __syncthreads();
        float tot = 0.f;
        #pragma unroll
        for (int i = 0; i < 8; ++i) tot += sh[i];
        float mean = tot * (1.0f / CDIM);
        __syncthreads();
        float d = v - mean;
        float s2 = d * d;
        #pragma unroll
        for (int o = 16; o; o >>= 1) s2 += __shfl_xor_sync(0xffffffffu, s2, o);
        if ((c & 31) == 0) sh[c >> 5] = s2;
        __syncthreads();
        float v2 = 0.f;
        #pragma unroll
        for (int i = 0; i < 8; ++i) v2 += sh[i];
        float var = v2 * (1.0f / CDIM);
        float out = d * rsqrtf(var + 1e-5f) * g[c] + b[c];
        xn[(size_t)tok * CDIM + c]  = __uint_as_float(f2tf32(out));
        xnb[(size_t)tok * CDIM + c] = __float2bfloat16(out);
        return;
    }
    int i = (blockIdx.x - NTOK) * 256 + threadIdx.x;
    if (i < 65536) { wvb[i] = __float2bfloat16(wv[i]); return; }
    i -= 65536;
    if (i < 65536) { woutb[i] = __float2bfloat16(wout[i]); return; }
    i -= 65536;
    if (i < 262144) { w1b[i] = __float2bfloat16(w1[i]); return; }
    i -= 262144;
    if (i < 262144) { w2b[i] = __float2bfloat16(w2[i]); return; }
    i -= 262144;
    if (i < 65536) {
        int k = i >> 8, col = i & 255;
        float v = (col < 144) ? w_off[k * 144 + col]
                : (col < 216) ? w_attn[k * 72 + (col - 144)] : 0.f;
        wcat[i] = __uint_as_float(f2tf32(v));
        if (k == 0)
            bcat[col] = (col < 144) ? b_off[col]
                      : (col < 216) ? b_attn[col - 144] : 0.f;
    }
}

// ---------------- shared GEMM geometry constants ----------------
#define PBK 32
#define PASTR 80
#define PBSTR 272
// 64x128 stage: A 64 rows x 80B + B 32 rows x 272B
#define H64_A  (64 * PASTR)          // 5120
#define H64_B  (PBK * PBSTR)         // 8704
#define H64_STG (H64_A + H64_B)      // 13824
#define H64_SMEM (3 * H64_STG)       // 41472
// tf32 64x128 stage (same total 13824)
#define TFA_STR 20
#define TFB_STR 136
#define TFA_SZ  (64 * TFA_STR * 4)   // 5120
#define TFB_SZ  (16 * TFB_STR * 4)   // 8704
#define TF_STG  (TFA_SZ + TFB_SZ)    // 13824

// ---------------- tf32 GEMM device body: 64x128x16, 3-stage ------------------
__device__ void tgemm64_dev(char* sm_, int bx, int by,
                            const float* __restrict__ A, const float* __restrict__ Bw,
                            const float* __restrict__ bias, float* __restrict__ C) {
    uint32_t S0 = smem_u32(sm_);
    int t = threadIdx.x;
    int lane = t & 31, warp = t >> 5;
    int wm = (warp & 1) * 32;
    int wn = (warp >> 1) * 32;
    int m0 = by * 64;
    int n0 = bx * 128;

    int a_row = t >> 2, a_c4 = (t & 3) * 4;
    const float* Ag = A + (size_t)(m0 + a_row) * 256 + a_c4;
    uint32_t a_s = S0 + (a_row * TFA_STR + a_c4) * 4;

    auto prefetch = [&](int it) {
        int st = it % 3;
        asm volatile("cp.async.cg.shared.global [%0], [%1], 16;"
                     :: "r"(a_s + st * TF_STG), "l"(Ag + it * 16));
        #pragma unroll
        for (int i = 0; i < 2; ++i) {
            int idx = t + i * 256;
            int row = idx >> 5, c4 = (idx & 31) * 4;
            const float* bg = Bw + (size_t)(it * 16 + row) * 256 + n0 + c4;
            uint32_t dst = S0 + TFA_SZ + (row * TFB_STR + c4) * 4 + st * TF_STG;
            asm volatile("cp.async.cg.shared.global [%0], [%1], 16;" :: "r"(dst), "l"(bg));
        }
        asm volatile("cp.async.commit_group;");
    };

    float acc[2][4][4];
    #pragma unroll
    for (int mi = 0; mi < 2; ++mi)
        #pragma unroll
        for (int nj = 0; nj < 4; ++nj)
            #pragma unroll
            for (int r = 0; r < 4; ++r) acc[mi][nj][r] = 0.f;

    const int niter = 16;
    prefetch(0); prefetch(1);

    int lr = lane >> 2, lc = lane & 3;
    for (int it = 0; it < niter; ++it) {
        if (it + 1 < niter) asm volatile("cp.async.wait_group 1;");
        else                asm volatile("cp.async.wait_group 0;");
        __syncthreads();
        if (it + 2 < niter) prefetch(it + 2);

        const uint32_t* As = (const uint32_t*)(sm_ + (it % 3) * TF_STG);
        const uint32_t* Bs = (const uint32_t*)(sm_ + (it % 3) * TF_STG + TFA_SZ);

        #pragma unroll
        for (int kk = 0; kk < 2; ++kk) {
            uint32_t af[2][4];
            #pragma unroll
            for (int mi = 0; mi < 2; ++mi) {
                int rb = wm + mi * 16 + lr;
                af[mi][0] = As[rb * TFA_STR + kk * 8 + lc];
                af[mi][1] = As[(rb + 8) * TFA_STR + kk * 8 + lc];
                af[mi][2] = As[rb * TFA_STR + kk * 8 + lc + 4];
                af[mi][3] = As[(rb + 8) * TFA_STR + kk * 8 + lc + 4];
            }
            #pragma unroll
            for (int nj = 0; nj < 4; ++nj) {
                uint32_t b0 = Bs[(kk * 8 + lc) * TFB_STR + wn + nj * 8 + lr];
                uint32_t b1 = Bs[(kk * 8 + lc + 4) * TFB_STR + wn + nj * 8 + lr];
                #pragma unroll
                for (int mi = 0; mi < 2; ++mi)
                    asm volatile(
                        "mma.sync.aligned.m16n8k8.row.col.f32.tf32.tf32.f32 "
                        "{%0,%1,%2,%3}, {%4,%5,%6,%7}, {%8,%9}, {%0,%1,%2,%3};"
                        : "+f"(acc[mi][nj][0]), "+f"(acc[mi][nj][1]),
                          "+f"(acc[mi][nj][2]), "+f"(acc[mi][nj][3])
                        : "r"(af[mi][0]), "r"(af[mi][1]), "r"(af[mi][2]), "r"(af[mi][3]),
                          "r"(b0), "r"(b1));
            }
        }
    }

    #pragma unroll
    for (int mi = 0; mi < 2; ++mi) {
        #pragma unroll
        for (int nj = 0; nj < 4; ++nj) {
            int r = m0 + wm + mi * 16 + lr;
            int c = n0 + wn + nj * 8 + lc * 2;
            float bx2 = bias[c], by2 = bias[c + 1];
            float2 v0 = {acc[mi][nj][0] + bx2, acc[mi][nj][1] + by2};
            float2 v1 = {acc[mi][nj][2] + bx2, acc[mi][nj][3] + by2};
            *(float2*)(C + (size_t)r * 256 + c) = v0;
            *(float2*)(C + (size_t)(r + 8) * 256 + c) = v1;
        }
    }
}

// ---------------- bf16 GEMM device body: 64x128x32, 3-stage ------------------
template<int EPI>
__device__ void hgemm64_dev(char* sm_, int bx, int by,
                            const bf16* __restrict__ A, const bf16* __restrict__ B,
                            const float* __restrict__ bias, const float* __restrict__ resid,
                            void* __restrict__ Cp, int N, int K) {
    uint32_t S0 = smem_u32(sm_);
    int t = threadIdx.x;
    int lane = t & 31, warp = t >> 5;
    int wm = (warp & 1) * 32;
    int wn = (warp >> 1) * 32;
    int m0 = by * 64;
    int n0 = bx * 128;

    int a_row = t >> 2, a_c16 = t & 3;
    const bf16* Ag = A + (size_t)(m0 + a_row) * K + a_c16 * 8;
    uint32_t a_s = S0 + a_row * PASTR + a_c16 * 16;
    int b_row = t >> 3;
    int b_c16 = (t & 7) * 2;
    const bf16* Bg = B + (size_t)b_row * N + n0 + b_c16 * 8;
    uint32_t b_s = S0 + H64_A + b_row * PBSTR + b_c16 * 16;

    auto prefetch = [&](int chunk) {
        int st = chunk % 3;
        const bf16* bg = Bg + (size_t)chunk * PBK * N;
        asm volatile("cp.async.cg.shared.global [%0], [%1], 16;"
                     :: "r"(a_s + st * H64_STG), "l"(Ag + chunk * PBK));
        asm volatile("cp.async.cg.shared.global [%0], [%1], 16;" :: "r"(b_s + st * H64_STG), "l"(bg));
        asm volatile("cp.async.cg.shared.global [%0], [%1], 16;" :: "r"(b_s + st * H64_STG + 16), "l"(bg + 8));
        asm volatile("cp.async.commit_group;");
    };

    uint32_t aoff[2], boff[2];
    #pragma unroll
    for (int mi = 0; mi < 2; ++mi)
        aoff[mi] = (wm + mi * 16 + (lane & 15)) * PASTR + (lane >> 4) * 16;
    int tile = lane >> 3;
    #pragma unroll
    for (int ni = 0; ni < 2; ++ni)
        boff[ni] = H64_A + ((tile & 1) * 8 + (lane & 7)) * PBSTR
                 + (wn + ni * 16 + (tile >> 1) * 8) * 2;

    float acc[2][4][4];
    #pragma unroll
    for (int mi = 0; mi < 2; ++mi)
        #pragma unroll
        for (int nj = 0; nj < 4; ++nj)
            #pragma unroll
            for (int r = 0; r < 4; ++r) acc[mi][nj][r] = 0.f;

    int niter = K / PBK;
    prefetch(0); prefetch(1);

    for (int it = 0; it < niter; ++it) {
        if (it + 1 < niter) asm volatile("cp.async.wait_group 1;");
        else                asm volatile("cp.async.wait_group 0;");
        __syncthreads();
        if (it + 2 < niter) prefetch(it + 2);

        uint32_t Sb = S0 + (it % 3) * H64_STG;
        #pragma unroll
        for (int kk = 0; kk < 2; ++kk) {
            uint32_t a[2][4];
            #pragma unroll
            for (int mi = 0; mi < 2; ++mi) {
                uint32_t addr = Sb + aoff[mi] + kk * 32;
                asm volatile("ldmatrix.sync.aligned.m8n8.x4.shared.b16 {%0,%1,%2,%3}, [%4];"
                    : "=r"(a[mi][0]), "=r"(a[mi][1]), "=r"(a[mi][2]), "=r"(a[mi][3]) : "r"(addr));
            }
            uint32_t bq[2][4];
            #pragma unroll
            for (int ni = 0; ni < 2; ++ni) {
                uint32_t addr = Sb + boff[ni] + kk * 16 * PBSTR;
                asm volatile("ldmatrix.sync.aligned.m8n8.x4.trans.shared.b16 {%0,%1,%2,%3}, [%4];"
                    : "=r"(bq[ni][0]), "=r"(bq[ni][1]), "=r"(bq[ni][2]), "=r"(bq[ni][3]) : "r"(addr));
            }
            #pragma unroll
            for (int mi = 0; mi < 2; ++mi)
                #pragma unroll
                for (int nj = 0; nj < 4; ++nj) {
                    uint32_t b0 = bq[nj >> 1][(nj & 1) * 2];
                    uint32_t b1 = bq[nj >> 1][(nj & 1) * 2 + 1];
                    asm volatile(
                        "mma.sync.aligned.m16n8k16.row.col.f32.bf16.bf16.f32 "
                        "{%0,%1,%2,%3}, {%4,%5,%6,%7}, {%8,%9}, {%0,%1,%2,%3};"
                        : "+f"(acc[mi][nj][0]), "+f"(acc[mi][nj][1]),
                          "+f"(acc[mi][nj][2]), "+f"(acc[mi][nj][3])
                        : "r"(a[mi][0]), "r"(a[mi][1]), "r"(a[mi][2]), "r"(a[mi][3]),
                          "r"(b0), "r"(b1));
                }
        }
    }

    int r_base = m0 + wm + (lane >> 2);
    int c_base = n0 + wn + (lane & 3) * 2;
    #pragma unroll
    for (int mi = 0; mi < 2; ++mi) {
        #pragma unroll
        for (int nj = 0; nj < 4; ++nj) {
            int r = r_base + mi * 16;
            int c = c_base + nj * 8;
            float bx2 = bias[c], by2 = bias[c + 1];
            float o00 = acc[mi][nj][0] + bx2;
            float o01 = acc[mi][nj][1] + by2;
            float o10 = acc[mi][nj][2] + bx2;
            float o11 = acc[mi][nj][3] + by2;
            if (EPI == 2) {
                const float* rp0 = resid + (size_t)r * N + c;
                const float* rp1 = resid + (size_t)(r + 8) * N + c;
                float* Cf = (float*)Cp;
                float2 v0 = {o00 + rp0[0], o01 + rp0[1]};
                float2 v1 = {o10 + rp1[0], o11 + rp1[1]};
                *(float2*)(Cf + (size_t)r * N + c) = v0;
                *(float2*)(Cf + (size_t)(r + 8) * N + c) = v1;
            } else {
                bf16* Cb = (bf16*)Cp;
                __nv_bfloat162 v0 = {__float2bfloat16(o00), __float2bfloat16(o01)};
                __nv_bfloat162 v1 = {__float2bfloat16(o10), __float2bfloat16(o11)};
                *(__nv_bfloat162*)(Cb + (size_t)r * N + c) = v0;
                *(__nv_bfloat162*)(Cb + (size_t)(r + 8) * N + c) = v1;
            }
        }
    }
}

// ========== K2: fused v-proj (bf16, 64x128) || off/attn (tf32, 64x128) =======
// Resource-matched: both bodies use exactly 41472 B dynamic smem, ~64-70 regs.
__global__ __launch_bounds__(256)
void fused_k2(const bf16* __restrict__ xnb, const bf16* __restrict__ wvb,
              const float* __restrict__ b_v, bf16* __restrict__ vb,
              const float* __restrict__ xn, const float* __restrict__ wcat,
              const float* __restrict__ bcat, float* __restrict__ offattn) {
    extern __shared__ char sm_[];
    if (blockIdx.z == 0)
        hgemm64_dev<0>(sm_, blockIdx.x, blockIdx.y, xnb, wvb, b_v, nullptr, vb, 256, 256);
    else
        tgemm64_dev(sm_, blockIdx.x, blockIdx.y, xn, wcat, bcat, offattn);
}

// ---------------- bf16 GEMM 128x128x32 (fc1, fc2), 3-stage -------------------
#define PBM 128
#define PBN 128
#define PA_ST (PBM * PASTR)
#define PB_ST (PBK * PBSTR)
#define PSTG  (PA_ST + PB_ST)
#define PSMEM (3 * PSTG)

template<int EPI>
__global__ __launch_bounds__(256)
void hgemm_kernel(const bf16* __restrict__ A, const bf16* __restrict__ B,
                  const float* __restrict__ bias, const float* __restrict__ resid,
                  void* __restrict__ Cp, int N, int K) {
    extern __shared__ char sm_[];
    uint32_t S0 = smem_u32(sm_);

    int t = threadIdx.x;
    int lane = t & 31, warp = t >> 5;
    int wm = (warp & 3) * 32;
    int wn = (warp >> 2) * 64;
    int m0 = blockIdx.y * PBM;
    int n0 = blockIdx.x * PBN;

    int a_row = t >> 1;
    int a_c16 = (t & 1) * 2;
    const bf16* Ag = A + (size_t)(m0 + a_row) * K + a_c16 * 8;
    uint32_t a_s = S0 + a_row * PASTR + a_c16 * 16;
    int b_row = t >> 3;
    int b_c16 = (t & 7) * 2;
    const bf16* Bg = B + (size_t)b_row * N + n0 + b_c16 * 8;
    uint32_t b_s = S0 + PA_ST + b_row * PBSTR + b_c16 * 16;

    auto prefetch = [&](int chunk) {
        int st = chunk % 3;
        const bf16* ag = Ag + chunk * PBK;
        const bf16* bg = Bg + (size_t)chunk * PBK * N;
        uint32_t sa = a_s + st * PSTG;
        uint32_t sb = b_s + st * PSTG;
        asm volatile("cp.async.cg.shared.global [%0], [%1], 16;" :: "r"(sa), "l"(ag));
        asm volatile("cp.async.cg.shared.global [%0], [%1], 16;" :: "r"(sa + 16), "l"(ag + 8));
        asm volatile("cp.async.cg.shared.global [%0], [%1], 16;" :: "r"(sb), "l"(bg));
        asm volatile("cp.async.cg.shared.global [%0], [%1], 16;" :: "r"(sb + 16), "l"(bg + 8));
        asm volatile("cp.async.commit_group;");
    };

    uint32_t aoff[2], boff[4];
    #pragma unroll
    for (int mi = 0; mi < 2; ++mi)
        aoff[mi] = (wm + mi * 16 + (lane & 15)) * PASTR + (lane >> 4) * 16;
    int tile = lane >> 3;
    #pragma unroll
    for (int ni = 0; ni < 4; ++ni)
        boff[ni] = PA_ST + ((tile & 1) * 8 + (lane & 7)) * PBSTR
                 + (wn + ni * 16 + (tile >> 1) * 8) * 2;

    float acc[2][8][4];
    #pragma unroll
    for (int mi = 0; mi < 2; ++mi)
        #pragma unroll
        for (int nj = 0; nj < 8; ++nj)
            #pragma unroll
            for (int r = 0; r < 4; ++r) acc[mi][nj][r] = 0.f;

    int niter = K / PBK;
    prefetch(0);
    prefetch(1);

    for (int it = 0; it < niter; ++it) {
        if (it + 1 < niter) asm volatile("cp.async.wait_group 1;");
        else                asm volatile("cp.async.wait_group 0;");
        __syncthreads();
        if (it + 2 < niter) prefetch(it + 2);

        uint32_t Sb = S0 + (it % 3) * PSTG;
        #pragma unroll
        for (int kk = 0; kk < 2; ++kk) {
            uint32_t a[2][4];
            #pragma unroll
            for (int mi = 0; mi < 2; ++mi) {
                uint32_t addr = Sb + aoff[mi] + kk * 32;
                asm volatile("ldmatrix.sync.aligned.m8n8.x4.shared.b16 {%0,%1,%2,%3}, [%4];"
                    : "=r"(a[mi][0]), "=r"(a[mi][1]), "=r"(a[mi][2]), "=r"(a[mi][3]) : "r"(addr));
            }
            uint32_t bq[4][4];
            #pragma unroll
            for (int ni = 0; ni < 4; ++ni) {
                uint32_t addr = Sb + boff[ni] + kk * 16 * PBSTR;
                asm volatile("ldmatrix.sync.aligned.m8n8.x4.trans.shared.b16 {%0,%1,%2,%3}, [%4];"
                    : "=r"(bq[ni][0]), "=r"(bq[ni][1]), "=r"(bq[ni][2]), "=r"(bq[ni][3]) : "r"(addr));
            }
            #pragma unroll
            for (int mi = 0; mi < 2; ++mi)
                #pragma unroll
                for (int nj = 0; nj < 8; ++nj) {
                    uint32_t b0 = bq[nj >> 1][(nj & 1) * 2];
                    uint32_t b1 = bq[nj >> 1][(nj & 1) * 2 + 1];
                    asm volatile(
                        "mma.sync.aligned.m16n8k16.row.col.f32.bf16.bf16.f32 "
                        "{%0,%1,%2,%3}, {%4,%5,%6,%7}, {%8,%9}, {%0,%1,%2,%3};"
                        : "+f"(acc[mi][nj][0]), "+f"(acc[mi][nj][1]),
                          "+f"(acc[mi][nj][2]), "+f"(acc[mi][nj][3])
                        : "r"(a[mi][0]), "r"(a[mi][1]), "r"(a[mi][2]), "r"(a[mi][3]),
                          "r"(b0), "r"(b1));
                }
        }
    }

    int r_base = m0 + wm + (lane >> 2);
    int c_base = n0 + wn + (lane & 3) * 2;
    #pragma unroll
    for (int mi = 0; mi < 2; ++mi) {
        #pragma unroll
        for (int nj = 0; nj < 8; ++nj) {
            int r = r_base + mi * 16;
            int c = c_base + nj * 8;
            float bx = bias[c], by = bias[c + 1];
            float o00 = acc[mi][nj][0] + bx;
            float o01 = acc[mi][nj][1] + by;
            float o10 = acc[mi][nj][2] + bx;
            float o11 = acc[mi][nj][3] + by;
            if (EPI == 1) {
                o00 = gelu_f(o00); o01 = gelu_f(o01);
                o10 = gelu_f(o10); o11 = gelu_f(o11);
            }
            if (EPI == 2) {
                const float* rp0 = resid + (size_t)r * N + c;
                const float* rp1 = resid + (size_t)(r + 8) * N + c;
                float* Cf = (float*)Cp;
                float2 v0 = {o00 + rp0[0], o01 + rp0[1]};
                float2 v1 = {o10 + rp1[0], o11 + rp1[1]};
                *(float2*)(Cf + (size_t)r * N + c) = v0;
                *(float2*)(Cf + (size_t)(r + 8) * N + c) = v1;
            } else {
                bf16* Cb = (bf16*)Cp;
                __nv_bfloat162 v0 = {__float2bfloat16(o00), __float2bfloat16(o01)};
                __nv_bfloat162 v1 = {__float2bfloat16(o10), __float2bfloat16(o11)};
                *(__nv_bfloat162*)(Cb + (size_t)r * N + c) = v0;
                *(__nv_bfloat162*)(Cb + (size_t)(r + 8) * N + c) = v1;
            }
        }
    }
}

// ======== fused wout GEMM + residual + LN2: 64x256 tile, LN in epilogue ======
#define QBM 64
#define QASTR 80
#define QBSTR 528
#define QA_SZ (QBM * QASTR)
#define QB_SZ (32 * QBSTR)
#define QSTG  (QA_SZ + QB_SZ)
#define QLN_SZ (64 * 264 * 4)
#define QSMEM (QLN_SZ > 3 * QSTG ? QLN_SZ : 3 * QSTG)

__global__ __launch_bounds__(256)
void hgemm_wout_ln(const bf16* __restrict__ A, const bf16* __restrict__ B,
                   const float* __restrict__ bias, const float* __restrict__ resid,
                   float* __restrict__ xres, const float* __restrict__ g2,
                   const float* __restrict__ b2g, bf16* __restrict__ yb) {
    extern __shared__ char sm_[];
    uint32_t S0 = smem_u32(sm_);
    int t = threadIdx.x;
    int lane = t & 31, warp = t >> 5;
    int wm = (warp & 1) * 32;
    int wn = (warp >> 1) * 64;
    int m0 = blockIdx.x * QBM;

    int a_row = t >> 2, a_c16 = t & 3;
    const bf16* Ag = A + (size_t)(m0 + a_row) * 256 + a_c16 * 8;
    uint32_t a_s = S0 + a_row * QASTR + a_c16 * 16;

    auto prefetch = [&](int ck) {
        int st = ck % 3;
        asm volatile("cp.async.cg.shared.global [%0], [%1], 16;"
                     :: "r"(a_s + st * QSTG), "l"(Ag + ck * 32));
        #pragma unroll
        for (int i = 0; i < 4; ++i) {
            int idx = t + i * 256;
            int row = idx >> 5, c16 = idx & 31;
            const bf16* bg = B + (size_t)(ck * 32 + row) * 256 + c16 * 8;
            uint32_t dst = S0 + st * QSTG + QA_SZ + row * QBSTR + c16 * 16;
            asm volatile("cp.async.cg.shared.global [%0], [%1], 16;" :: "r"(dst), "l"(bg));
        }
        asm volatile("cp.async.commit_group;");
    };

    uint32_t aoff[2], boff[4];
    #pragma unroll
    for (int mi = 0; mi < 2; ++mi)
        aoff[mi] = (wm + mi * 16 + (lane & 15)) * QASTR + (lane >> 4) * 16;
    int tile = lane >> 3;
    #pragma unroll
    for (int ni = 0; ni < 4; ++ni)
        boff[ni] = QA_SZ + ((tile & 1) * 8 + (lane & 7)) * QBSTR
                 + (wn + ni * 16 + (tile >> 1) * 8) * 2;

    float acc[2][8][4];
    #pragma unroll
    for (int mi = 0; mi < 2; ++mi)
        #pragma unroll
        for (int nj = 0; nj < 8; ++nj)
            #pragma unroll
            for (int r = 0; r < 4; ++r) acc[mi][nj][r] = 0.f;

    const int niter = 8;
    prefetch(0); prefetch(1);

    for (int it = 0; it < niter; ++it) {
        if (it + 1 < niter) asm volatile("cp.async.wait_group 1;");
        else                asm volatile("cp.async.wait_group 0;");
        __syncthreads();
        if (it + 2 < niter) prefetch(it + 2);

        uint32_t Sb = S0 + (it % 3) * QSTG;
        #pragma unroll
        for (int kk = 0; kk < 2; ++kk) {
            uint32_t a[2][4];
            #pragma unroll
            for (int mi = 0; mi < 2; ++mi) {
                uint32_t addr = Sb + aoff[mi] + kk * 32;
                asm volatile("ldmatrix.sync.aligned.m8n8.x4.shared.b16 {%0,%1,%2,%3}, [%4];"
                    : "=r"(a[mi][0]), "=r"(a[mi][1]), "=r"(a[mi][2]), "=r"(a[mi][3]) : "r"(addr));
            }
            uint32_t bq[4][4];
            #pragma unroll
            for (int ni = 0; ni < 4; ++ni) {
                uint32_t addr = Sb + boff[ni] + kk * 16 * QBSTR;
                asm volatile("ldmatrix.sync.aligned.m8n8.x4.trans.shared.b16 {%0,%1,%2,%3}, [%4];"
                    : "=r"(bq[ni][0]), "=r"(bq[ni][1]), "=r"(bq[ni][2]), "=r"(bq[ni][3]) : "r"(addr));
            }
            #pragma unroll
            for (int mi = 0; mi < 2; ++mi)
                #pragma unroll
                for (int nj = 0; nj < 8; ++nj) {
                    uint32_t b0 = bq[nj >> 1][(nj & 1) * 2];
                    uint32_t b1 = bq[nj >> 1][(nj & 1) * 2 + 1];
                    asm volatile(
                        "mma.sync.aligned.m16n8k16.row.col.f32.bf16.bf16.f32 "
                        "{%0,%1,%2,%3}, {%4,%5,%6,%7}, {%8,%9}, {%0,%1,%2,%3};"
                        : "+f"(acc[mi][nj][0]), "+f"(acc[mi][nj][1]),
                          "+f"(acc[mi][nj][2]), "+f"(acc[mi][nj][3])
                        : "r"(a[mi][0]), "r"(a[mi][1]), "r"(a[mi][2]), "r"(a[mi][3]),
                          "r"(b0), "r"(b1));
                }
        }
    }

    __syncthreads();
    float* lt = (float*)sm_;

    int lr0 = wm + (lane >> 2);
    int cb = wn + (lane & 3) * 2;
    #pragma unroll
    for (int mi = 0; mi < 2; ++mi) {
        #pragma unroll
        for (int nj = 0; nj < 8; ++nj) {
            int rl = lr0 + mi * 16;
            int c = cb + nj * 8;
            float bx = bias[c], by = bias[c + 1];
            const float* rp0 = resid + (size_t)(m0 + rl) * 256 + c;
            const float* rp1 = resid + (size_t)(m0 + rl + 8) * 256 + c;
            float2 v0 = {acc[mi][nj][0] + bx + rp0[0], acc[mi][nj][1] + by + rp0[1]};
            float2 v1 = {acc[mi][nj][2] + bx + rp1[0], acc[mi][nj][3] + by + rp1[1]};
            *(float2*)(xres + (size_t)(m0 + rl) * 256 + c) = v0;
            *(float2*)(xres + (size_t)(m0 + rl + 8) * 256 + c) = v1;
            lt[rl * 264 + c] = v0.x;       lt[rl * 264 + c + 1] = v0.y;
            lt[(rl + 8) * 264 + c] = v1.x; lt[(rl + 8) * 264 + c + 1] = v1.y;
        }
    }
    __syncthreads();

    int colb = lane * 8;
    float gg[8], bb[8];
    #pragma unroll
    for (int j = 0; j < 8; ++j) { gg[j] = g2[colb + j]; bb[j] = b2g[colb + j]; }

    for (int i = 0; i < 8; ++i) {
        int rr = warp * 8 + i;
        const float* rowp = lt + rr * 264 + colb;
        float v[8];
        float s = 0.f;
        #pragma unroll
        for (int j = 0; j < 8; ++j) { v[j] = rowp[j]; s += v[j]; }
        #pragma unroll
        for (int o = 16; o; o >>= 1) s += __shfl_xor_sync(0xffffffffu, s, o);
        float mean = s * (1.0f / 256.0f);
        float s2 = 0.f;
        #pragma unroll
        for (int j = 0; j < 8; ++j) { float d = v[j] - mean; s2 += d * d; }
        #pragma unroll
        for (int o = 16; o; o >>= 1) s2 += __shfl_xor_sync(0xffffffffu, s2, o);
        float inv = rsqrtf(s2 * (1.0f / 256.0f) + 1e-5f);
        bf16 ob[8];
        #pragma unroll
        for (int j = 0; j < 8; ++j)
            ob[j] = __float2bfloat16((v[j] - mean) * inv * gg[j] + bb[j]);
        *(uint4*)(yb + (size_t)(m0 + rr) * 256 + colb) = *(uint4*)ob;
    }
}

// ---------------- Deformable sampling: one warp = (token, head-pair) ---------
__global__ void sample_kernel(const bf16* __restrict__ v, const float* __restrict__ offattn,
                              const float* __restrict__ rp, bf16* __restrict__ agg) {
    int gw = blockIdx.x * 8 + (threadIdx.x >> 5);
    int lane = threadIdx.x & 31;
    int tg = gw >> 2;
    int head = ((gw & 3) << 1) + (lane >> 4);
    int l16 = lane & 15;
    int bb = tg >> 13;
    int pos = tg & 8191;

    const float* lg = offattn + (size_t)tg * 256 + 144 + head * 9;
    float w[9];
    float mx = -1e30f;
    #pragma unroll
    for (int k = 0; k < 9; ++k) { w[k] = lg[k]; mx = fmaxf(mx, w[k]); }
    float sum = 0.f;
    #pragma unroll
    for (int k = 0; k < 9; ++k) { w[k] = expf(w[k] - mx); sum += w[k]; }
    float inv = 1.0f / sum;

    const float* rpp  = rp + (size_t)pos * 18;
    const float* offp = offattn + (size_t)tg * 256 + head * 18;
    const __nv_bfloat162* vc = (const __nv_bfloat162*)v + head * 16 + l16;
    int base = bb << 13;
    float a0 = 0.f, a1 = 0.f;
    #pragma unroll
    for (int k = 0; k < 9; ++k) {
        float cx = (rpp[k * 2 + 0] + offp[k * 2 + 0] + 1.0f) * 0.5f * 127.0f;
        float cy = (rpp[k * 2 + 1] + offp[k * 2 + 1] + 1.0f) * 0.5f * 63.0f;
        float fx = floorf(cx), fy = floorf(cy);
        float wx = cx - fx, wy = cy - fy;
        int x0 = min(max((int)fx, 0), 127);
        int x1 = min(max((int)fx + 1, 0), 127);
        int y0 = min(max((int)fy, 0), 63);
        int y1 = min(max((int)fy + 1, 0), 63);
        float2 v00 = __bfloat1622float2(vc[(size_t)(base + y0 * 128 + x0) * 128]);
        float2 v01 = __bfloat1622float2(vc[(size_t)(base + y0 * 128 + x1) * 128]);
        float2 v10 = __bfloat1622float2(vc[(size_t)(base + y1 * 128 + x0) * 128]);
        float2 v11 = __bfloat1622float2(vc[(size_t)(base + y1 * 128 + x1) * 128]);
        float w00 = (1.f - wy) * (1.f - wx), w01 = (1.f - wy) * wx;
        float w10 = wy * (1.f - wx),         w11 = wy * wx;
        float wk = w[k] * inv;
        a0 += (v00.x * w00 + v01.x * w01 + v10.x * w10 + v11.x * w11) * wk;
        a1 += (v00.y * w00 + v01.y * w01 + v10.y * w10 + v11.y * w11) * wk;
    }
    __nv_bfloat162 ov = {__float2bfloat16(a0), __float2bfloat16(a1)};
    *(__nv_bfloat162*)(agg + (size_t)tg * 256 + head * 32 + l16 * 2) = ov;
}

// ---------------- Depthwise 3x3 conv: sliding window, 4-way x-split ----------
__global__ void dwconv_kernel(const bf16* __restrict__ h, const float* __restrict__ wdw,
                              const float* __restrict__ bdw, bf16* __restrict__ o) {
    int c2 = blockIdx.x * 256 + threadIdx.x;
    int y = blockIdx.y & 63;
    int seg = blockIdx.y >> 6;
    int bb = blockIdx.z;
    int c = c2 * 2;
    int x0 = seg * 32;

    float w0[9], w1[9];
    #pragma unroll
    for (int i = 0; i < 9; ++i) { w0[i] = wdw[c * 9 + i]; w1[i] = wdw[(c + 1) * 9 + i]; }
    float bb0 = bdw[c], bb1 = bdw[c + 1];

    const __nv_bfloat162* hp = (const __nv_bfloat162*)h;
    size_t base = ((size_t)(bb << 13) + y * 128) * 512 + c2;
    bool hu = (y > 0), hd = (y < 63);
    __nv_bfloat162 zero = __float2bfloat162_rn(0.f);

    __nv_bfloat162 cm[3], cc[3], cn[3];
    {
        size_t p = base + ((x0 + 127) & 127) * 512;
        cm[0] = hu ? hp[p - 65536] : zero; cm[1] = hp[p]; cm[2] = hd ? hp[p + 65536] : zero;
        p = base + x0 * 512;
        cc[0] = hu ? hp[p - 65536] : zero; cc[1] = hp[p]; cc[2] = hd ? hp[p + 65536] : zero;
    }
    bf16* op = o + ((size_t)(bb << 13) + y * 128) * 1024 + c;

    for (int x = x0; x < x0 + 32; ++x) {
        size_t p = base + ((x + 1) & 127) * 512;
        cn[0] = hu ? hp[p - 65536] : zero; cn[1] = hp[p]; cn[2] = hd ? hp[p + 65536] : zero;

        float a0 = bb0, a1 = bb1;
        #pragma unroll
        for (int dy = 0; dy < 3; ++dy) {
            float2 vm = __bfloat1622float2(cm[dy]);
            float2 vc = __bfloat1622float2(cc[dy]);
            float2 vp = __bfloat1622float2(cn[dy]);
            a0 += vm.x * w0[dy * 3 + 0] + vc.x * w0[dy * 3 + 1] + vp.x * w0[dy * 3 + 2];
            a1 += vm.y * w1[dy * 3 + 0] + vc.y * w1[dy * 3 + 1] + vp.y * w1[dy * 3 + 2];
        }
        __nv_bfloat162 ov = {__float2bfloat16(gelu_f(a0)), __float2bfloat16(gelu_f(a1))};
        *(__nv_bfloat162*)(op + (size_t)x * 1024) = ov;

        #pragma unroll
        for (int i = 0; i < 3; ++i) { cm[i] = cc[i]; cc[i] = cn[i]; }
    }
}

// ---------------- launch ----------------
extern "C" void kernel_launch(void* const* d_in, const int* in_sizes, int n_in,
                              void* d_out, int out_size) {
    const float* x      = (const float*)d_in[0];
    const float* rp     = (const float*)d_in[1];
    const float* ln1_g  = (const float*)d_in[2];
    const float* ln1_b  = (const float*)d_in[3];
    const float* w_v    = (const float*)d_in[4];
    const float* b_v    = (const float*)d_in[5];
    const float* w_off  = (const float*)d_in[6];
    const float* b_off  = (const float*)d_in[7];
    const float* w_attn = (const float*)d_in[8];
    const float* b_attn = (const float*)d_in[9];
    const float* w_out  = (const float*)d_in[10];
    const float* b_out  = (const float*)d_in[11];
    const float* ln2_g  = (const float*)d_in[12];
    const float* ln2_b  = (const float*)d_in[13];
    const float* w1     = (const float*)d_in[14];
    const float* b1     = (const float*)d_in[15];
    const float* w_dw   = (const float*)d_in[16];
    const float* b_dw   = (const float*)d_in[17];
    const float* w2     = (const float*)d_in[18];
    const float* b2     = (const float*)d_in[19];
    float* out = (float*)d_out;

    float *xn, *offattn, *xres, *wcat, *bcat;
    bf16 *xnb, *vb, *aggb, *yb, *hb, *h2b, *wvb, *woutb, *w1b, *w2b;
    cudaGetSymbolAddress((void**)&xn,      g_xn);
    cudaGetSymbolAddress((void**)&offattn, g_offattn);
    cudaGetSymbolAddress((void**)&xres,    g_xres);
    cudaGetSymbolAddress((void**)&wcat,    g_wcat);
    cudaGetSymbolAddress((void**)&bcat,    g_bcat);
    cudaGetSymbolAddress((void**)&xnb,     g_xnb);
    cudaGetSymbolAddress((void**)&vb,      g_vb);
    cudaGetSymbolAddress((void**)&aggb,    g_aggb);
    cudaGetSymbolAddress((void**)&yb,      g_yb);
    cudaGetSymbolAddress((void**)&hb,      g_hb);
    cudaGetSymbolAddress((void**)&h2b,     g_h2b);
    cudaGetSymbolAddress((void**)&wvb,     g_wvb);
    cudaGetSymbolAddress((void**)&woutb,   g_woutb);
    cudaGetSymbolAddress((void**)&w1b,     g_w1b);
    cudaGetSymbolAddress((void**)&w2b,     g_w2b);

    cudaFuncSetAttribute(hgemm_kernel<1>, cudaFuncAttributeMaxDynamicSharedMemorySize, PSMEM);
    cudaFuncSetAttribute(hgemm_kernel<2>, cudaFuncAttributeMaxDynamicSharedMemorySize, PSMEM);
    cudaFuncSetAttribute(fused_k2,        cudaFuncAttributeMaxDynamicSharedMemorySize, H64_SMEM);
    cudaFuncSetAttribute(hgemm_wout_ln,   cudaFuncAttributeMaxDynamicSharedMemorySize, QSMEM);

    // K1: LN1 || weight prep
    prep_ln_kernel<<<NTOK + 2816, 256>>>(
        x, ln1_g, ln1_b, xn, xnb,
        w_v, w_out, w1, w2, w_off, w_attn, b_off, b_attn,
        wvb, woutb, w1b, w2b, wcat, bcat);
    // K2: v projection || offsets+attn (resource-matched 64x128 bodies)
    fused_k2<<<dim3(2, NTOK / 64, 2), 256, H64_SMEM>>>(
        xnb, wvb, b_v, vb, xn, wcat, bcat, offattn);
    // K3: softmax + bilinear sampling + aggregation
    sample_kernel<<<NTOK / 2, 256>>>(vb, offattn, rp, aggb);
    // K4: output proj + residual + LN2 fused -> xres (f32) + yb (bf16)
    hgemm_wout_ln<<<NTOK / QBM, 256, QSMEM>>>(aggb, woutb, b_out, x, xres, ln2_g, ln2_b, yb);
    // K5: fc1 + GELU (bf16 TC, 128x128)
    hgemm_kernel<1><<<dim3(HID / PBN, NTOK / PBM), 256, PSMEM>>>(yb, w1b, b1, nullptr, hb, HID, 256);
    // K6: depthwise conv + GELU
    dwconv_kernel<<<dim3(2, 256, 2), 256>>>(hb, w_dw, b_dw, h2b);
    // K7: fc2 + residual -> out (f32, 128x128)
    hgemm_kernel<2><<<dim3(256 / PBN, NTOK / PBM), 256, PSMEM>>>(h2b, w2b, b2, xres, out, 256, 1024);
}

// round 13
// speedup vs baseline: 1.0270x; 1.0136x over previous
#include <cuda_runtime.h>
#include <cuda_bf16.h>
#include <math.h>
#include <stdint.h>

typedef __nv_bfloat16 bf16;

#define NTOK 16384
#define CDIM 256
#define HID  1024

// -------- scratch (__device__ globals; no allocations allowed) --------
__device__ float g_xn     [NTOK * CDIM];
__device__ float g_offattn[NTOK * 256];
__device__ float g_xres   [NTOK * CDIM];
__device__ bf16  g_xnb    [NTOK * CDIM];
__device__ bf16  g_vb     [NTOK * CDIM];
__device__ bf16  g_aggb   [NTOK * CDIM];
__device__ bf16  g_yb     [NTOK * CDIM];
__device__ bf16  g_hb     [NTOK * HID];
__device__ bf16  g_h2b    [NTOK * HID];
__device__ bf16  g_wvb    [256 * 256];
__device__ bf16  g_woutb  [256 * 256];
__device__ bf16  g_w1b    [256 * 1024];
__device__ bf16  g_w2b    [1024 * 256];
__device__ float g_wcat   [256 * 256];
__device__ float g_bcat   [256];

__device__ __forceinline__ float gelu_f(float v) {
    return 0.5f * v * (1.0f + erff(v * 0.7071067811865476f));
}

__device__ __forceinline__ uint32_t smem_u32(const void* p) {
    uint32_t a;
    asm("{ .reg .u64 t; cvta.to.shared.u64 t, %1; cvt.u32.u64 %0, t; }" : "=r"(a) : "l"(p));
    return a;
}

__device__ __forceinline__ uint32_t f2tf32(float f) {
    uint32_t r;
    asm("cvt.rna.tf32.f32 %0, %1;" : "=r"(r) : "f"(f));
    return r;
}

// ================= K1: fused prep + LN1 (block-range dispatch) =================
__global__ void prep_ln_kernel(
    const float* __restrict__ x, const float* __restrict__ g, const float* __restrict__ b,
    float* __restrict__ xn, bf16* __restrict__ xnb,
    const float* wv, const float* wout, const float* w1, const float* w2,
    const float* w_off, const float* w_attn, const float* b_off, const float* b_attn,
    bf16* wvb, bf16* woutb, bf16* w1b, bf16* w2b, float* wcat, float* bcat) {
    if (blockIdx.x < NTOK) {
        int tok = blockIdx.x;
        int c = threadIdx.x;
        float v = x[(size_t)tok * CDIM + c];
        __shared__ float sh[8];
        float s = v;
        #pragma unroll
        for (int o = 16; o; o >>= 1) s += __shfl_xor_sync(0xffffffffu, s, o);
        if ((c & 31) == 0) sh[c >> 5] = s;
        __syncthreads();
        float tot = 0.f;
        #pragma unroll
        for (int i = 0; i < 8; ++i) tot += sh[i];
        float mean = tot * (1.0f / CDIM);
        __syncthreads();
        float d = v - mean;
        float s2 = d * d;
        #pragma unroll
        for (int o = 16; o; o >>= 1) s2 += __shfl_xor_sync(0xffffffffu, s2, o);
        if ((c & 31) == 0) sh[c >> 5] = s2;
        __syncthreads();
        float v2 = 0.f;
        #pragma unroll
        for (int i = 0; i < 8; ++i) v2 += sh[i];
        float var = v2 * (1.0f / CDIM);
        float out = d * rsqrtf(var + 1e-5f) * g[c] + b[c];
        xn[(size_t)tok * CDIM + c]  = __uint_as_float(f2tf32(out));
        xnb[(size_t)tok * CDIM + c] = __float2bfloat16(out);
        return;
    }
    int i = (blockIdx.x - NTOK) * 256 + threadIdx.x;
    if (i < 65536) { wvb[i] = __float2bfloat16(wv[i]); return; }
    i -= 65536;
    if (i < 65536) { woutb[i] = __float2bfloat16(wout[i]); return; }
    i -= 65536;
    if (i < 262144) { w1b[i] = __float2bfloat16(w1[i]); return; }
    i -= 262144;
    if (i < 262144) { w2b[i] = __float2bfloat16(w2[i]); return; }
    i -= 262144;
    if (i < 65536) {
        int k = i >> 8, col = i & 255;
        float v = (col < 144) ? w_off[k * 144 + col]
                : (col < 216) ? w_attn[k * 72 + (col - 144)] : 0.f;
        wcat[i] = __uint_as_float(f2tf32(v));
        if (k == 0)
            bcat[col] = (col < 144) ? b_off[col]
                      : (col < 216) ? b_attn[col - 144] : 0.f;
    }
}

// ---------------- shared GEMM geometry constants ----------------
#define PBK 32
#define PASTR 80
#define PBSTR 272
#define H64_A  (64 * PASTR)
#define H64_B  (PBK * PBSTR)
#define H64_STG (H64_A + H64_B)
#define H64_SMEM (3 * H64_STG)
#define TFA_STR 20
#define TFB_STR 136
#define TFA_SZ  (64 * TFA_STR * 4)
#define TFB_SZ  (16 * TFB_STR * 4)
#define TF_STG  (TFA_SZ + TFB_SZ)

// ---------------- tf32 GEMM device body: 64x128x16, 3-stage ------------------
__device__ void tgemm64_dev(char* sm_, int bx, int by,
                            const float* __restrict__ A, const float* __restrict__ Bw,
                            const float* __restrict__ bias, float* __restrict__ C) {
    uint32_t S0 = smem_u32(sm_);
    int t = threadIdx.x;
    int lane = t & 31, warp = t >> 5;
    int wm = (warp & 1) * 32;
    int wn = (warp >> 1) * 32;
    int m0 = by * 64;
    int n0 = bx * 128;

    int a_row = t >> 2, a_c4 = (t & 3) * 4;
    const float* Ag = A + (size_t)(m0 + a_row) * 256 + a_c4;
    uint32_t a_s = S0 + (a_row * TFA_STR + a_c4) * 4;

    auto prefetch = [&](int it) {
        int st = it % 3;
        asm volatile("cp.async.cg.shared.global [%0], [%1], 16;"
                     :: "r"(a_s + st * TF_STG), "l"(Ag + it * 16));
        #pragma unroll
        for (int i = 0; i < 2; ++i) {
            int idx = t + i * 256;
            int row = idx >> 5, c4 = (idx & 31) * 4;
            const float* bg = Bw + (size_t)(it * 16 + row) * 256 + n0 + c4;
            uint32_t dst = S0 + TFA_SZ + (row * TFB_STR + c4) * 4 + st * TF_STG;
            asm volatile("cp.async.cg.shared.global [%0], [%1], 16;" :: "r"(dst), "l"(bg));
        }
        asm volatile("cp.async.commit_group;");
    };

    float acc[2][4][4];
    #pragma unroll
    for (int mi = 0; mi < 2; ++mi)
        #pragma unroll
        for (int nj = 0; nj < 4; ++nj)
            #pragma unroll
            for (int r = 0; r < 4; ++r) acc[mi][nj][r] = 0.f;

    const int niter = 16;
    prefetch(0); prefetch(1);

    int lr = lane >> 2, lc = lane & 3;
    for (int it = 0; it < niter; ++it) {
        if (it + 1 < niter) asm volatile("cp.async.wait_group 1;");
        else                asm volatile("cp.async.wait_group 0;");
        __syncthreads();
        if (it + 2 < niter) prefetch(it + 2);

        const uint32_t* As = (const uint32_t*)(sm_ + (it % 3) * TF_STG);
        const uint32_t* Bs = (const uint32_t*)(sm_ + (it % 3) * TF_STG + TFA_SZ);

        #pragma unroll
        for (int kk = 0; kk < 2; ++kk) {
            uint32_t af[2][4];
            #pragma unroll
            for (int mi = 0; mi < 2; ++mi) {
                int rb = wm + mi * 16 + lr;
                af[mi][0] = As[rb * TFA_STR + kk * 8 + lc];
                af[mi][1] = As[(rb + 8) * TFA_STR + kk * 8 + lc];
                af[mi][2] = As[rb * TFA_STR + kk * 8 + lc + 4];
                af[mi][3] = As[(rb + 8) * TFA_STR + kk * 8 + lc + 4];
            }
            #pragma unroll
            for (int nj = 0; nj < 4; ++nj) {
                uint32_t b0 = Bs[(kk * 8 + lc) * TFB_STR + wn + nj * 8 + lr];
                uint32_t b1 = Bs[(kk * 8 + lc + 4) * TFB_STR + wn + nj * 8 + lr];
                #pragma unroll
                for (int mi = 0; mi < 2; ++mi)
                    asm volatile(
                        "mma.sync.aligned.m16n8k8.row.col.f32.tf32.tf32.f32 "
                        "{%0,%1,%2,%3}, {%4,%5,%6,%7}, {%8,%9}, {%0,%1,%2,%3};"
                        : "+f"(acc[mi][nj][0]), "+f"(acc[mi][nj][1]),
                          "+f"(acc[mi][nj][2]), "+f"(acc[mi][nj][3])
                        : "r"(af[mi][0]), "r"(af[mi][1]), "r"(af[mi][2]), "r"(af[mi][3]),
                          "r"(b0), "r"(b1));
            }
        }
    }

    #pragma unroll
    for (int mi = 0; mi < 2; ++mi) {
        #pragma unroll
        for (int nj = 0; nj < 4; ++nj) {
            int r = m0 + wm + mi * 16 + lr;
            int c = n0 + wn + nj * 8 + lc * 2;
            float bx2 = bias[c], by2 = bias[c + 1];
            float2 v0 = {acc[mi][nj][0] + bx2, acc[mi][nj][1] + by2};
            float2 v1 = {acc[mi][nj][2] + bx2, acc[mi][nj][3] + by2};
            *(float2*)(C + (size_t)r * 256 + c) = v0;
            *(float2*)(C + (size_t)(r + 8) * 256 + c) = v1;
        }
    }
}

// ---------------- bf16 GEMM device body: 64x128x32, 3-stage ------------------
template<int EPI>
__device__ void hgemm64_dev(char* sm_, int bx, int by,
                            const bf16* __restrict__ A, const bf16* __restrict__ B,
                            const float* __restrict__ bias, const float* __restrict__ resid,
                            void* __restrict__ Cp, int N, int K) {
    uint32_t S0 = smem_u32(sm_);
    int t = threadIdx.x;
    int lane = t & 31, warp = t >> 5;
    int wm = (warp & 1) * 32;
    int wn = (warp >> 1) * 32;
    int m0 = by * 64;
    int n0 = bx * 128;

    int a_row = t >> 2, a_c16 = t & 3;
    const bf16* Ag = A + (size_t)(m0 + a_row) * K + a_c16 * 8;
    uint32_t a_s = S0 + a_row * PASTR + a_c16 * 16;
    int b_row = t >> 3;
    int b_c16 = (t & 7) * 2;
    const bf16* Bg = B + (size_t)b_row * N + n0 + b_c16 * 8;
    uint32_t b_s = S0 + H64_A + b_row * PBSTR + b_c16 * 16;

    auto prefetch = [&](int chunk) {
        int st = chunk % 3;
        const bf16* bg = Bg + (size_t)chunk * PBK * N;
        asm volatile("cp.async.cg.shared.global [%0], [%1], 16;"
                     :: "r"(a_s + st * H64_STG), "l"(Ag + chunk * PBK));
        asm volatile("cp.async.cg.shared.global [%0], [%1], 16;" :: "r"(b_s + st * H64_STG), "l"(bg));
        asm volatile("cp.async.cg.shared.global [%0], [%1], 16;" :: "r"(b_s + st * H64_STG + 16), "l"(bg + 8));
        asm volatile("cp.async.commit_group;");
    };

    uint32_t aoff[2], boff[2];
    #pragma unroll
    for (int mi = 0; mi < 2; ++mi)
        aoff[mi] = (wm + mi * 16 + (lane & 15)) * PASTR + (lane >> 4) * 16;
    int tile = lane >> 3;
    #pragma unroll
    for (int ni = 0; ni < 2; ++ni)
        boff[ni] = H64_A + ((tile & 1) * 8 + (lane & 7)) * PBSTR
                 + (wn + ni * 16 + (tile >> 1) * 8) * 2;

    float acc[2][4][4];
    #pragma unroll
    for (int mi = 0; mi < 2; ++mi)
        #pragma unroll
        for (int nj = 0; nj < 4; ++nj)
            #pragma unroll
            for (int r = 0; r < 4; ++r) acc[mi][nj][r] = 0.f;

    int niter = K / PBK;
    prefetch(0); prefetch(1);

    for (int it = 0; it < niter; ++it) {
        if (it + 1 < niter) asm volatile("cp.async.wait_group 1;");
        else                asm volatile("cp.async.wait_group 0;");
        __syncthreads();
        if (it + 2 < niter) prefetch(it + 2);

        uint32_t Sb = S0 + (it % 3) * H64_STG;
        #pragma unroll
        for (int kk = 0; kk < 2; ++kk) {
            uint32_t a[2][4];
            #pragma unroll
            for (int mi = 0; mi < 2; ++mi) {
                uint32_t addr = Sb + aoff[mi] + kk * 32;
                asm volatile("ldmatrix.sync.aligned.m8n8.x4.shared.b16 {%0,%1,%2,%3}, [%4];"
                    : "=r"(a[mi][0]), "=r"(a[mi][1]), "=r"(a[mi][2]), "=r"(a[mi][3]) : "r"(addr));
            }
            uint32_t bq[2][4];
            #pragma unroll
            for (int ni = 0; ni < 2; ++ni) {
                uint32_t addr = Sb + boff[ni] + kk * 16 * PBSTR;
                asm volatile("ldmatrix.sync.aligned.m8n8.x4.trans.shared.b16 {%0,%1,%2,%3}, [%4];"
                    : "=r"(bq[ni][0]), "=r"(bq[ni][1]), "=r"(bq[ni][2]), "=r"(bq[ni][3]) : "r"(addr));
            }
            #pragma unroll
            for (int mi = 0; mi < 2; ++mi)
                #pragma unroll
                for (int nj = 0; nj < 4; ++nj) {
                    uint32_t b0 = bq[nj >> 1][(nj & 1) * 2];
                    uint32_t b1 = bq[nj >> 1][(nj & 1) * 2 + 1];
                    asm volatile(
                        "mma.sync.aligned.m16n8k16.row.col.f32.bf16.bf16.f32 "
                        "{%0,%1,%2,%3}, {%4,%5,%6,%7}, {%8,%9}, {%0,%1,%2,%3};"
                        : "+f"(acc[mi][nj][0]), "+f"(acc[mi][nj][1]),
                          "+f"(acc[mi][nj][2]), "+f"(acc[mi][nj][3])
                        : "r"(a[mi][0]), "r"(a[mi][1]), "r"(a[mi][2]), "r"(a[mi][3]),
                          "r"(b0), "r"(b1));
                }
        }
    }

    int r_base = m0 + wm + (lane >> 2);
    int c_base = n0 + wn + (lane & 3) * 2;
    #pragma unroll
    for (int mi = 0; mi < 2; ++mi) {
        #pragma unroll
        for (int nj = 0; nj < 4; ++nj) {
            int r = r_base + mi * 16;
            int c = c_base + nj * 8;
            float bx2 = bias[c], by2 = bias[c + 1];
            float o00 = acc[mi][nj][0] + bx2;
            float o01 = acc[mi][nj][1] + by2;
            float o10 = acc[mi][nj][2] + bx2;
            float o11 = acc[mi][nj][3] + by2;
            if (EPI == 2) {
                const float* rp0 = resid + (size_t)r * N + c;
                const float* rp1 = resid + (size_t)(r + 8) * N + c;
                float* Cf = (float*)Cp;
                float2 v0 = {o00 + rp0[0], o01 + rp0[1]};
                float2 v1 = {o10 + rp1[0], o11 + rp1[1]};
                *(float2*)(Cf + (size_t)r * N + c) = v0;
                *(float2*)(Cf + (size_t)(r + 8) * N + c) = v1;
            } else {
                bf16* Cb = (bf16*)Cp;
                __nv_bfloat162 v0 = {__float2bfloat16(o00), __float2bfloat16(o01)};
                __nv_bfloat162 v1 = {__float2bfloat16(o10), __float2bfloat16(o11)};
                *(__nv_bfloat162*)(Cb + (size_t)r * N + c) = v0;
                *(__nv_bfloat162*)(Cb + (size_t)(r + 8) * N + c) = v1;
            }
        }
    }
}

// ========== K2: fused v-proj (bf16, 64x128) || off/attn (tf32, 64x128) =======
__global__ __launch_bounds__(256)
void fused_k2(const bf16* __restrict__ xnb, const bf16* __restrict__ wvb,
              const float* __restrict__ b_v, bf16* __restrict__ vb,
              const float* __restrict__ xn, const float* __restrict__ wcat,
              const float* __restrict__ bcat, float* __restrict__ offattn) {
    extern __shared__ char sm_[];
    if (blockIdx.z == 0)
        hgemm64_dev<0>(sm_, blockIdx.x, blockIdx.y, xnb, wvb, b_v, nullptr, vb, 256, 256);
    else
        tgemm64_dev(sm_, blockIdx.x, blockIdx.y, xn, wcat, bcat, offattn);
}

// ---------------- bf16 GEMM 128x128x32 (fc1, fc2), 3-stage -------------------
#define PBM 128
#define PBN 128
#define PA_ST (PBM * PASTR)
#define PB_ST (PBK * PBSTR)
#define PSTG  (PA_ST + PB_ST)
#define PSMEM (3 * PSTG)

template<int EPI>
__global__ __launch_bounds__(256)
void hgemm_kernel(const bf16* __restrict__ A, const bf16* __restrict__ B,
                  const float* __restrict__ bias, const float* __restrict__ resid,
                  void* __restrict__ Cp, int N, int K) {
    extern __shared__ char sm_[];
    uint32_t S0 = smem_u32(sm_);

    int t = threadIdx.x;
    int lane = t & 31, warp = t >> 5;
    int wm = (warp & 3) * 32;
    int wn = (warp >> 2) * 64;
    int m0 = blockIdx.y * PBM;
    int n0 = blockIdx.x * PBN;

    int a_row = t >> 1;
    int a_c16 = (t & 1) * 2;
    const bf16* Ag = A + (size_t)(m0 + a_row) * K + a_c16 * 8;
    uint32_t a_s = S0 + a_row * PASTR + a_c16 * 16;
    int b_row = t >> 3;
    int b_c16 = (t & 7) * 2;
    const bf16* Bg = B + (size_t)b_row * N + n0 + b_c16 * 8;
    uint32_t b_s = S0 + PA_ST + b_row * PBSTR + b_c16 * 16;

    auto prefetch = [&](int chunk) {
        int st = chunk % 3;
        const bf16* ag = Ag + chunk * PBK;
        const bf16* bg = Bg + (size_t)chunk * PBK * N;
        uint32_t sa = a_s + st * PSTG;
        uint32_t sb = b_s + st * PSTG;
        asm volatile("cp.async.cg.shared.global [%0], [%1], 16;" :: "r"(sa), "l"(ag));
        asm volatile("cp.async.cg.shared.global [%0], [%1], 16;" :: "r"(sa + 16), "l"(ag + 8));
        asm volatile("cp.async.cg.shared.global [%0], [%1], 16;" :: "r"(sb), "l"(bg));
        asm volatile("cp.async.cg.shared.global [%0], [%1], 16;" :: "r"(sb + 16), "l"(bg + 8));
        asm volatile("cp.async.commit_group;");
    };

    uint32_t aoff[2], boff[4];
    #pragma unroll
    for (int mi = 0; mi < 2; ++mi)
        aoff[mi] = (wm + mi * 16 + (lane & 15)) * PASTR + (lane >> 4) * 16;
    int tile = lane >> 3;
    #pragma unroll
    for (int ni = 0; ni < 4; ++ni)
        boff[ni] = PA_ST + ((tile & 1) * 8 + (lane & 7)) * PBSTR
                 + (wn + ni * 16 + (tile >> 1) * 8) * 2;

    float acc[2][8][4];
    #pragma unroll
    for (int mi = 0; mi < 2; ++mi)
        #pragma unroll
        for (int nj = 0; nj < 8; ++nj)
            #pragma unroll
            for (int r = 0; r < 4; ++r) acc[mi][nj][r] = 0.f;

    int niter = K / PBK;
    prefetch(0);
    prefetch(1);

    for (int it = 0; it < niter; ++it) {
        if (it + 1 < niter) asm volatile("cp.async.wait_group 1;");
        else                asm volatile("cp.async.wait_group 0;");
        __syncthreads();
        if (it + 2 < niter) prefetch(it + 2);

        uint32_t Sb = S0 + (it % 3) * PSTG;
        #pragma unroll
        for (int kk = 0; kk < 2; ++kk) {
            uint32_t a[2][4];
            #pragma unroll
            for (int mi = 0; mi < 2; ++mi) {
                uint32_t addr = Sb + aoff[mi] + kk * 32;
                asm volatile("ldmatrix.sync.aligned.m8n8.x4.shared.b16 {%0,%1,%2,%3}, [%4];"
                    : "=r"(a[mi][0]), "=r"(a[mi][1]), "=r"(a[mi][2]), "=r"(a[mi][3]) : "r"(addr));
            }
            uint32_t bq[4][4];
            #pragma unroll
            for (int ni = 0; ni < 4; ++ni) {
                uint32_t addr = Sb + boff[ni] + kk * 16 * PBSTR;
                asm volatile("ldmatrix.sync.aligned.m8n8.x4.trans.shared.b16 {%0,%1,%2,%3}, [%4];"
                    : "=r"(bq[ni][0]), "=r"(bq[ni][1]), "=r"(bq[ni][2]), "=r"(bq[ni][3]) : "r"(addr));
            }
            #pragma unroll
            for (int mi = 0; mi < 2; ++mi)
                #pragma unroll
                for (int nj = 0; nj < 8; ++nj) {
                    uint32_t b0 = bq[nj >> 1][(nj & 1) * 2];
                    uint32_t b1 = bq[nj >> 1][(nj & 1) * 2 + 1];
                    asm volatile(
                        "mma.sync.aligned.m16n8k16.row.col.f32.bf16.bf16.f32 "
                        "{%0,%1,%2,%3}, {%4,%5,%6,%7}, {%8,%9}, {%0,%1,%2,%3};"
                        : "+f"(acc[mi][nj][0]), "+f"(acc[mi][nj][1]),
                          "+f"(acc[mi][nj][2]), "+f"(acc[mi][nj][3])
                        : "r"(a[mi][0]), "r"(a[mi][1]), "r"(a[mi][2]), "r"(a[mi][3]),
                          "r"(b0), "r"(b1));
                }
        }
    }

    int r_base = m0 + wm + (lane >> 2);
    int c_base = n0 + wn + (lane & 3) * 2;
    #pragma unroll
    for (int mi = 0; mi < 2; ++mi) {
        #pragma unroll
        for (int nj = 0; nj < 8; ++nj) {
            int r = r_base + mi * 16;
            int c = c_base + nj * 8;
            float bx = bias[c], by = bias[c + 1];
            float o00 = acc[mi][nj][0] + bx;
            float o01 = acc[mi][nj][1] + by;
            float o10 = acc[mi][nj][2] + bx;
            float o11 = acc[mi][nj][3] + by;
            if (EPI == 1) {
                o00 = gelu_f(o00); o01 = gelu_f(o01);
                o10 = gelu_f(o10); o11 = gelu_f(o11);
            }
            if (EPI == 2) {
                const float* rp0 = resid + (size_t)r * N + c;
                const float* rp1 = resid + (size_t)(r + 8) * N + c;
                float* Cf = (float*)Cp;
                float2 v0 = {o00 + rp0[0], o01 + rp0[1]};
                float2 v1 = {o10 + rp1[0], o11 + rp1[1]};
                *(float2*)(Cf + (size_t)r * N + c) = v0;
                *(float2*)(Cf + (size_t)(r + 8) * N + c) = v1;
            } else {
                bf16* Cb = (bf16*)Cp;
                __nv_bfloat162 v0 = {__float2bfloat16(o00), __float2bfloat16(o01)};
                __nv_bfloat162 v1 = {__float2bfloat16(o10), __float2bfloat16(o11)};
                *(__nv_bfloat162*)(Cb + (size_t)r * N + c) = v0;
                *(__nv_bfloat162*)(Cb + (size_t)(r + 8) * N + c) = v1;
            }
        }
    }
}

// ======== fused wout GEMM + residual + LN2: register-resident LN epilogue ====
// Stats-only smem reduction: partials [64 rows][4 col-groups][2] = 2 KB.
#define QBM 64
#define QASTR 80
#define QBSTR 528
#define QA_SZ (QBM * QASTR)
#define QB_SZ (32 * QBSTR)
#define QSTG  (QA_SZ + QB_SZ)
#define QSMEM (3 * QSTG)

__global__ __launch_bounds__(256)
void hgemm_wout_ln(const bf16* __restrict__ A, const bf16* __restrict__ B,
                   const float* __restrict__ bias, const float* __restrict__ resid,
                   float* __restrict__ xres, const float* __restrict__ g2,
                   const float* __restrict__ b2g, bf16* __restrict__ yb) {
    extern __shared__ char sm_[];
    uint32_t S0 = smem_u32(sm_);
    int t = threadIdx.x;
    int lane = t & 31, warp = t >> 5;
    int wm = (warp & 1) * 32;
    int wn = (warp >> 1) * 64;
    int wng = warp >> 1;            // col-group 0..3
    int m0 = blockIdx.x * QBM;

    int a_row = t >> 2, a_c16 = t & 3;
    const bf16* Ag = A + (size_t)(m0 + a_row) * 256 + a_c16 * 8;
    uint32_t a_s = S0 + a_row * QASTR + a_c16 * 16;

    auto prefetch = [&](int ck) {
        int st = ck % 3;
        asm volatile("cp.async.cg.shared.global [%0], [%1], 16;"
                     :: "r"(a_s + st * QSTG), "l"(Ag + ck * 32));
        #pragma unroll
        for (int i = 0; i < 4; ++i) {
            int idx = t + i * 256;
            int row = idx >> 5, c16 = idx & 31;
            const bf16* bg = B + (size_t)(ck * 32 + row) * 256 + c16 * 8;
            uint32_t dst = S0 + st * QSTG + QA_SZ + row * QBSTR + c16 * 16;
            asm volatile("cp.async.cg.shared.global [%0], [%1], 16;" :: "r"(dst), "l"(bg));
        }
        asm volatile("cp.async.commit_group;");
    };

    uint32_t aoff[2], boff[4];
    #pragma unroll
    for (int mi = 0; mi < 2; ++mi)
        aoff[mi] = (wm + mi * 16 + (lane & 15)) * QASTR + (lane >> 4) * 16;
    int tile = lane >> 3;
    #pragma unroll
    for (int ni = 0; ni < 4; ++ni)
        boff[ni] = QA_SZ + ((tile & 1) * 8 + (lane & 7)) * QBSTR
                 + (wn + ni * 16 + (tile >> 1) * 8) * 2;

    float acc[2][8][4];
    #pragma unroll
    for (int mi = 0; mi < 2; ++mi)
        #pragma unroll
        for (int nj = 0; nj < 8; ++nj)
            #pragma unroll
            for (int r = 0; r < 4; ++r) acc[mi][nj][r] = 0.f;

    const int niter = 8;
    prefetch(0); prefetch(1);

    for (int it = 0; it < niter; ++it) {
        if (it + 1 < niter) asm volatile("cp.async.wait_group 1;");
        else                asm volatile("cp.async.wait_group 0;");
        __syncthreads();
        if (it + 2 < niter) prefetch(it + 2);

        uint32_t Sb = S0 + (it % 3) * QSTG;
        #pragma unroll
        for (int kk = 0; kk < 2; ++kk) {
            uint32_t a[2][4];
            #pragma unroll
            for (int mi = 0; mi < 2; ++mi) {
                uint32_t addr = Sb + aoff[mi] + kk * 32;
                asm volatile("ldmatrix.sync.aligned.m8n8.x4.shared.b16 {%0,%1,%2,%3}, [%4];"
                    : "=r"(a[mi][0]), "=r"(a[mi][1]), "=r"(a[mi][2]), "=r"(a[mi][3]) : "r"(addr));
            }
            uint32_t bq[4][4];
            #pragma unroll
            for (int ni = 0; ni < 4; ++ni) {
                uint32_t addr = Sb + boff[ni] + kk * 16 * QBSTR;
                asm volatile("ldmatrix.sync.aligned.m8n8.x4.trans.shared.b16 {%0,%1,%2,%3}, [%4];"
                    : "=r"(bq[ni][0]), "=r"(bq[ni][1]), "=r"(bq[ni][2]), "=r"(bq[ni][3]) : "r"(addr));
            }
            #pragma unroll
            for (int mi = 0; mi < 2; ++mi)
                #pragma unroll
                for (int nj = 0; nj < 8; ++nj) {
                    uint32_t b0 = bq[nj >> 1][(nj & 1) * 2];
                    uint32_t b1 = bq[nj >> 1][(nj & 1) * 2 + 1];
                    asm volatile(
                        "mma.sync.aligned.m16n8k16.row.col.f32.bf16.bf16.f32 "
                        "{%0,%1,%2,%3}, {%4,%5,%6,%7}, {%8,%9}, {%0,%1,%2,%3};"
                        : "+f"(acc[mi][nj][0]), "+f"(acc[mi][nj][1]),
                          "+f"(acc[mi][nj][2]), "+f"(acc[mi][nj][3])
                        : "r"(a[mi][0]), "r"(a[mi][1]), "r"(a[mi][2]), "r"(a[mi][3]),
                          "r"(b0), "r"(b1));
                }
        }
    }

    // ---- fold bias + residual into acc; write xres ----
    int lr0 = wm + (lane >> 2);           // local row base
    int cb = wn + (lane & 3) * 2;         // column base
    #pragma unroll
    for (int mi = 0; mi < 2; ++mi) {
        #pragma unroll
        for (int nj = 0; nj < 8; ++nj) {
            int rl = lr0 + mi * 16;
            int c = cb + nj * 8;
            float bx = bias[c], by = bias[c + 1];
            const float* rp0 = resid + (size_t)(m0 + rl) * 256 + c;
            const float* rp1 = resid + (size_t)(m0 + rl + 8) * 256 + c;
            acc[mi][nj][0] += bx + rp0[0];
            acc[mi][nj][1] += by + rp0[1];
            acc[mi][nj][2] += bx + rp1[0];
            acc[mi][nj][3] += by + rp1[1];
            float2 v0 = {acc[mi][nj][0], acc[mi][nj][1]};
            float2 v1 = {acc[mi][nj][2], acc[mi][nj][3]};
            *(float2*)(xres + (size_t)(m0 + rl) * 256 + c) = v0;
            *(float2*)(xres + (size_t)(m0 + rl + 8) * 256 + c) = v1;
        }
    }

    // ---- per-thread partial sums for its 4 rows (rl0, rl0+8, rl0+16, rl0+24) ----
    // row index within thread: idx = mi*2 + (upper?1:0) -> rows lr0+16mi (+8)
    float ls[4], lq[4];
    #pragma unroll
    for (int i = 0; i < 4; ++i) { ls[i] = 0.f; lq[i] = 0.f; }
    #pragma unroll
    for (int mi = 0; mi < 2; ++mi) {
        #pragma unroll
        for (int nj = 0; nj < 8; ++nj) {
            float a0 = acc[mi][nj][0], a1 = acc[mi][nj][1];
            float a2 = acc[mi][nj][2], a3 = acc[mi][nj][3];
            ls[mi * 2]     += a0 + a1;  lq[mi * 2]     += a0 * a0 + a1 * a1;
            ls[mi * 2 + 1] += a2 + a3;  lq[mi * 2 + 1] += a2 * a2 + a3 * a3;
        }
    }
    // intra-warp: reduce across the 4 lanes sharing a row (lane&3 varies)
    #pragma unroll
    for (int o = 1; o <= 2; o <<= 1) {
        #pragma unroll
        for (int i = 0; i < 4; ++i) {
            ls[i] += __shfl_xor_sync(0xffffffffu, ls[i], o);
            lq[i] += __shfl_xor_sync(0xffffffffu, lq[i], o);
        }
    }
    // stage warp partials (sync first: smem stage buffers still being read? no —
    // mainloop done and all MMA reads complete; but other warps may still read
    // stage smem? MMA reads finished at final wait_group+syncthreads in loop's
    // last iteration... last iteration has no trailing sync -> need one here)
    __syncthreads();
    float* part = (float*)sm_;   // [64][4][2] = 2048 B
    if ((lane & 3) == 0) {
        int rbase = wm + (lane >> 2);
        #pragma unroll
        for (int i = 0; i < 4; ++i) {
            int rl = rbase + (i >> 1) * 16 + (i & 1) * 8;
            part[(rl * 4 + wng) * 2 + 0] = ls[i];
            part[(rl * 4 + wng) * 2 + 1] = lq[i];
        }
    }
    __syncthreads();

    // ---- stats for this thread's 4 rows (fixed-order read -> deterministic) ----
    float mean[4], inv[4];
    #pragma unroll
    for (int i = 0; i < 4; ++i) {
        int rl = lr0 + (i >> 1) * 16 + (i & 1) * 8;
        float s = 0.f, q = 0.f;
        #pragma unroll
        for (int gIdx = 0; gIdx < 4; ++gIdx) {
            s += part[(rl * 4 + gIdx) * 2 + 0];
            q += part[(rl * 4 + gIdx) * 2 + 1];
        }
        float m = s * (1.0f / 256.0f);
        float var = q * (1.0f / 256.0f) - m * m;
        mean[i] = m;
        inv[i] = rsqrtf(var + 1e-5f);
    }

    // ---- normalize register values, write yb ----
    #pragma unroll
    for (int mi = 0; mi < 2; ++mi) {
        #pragma unroll
        for (int nj = 0; nj < 8; ++nj) {
            int rl = lr0 + mi * 16;
            int c = cb + nj * 8;
            float gx = g2[c], gy = g2[c + 1];
            float bbx = b2g[c], bby = b2g[c + 1];
            int i0 = mi * 2, i1 = mi * 2 + 1;
            float o00 = (acc[mi][nj][0] - mean[i0]) * inv[i0] * gx + bbx;
            float o01 = (acc[mi][nj][1] - mean[i0]) * inv[i0] * gy + bby;
            float o10 = (acc[mi][nj][2] - mean[i1]) * inv[i1] * gx + bbx;
            float o11 = (acc[mi][nj][3] - mean[i1]) * inv[i1] * gy + bby;
            __nv_bfloat162 y0 = {__float2bfloat16(o00), __float2bfloat16(o01)};
            __nv_bfloat162 y1 = {__float2bfloat16(o10), __float2bfloat16(o11)};
            *(__nv_bfloat162*)(yb + (size_t)(m0 + rl) * 256 + c) = y0;
            *(__nv_bfloat162*)(yb + (size_t)(m0 + rl + 8) * 256 + c) = y1;
        }
    }
}

// ---------------- Deformable sampling: one warp = (token, head-pair) ---------
__global__ void sample_kernel(const bf16* __restrict__ v, const float* __restrict__ offattn,
                              const float* __restrict__ rp, bf16* __restrict__ agg) {
    int gw = blockIdx.x * 8 + (threadIdx.x >> 5);
    int lane = threadIdx.x & 31;
    int tg = gw >> 2;
    int head = ((gw & 3) << 1) + (lane >> 4);
    int l16 = lane & 15;
    int bb = tg >> 13;
    int pos = tg & 8191;

    const float* lg = offattn + (size_t)tg * 256 + 144 + head * 9;
    float w[9];
    float mx = -1e30f;
    #pragma unroll
    for (int k = 0; k < 9; ++k) { w[k] = lg[k]; mx = fmaxf(mx, w[k]); }
    float sum = 0.f;
    #pragma unroll
    for (int k = 0; k < 9; ++k) { w[k] = expf(w[k] - mx); sum += w[k]; }
    float inv = 1.0f / sum;

    const float* rpp  = rp + (size_t)pos * 18;
    const float* offp = offattn + (size_t)tg * 256 + head * 18;
    const __nv_bfloat162* vc = (const __nv_bfloat162*)v + head * 16 + l16;
    int base = bb << 13;
    float a0 = 0.f, a1 = 0.f;
    #pragma unroll
    for (int k = 0; k < 9; ++k) {
        float cx = (rpp[k * 2 + 0] + offp[k * 2 + 0] + 1.0f) * 0.5f * 127.0f;
        float cy = (rpp[k * 2 + 1] + offp[k * 2 + 1] + 1.0f) * 0.5f * 63.0f;
        float fx = floorf(cx), fy = floorf(cy);
        float wx = cx - fx, wy = cy - fy;
        int x0 = min(max((int)fx, 0), 127);
        int x1 = min(max((int)fx + 1, 0), 127);
        int y0 = min(max((int)fy, 0), 63);
        int y1 = min(max((int)fy + 1, 0), 63);
        float2 v00 = __bfloat1622float2(vc[(size_t)(base + y0 * 128 + x0) * 128]);
        float2 v01 = __bfloat1622float2(vc[(size_t)(base + y0 * 128 + x1) * 128]);
        float2 v10 = __bfloat1622float2(vc[(size_t)(base + y1 * 128 + x0) * 128]);
        float2 v11 = __bfloat1622float2(vc[(size_t)(base + y1 * 128 + x1) * 128]);
        float w00 = (1.f - wy) * (1.f - wx), w01 = (1.f - wy) * wx;
        float w10 = wy * (1.f - wx),         w11 = wy * wx;
        float wk = w[k] * inv;
        a0 += (v00.x * w00 + v01.x * w01 + v10.x * w10 + v11.x * w11) * wk;
        a1 += (v00.y * w00 + v01.y * w01 + v10.y * w10 + v11.y * w11) * wk;
    }
    __nv_bfloat162 ov = {__float2bfloat16(a0), __float2bfloat16(a1)};
    *(__nv_bfloat162*)(agg + (size_t)tg * 256 + head * 32 + l16 * 2) = ov;
}

// ---------------- Depthwise 3x3 conv: sliding window, 4-way x-split ----------
__global__ void dwconv_kernel(const bf16* __restrict__ h, const float* __restrict__ wdw,
                              const float* __restrict__ bdw, bf16* __restrict__ o) {
    int c2 = blockIdx.x * 256 + threadIdx.x;
    int y = blockIdx.y & 63;
    int seg = blockIdx.y >> 6;
    int bb = blockIdx.z;
    int c = c2 * 2;
    int x0 = seg * 32;

    float w0[9], w1[9];
    #pragma unroll
    for (int i = 0; i < 9; ++i) { w0[i] = wdw[c * 9 + i]; w1[i] = wdw[(c + 1) * 9 + i]; }
    float bb0 = bdw[c], bb1 = bdw[c + 1];

    const __nv_bfloat162* hp = (const __nv_bfloat162*)h;
    size_t base = ((size_t)(bb << 13) + y * 128) * 512 + c2;
    bool hu = (y > 0), hd = (y < 63);
    __nv_bfloat162 zero = __float2bfloat162_rn(0.f);

    __nv_bfloat162 cm[3], cc[3], cn[3];
    {
        size_t p = base + ((x0 + 127) & 127) * 512;
        cm[0] = hu ? hp[p - 65536] : zero; cm[1] = hp[p]; cm[2] = hd ? hp[p + 65536] : zero;
        p = base + x0 * 512;
        cc[0] = hu ? hp[p - 65536] : zero; cc[1] = hp[p]; cc[2] = hd ? hp[p + 65536] : zero;
    }
    bf16* op = o + ((size_t)(bb << 13) + y * 128) * 1024 + c;

    for (int x = x0; x < x0 + 32; ++x) {
        size_t p = base + ((x + 1) & 127) * 512;
        cn[0] = hu ? hp[p - 65536] : zero; cn[1] = hp[p]; cn[2] = hd ? hp[p + 65536] : zero;

        float a0 = bb0, a1 = bb1;
        #pragma unroll
        for (int dy = 0; dy < 3; ++dy) {
            float2 vm = __bfloat1622float2(cm[dy]);
            float2 vc = __bfloat1622float2(cc[dy]);
            float2 vp = __bfloat1622float2(cn[dy]);
            a0 += vm.x * w0[dy * 3 + 0] + vc.x * w0[dy * 3 + 1] + vp.x * w0[dy * 3 + 2];
            a1 += vm.y * w1[dy * 3 + 0] + vc.y * w1[dy * 3 + 1] + vp.y * w1[dy * 3 + 2];
        }
        __nv_bfloat162 ov = {__float2bfloat16(gelu_f(a0)), __float2bfloat16(gelu_f(a1))};
        *(__nv_bfloat162*)(op + (size_t)x * 1024) = ov;

        #pragma unroll
        for (int i = 0; i < 3; ++i) { cm[i] = cc[i]; cc[i] = cn[i]; }
    }
}

// ---------------- launch ----------------
extern "C" void kernel_launch(void* const* d_in, const int* in_sizes, int n_in,
                              void* d_out, int out_size) {
    const float* x      = (const float*)d_in[0];
    const float* rp     = (const float*)d_in[1];
    const float* ln1_g  = (const float*)d_in[2];
    const float* ln1_b  = (const float*)d_in[3];
    const float* w_v    = (const float*)d_in[4];
    const float* b_v    = (const float*)d_in[5];
    const float* w_off  = (const float*)d_in[6];
    const float* b_off  = (const float*)d_in[7];
    const float* w_attn = (const float*)d_in[8];
    const float* b_attn = (const float*)d_in[9];
    const float* w_out  = (const float*)d_in[10];
    const float* b_out  = (const float*)d_in[11];
    const float* ln2_g  = (const float*)d_in[12];
    const float* ln2_b  = (const float*)d_in[13];
    const float* w1     = (const float*)d_in[14];
    const float* b1     = (const float*)d_in[15];
    const float* w_dw   = (const float*)d_in[16];
    const float* b_dw   = (const float*)d_in[17];
    const float* w2     = (const float*)d_in[18];
    const float* b2     = (const float*)d_in[19];
    float* out = (float*)d_out;

    float *xn, *offattn, *xres, *wcat, *bcat;
    bf16 *xnb, *vb, *aggb, *yb, *hb, *h2b, *wvb, *woutb, *w1b, *w2b;
    cudaGetSymbolAddress((void**)&xn,      g_xn);
    cudaGetSymbolAddress((void**)&offattn, g_offattn);
    cudaGetSymbolAddress((void**)&xres,    g_xres);
    cudaGetSymbolAddress((void**)&wcat,    g_wcat);
    cudaGetSymbolAddress((void**)&bcat,    g_bcat);
    cudaGetSymbolAddress((void**)&xnb,     g_xnb);
    cudaGetSymbolAddress((void**)&vb,      g_vb);
    cudaGetSymbolAddress((void**)&aggb,    g_aggb);
    cudaGetSymbolAddress((void**)&yb,      g_yb);
    cudaGetSymbolAddress((void**)&hb,      g_hb);
    cudaGetSymbolAddress((void**)&h2b,     g_h2b);
    cudaGetSymbolAddress((void**)&wvb,     g_wvb);
    cudaGetSymbolAddress((void**)&woutb,   g_woutb);
    cudaGetSymbolAddress((void**)&w1b,     g_w1b);
    cudaGetSymbolAddress((void**)&w2b,     g_w2b);

    cudaFuncSetAttribute(hgemm_kernel<1>, cudaFuncAttributeMaxDynamicSharedMemorySize, PSMEM);
    cudaFuncSetAttribute(hgemm_kernel<2>, cudaFuncAttributeMaxDynamicSharedMemorySize, PSMEM);
    cudaFuncSetAttribute(fused_k2,        cudaFuncAttributeMaxDynamicSharedMemorySize, H64_SMEM);
    cudaFuncSetAttribute(hgemm_wout_ln,   cudaFuncAttributeMaxDynamicSharedMemorySize, QSMEM);

    // K1: LN1 || weight prep
    prep_ln_kernel<<<NTOK + 2816, 256>>>(
        x, ln1_g, ln1_b, xn, xnb,
        w_v, w_out, w1, w2, w_off, w_attn, b_off, b_attn,
        wvb, woutb, w1b, w2b, wcat, bcat);
    // K2: v projection || offsets+attn (resource-matched 64x128 bodies)
    fused_k2<<<dim3(2, NTOK / 64, 2), 256, H64_SMEM>>>(
        xnb, wvb, b_v, vb, xn, wcat, bcat, offattn);
    // K3: softmax + bilinear sampling + aggregation
    sample_kernel<<<NTOK / 2, 256>>>(vb, offattn, rp, aggb);
    // K4: output proj + residual + LN2 fused (register-resident LN)
    hgemm_wout_ln<<<NTOK / QBM, 256, QSMEM>>>(aggb, woutb, b_out, x, xres, ln2_g, ln2_b, yb);
    // K5: fc1 + GELU (bf16 TC, 128x128)
    hgemm_kernel<1><<<dim3(HID / PBN, NTOK / PBM), 256, PSMEM>>>(yb, w1b, b1, nullptr, hb, HID, 256);
    // K6: depthwise conv + GELU
    dwconv_kernel<<<dim3(2, 256, 2), 256>>>(hb, w_dw, b_dw, h2b);
    // K7: fc2 + residual -> out (f32, 128x128)
    hgemm_kernel<2><<<dim3(256 / PBN, NTOK / PBM), 256, PSMEM>>>(h2b, w2b, b2, xres, out, 256, 1024);
}

// round 14
// speedup vs baseline: 1.0335x; 1.0064x over previous
#include <cuda_runtime.h>
#include <cuda_bf16.h>
#include <math.h>
#include <stdint.h>

typedef __nv_bfloat16 bf16;

#define NTOK 16384
#define CDIM 256
#define HID  1024

// -------- scratch (__device__ globals; no allocations allowed) --------
__device__ float g_xn     [NTOK * CDIM];
__device__ float g_offattn[NTOK * 256];
__device__ float g_xres   [NTOK * CDIM];
__device__ bf16  g_xnb    [NTOK * CDIM];
__device__ bf16  g_vb     [NTOK * CDIM];
__device__ bf16  g_aggb   [NTOK * CDIM];
__device__ bf16  g_yb     [NTOK * CDIM];
__device__ bf16  g_hb     [NTOK * HID];
__device__ bf16  g_h2b    [NTOK * HID];
__device__ bf16  g_wvb    [256 * 256];
__device__ bf16  g_woutb  [256 * 256];
__device__ bf16  g_w1b    [256 * 1024];
__device__ bf16  g_w2b    [1024 * 256];
__device__ float g_wcat   [256 * 256];
__device__ float g_bcat   [256];

__device__ __forceinline__ float gelu_f(float v) {
    return 0.5f * v * (1.0f + erff(v * 0.7071067811865476f));
}

__device__ __forceinline__ uint32_t smem_u32(const void* p) {
    uint32_t a;
    asm("{ .reg .u64 t; cvta.to.shared.u64 t, %1; cvt.u32.u64 %0, t; }" : "=r"(a) : "l"(p));
    return a;
}

__device__ __forceinline__ uint32_t f2tf32(float f) {
    uint32_t r;
    asm("cvt.rna.tf32.f32 %0, %1;" : "=r"(r) : "f"(f));
    return r;
}

// ================= K1: fused prep + LN1 (block-range dispatch) =================
__global__ void prep_ln_kernel(
    const float* __restrict__ x, const float* __restrict__ g, const float* __restrict__ b,
    float* __restrict__ xn, bf16* __restrict__ xnb,
    const float* wv, const float* wout, const float* w1, const float* w2,
    const float* w_off, const float* w_attn, const float* b_off, const float* b_attn,
    bf16* wvb, bf16* woutb, bf16* w1b, bf16* w2b, float* wcat, float* bcat) {
    if (blockIdx.x < NTOK) {
        int tok = blockIdx.x;
        int c = threadIdx.x;
        float v = x[(size_t)tok * CDIM + c];
        __shared__ float sh[8];
        float s = v;
        #pragma unroll
        for (int o = 16; o; o >>= 1) s += __shfl_xor_sync(0xffffffffu, s, o);
        if ((c & 31) == 0) sh[c >> 5] = s;
        __syncthreads();
        float tot = 0.f;
        #pragma unroll
        for (int i = 0; i < 8; ++i) tot += sh[i];
        float mean = tot * (1.0f / CDIM);
        __syncthreads();
        float d = v - mean;
        float s2 = d * d;
        #pragma unroll
        for (int o = 16; o; o >>= 1) s2 += __shfl_xor_sync(0xffffffffu, s2, o);
        if ((c & 31) == 0) sh[c >> 5] = s2;
        __syncthreads();
        float v2 = 0.f;
        #pragma unroll
        for (int i = 0; i < 8; ++i) v2 += sh[i];
        float var = v2 * (1.0f / CDIM);
        float out = d * rsqrtf(var + 1e-5f) * g[c] + b[c];
        xn[(size_t)tok * CDIM + c]  = __uint_as_float(f2tf32(out));
        xnb[(size_t)tok * CDIM + c] = __float2bfloat16(out);
        return;
    }
    int i = (blockIdx.x - NTOK) * 256 + threadIdx.x;
    if (i < 65536) { wvb[i] = __float2bfloat16(wv[i]); return; }
    i -= 65536;
    if (i < 65536) { woutb[i] = __float2bfloat16(wout[i]); return; }
    i -= 65536;
    if (i < 262144) { w1b[i] = __float2bfloat16(w1[i]); return; }
    i -= 262144;
    if (i < 262144) { w2b[i] = __float2bfloat16(w2[i]); return; }
    i -= 262144;
    if (i < 65536) {
        int k = i >> 8, col = i & 255;
        float v = (col < 144) ? w_off[k * 144 + col]
                : (col < 216) ? w_attn[k * 72 + (col - 144)] : 0.f;
        wcat[i] = __uint_as_float(f2tf32(v));
        if (k == 0)
            bcat[col] = (col < 144) ? b_off[col]
                      : (col < 216) ? b_attn[col - 144] : 0.f;
    }
}

// ---------------- shared GEMM geometry constants ----------------
#define PBK 32
#define PASTR 80
#define PBSTR 272
#define H64_A  (64 * PASTR)
#define H64_B  (PBK * PBSTR)
#define H64_STG (H64_A + H64_B)
#define H64_SMEM (3 * H64_STG)
#define TFA_STR 20
#define TFB_STR 136
#define TFA_SZ  (64 * TFA_STR * 4)
#define TFB_SZ  (16 * TFB_STR * 4)
#define TF_STG  (TFA_SZ + TFB_SZ)

// ---------------- tf32 GEMM device body: 64x128x16, 3-stage ------------------
__device__ void tgemm64_dev(char* sm_, int bx, int by,
                            const float* __restrict__ A, const float* __restrict__ Bw,
                            const float* __restrict__ bias, float* __restrict__ C) {
    uint32_t S0 = smem_u32(sm_);
    int t = threadIdx.x;
    int lane = t & 31, warp = t >> 5;
    int wm = (warp & 1) * 32;
    int wn = (warp >> 1) * 32;
    int m0 = by * 64;
    int n0 = bx * 128;

    int a_row = t >> 2, a_c4 = (t & 3) * 4;
    const float* Ag = A + (size_t)(m0 + a_row) * 256 + a_c4;
    uint32_t a_s = S0 + (a_row * TFA_STR + a_c4) * 4;

    auto prefetch = [&](int it) {
        int st = it % 3;
        asm volatile("cp.async.cg.shared.global [%0], [%1], 16;"
                     :: "r"(a_s + st * TF_STG), "l"(Ag + it * 16));
        #pragma unroll
        for (int i = 0; i < 2; ++i) {
            int idx = t + i * 256;
            int row = idx >> 5, c4 = (idx & 31) * 4;
            const float* bg = Bw + (size_t)(it * 16 + row) * 256 + n0 + c4;
            uint32_t dst = S0 + TFA_SZ + (row * TFB_STR + c4) * 4 + st * TF_STG;
            asm volatile("cp.async.cg.shared.global [%0], [%1], 16;" :: "r"(dst), "l"(bg));
        }
        asm volatile("cp.async.commit_group;");
    };

    float acc[2][4][4];
    #pragma unroll
    for (int mi = 0; mi < 2; ++mi)
        #pragma unroll
        for (int nj = 0; nj < 4; ++nj)
            #pragma unroll
            for (int r = 0; r < 4; ++r) acc[mi][nj][r] = 0.f;

    const int niter = 16;
    prefetch(0); prefetch(1);

    int lr = lane >> 2, lc = lane & 3;
    for (int it = 0; it < niter; ++it) {
        if (it + 1 < niter) asm volatile("cp.async.wait_group 1;");
        else                asm volatile("cp.async.wait_group 0;");
        __syncthreads();
        if (it + 2 < niter) prefetch(it + 2);

        const uint32_t* As = (const uint32_t*)(sm_ + (it % 3) * TF_STG);
        const uint32_t* Bs = (const uint32_t*)(sm_ + (it % 3) * TF_STG + TFA_SZ);

        #pragma unroll
        for (int kk = 0; kk < 2; ++kk) {
            uint32_t af[2][4];
            #pragma unroll
            for (int mi = 0; mi < 2; ++mi) {
                int rb = wm + mi * 16 + lr;
                af[mi][0] = As[rb * TFA_STR + kk * 8 + lc];
                af[mi][1] = As[(rb + 8) * TFA_STR + kk * 8 + lc];
                af[mi][2] = As[rb * TFA_STR + kk * 8 + lc + 4];
                af[mi][3] = As[(rb + 8) * TFA_STR + kk * 8 + lc + 4];
            }
            #pragma unroll
            for (int nj = 0; nj < 4; ++nj) {
                uint32_t b0 = Bs[(kk * 8 + lc) * TFB_STR + wn + nj * 8 + lr];
                uint32_t b1 = Bs[(kk * 8 + lc + 4) * TFB_STR + wn + nj * 8 + lr];
                #pragma unroll
                for (int mi = 0; mi < 2; ++mi)
                    asm volatile(
                        "mma.sync.aligned.m16n8k8.row.col.f32.tf32.tf32.f32 "
                        "{%0,%1,%2,%3}, {%4,%5,%6,%7}, {%8,%9}, {%0,%1,%2,%3};"
                        : "+f"(acc[mi][nj][0]), "+f"(acc[mi][nj][1]),
                          "+f"(acc[mi][nj][2]), "+f"(acc[mi][nj][3])
                        : "r"(af[mi][0]), "r"(af[mi][1]), "r"(af[mi][2]), "r"(af[mi][3]),
                          "r"(b0), "r"(b1));
            }
        }
    }

    #pragma unroll
    for (int mi = 0; mi < 2; ++mi) {
        #pragma unroll
        for (int nj = 0; nj < 4; ++nj) {
            int r = m0 + wm + mi * 16 + lr;
            int c = n0 + wn + nj * 8 + lc * 2;
            float bx2 = bias[c], by2 = bias[c + 1];
            float2 v0 = {acc[mi][nj][0] + bx2, acc[mi][nj][1] + by2};
            float2 v1 = {acc[mi][nj][2] + bx2, acc[mi][nj][3] + by2};
            *(float2*)(C + (size_t)r * 256 + c) = v0;
            *(float2*)(C + (size_t)(r + 8) * 256 + c) = v1;
        }
    }
}

// ---------------- bf16 GEMM device body: 64x128x32, 3-stage ------------------
template<int EPI>
__device__ void hgemm64_dev(char* sm_, int bx, int by,
                            const bf16* __restrict__ A, const bf16* __restrict__ B,
                            const float* __restrict__ bias, const float* __restrict__ resid,
                            void* __restrict__ Cp, int N, int K) {
    uint32_t S0 = smem_u32(sm_);
    int t = threadIdx.x;
    int lane = t & 31, warp = t >> 5;
    int wm = (warp & 1) * 32;
    int wn = (warp >> 1) * 32;
    int m0 = by * 64;
    int n0 = bx * 128;

    int a_row = t >> 2, a_c16 = t & 3;
    const bf16* Ag = A + (size_t)(m0 + a_row) * K + a_c16 * 8;
    uint32_t a_s = S0 + a_row * PASTR + a_c16 * 16;
    int b_row = t >> 3;
    int b_c16 = (t & 7) * 2;
    const bf16* Bg = B + (size_t)b_row * N + n0 + b_c16 * 8;
    uint32_t b_s = S0 + H64_A + b_row * PBSTR + b_c16 * 16;

    auto prefetch = [&](int chunk) {
        int st = chunk % 3;
        const bf16* bg = Bg + (size_t)chunk * PBK * N;
        asm volatile("cp.async.cg.shared.global [%0], [%1], 16;"
                     :: "r"(a_s + st * H64_STG), "l"(Ag + chunk * PBK));
        asm volatile("cp.async.cg.shared.global [%0], [%1], 16;" :: "r"(b_s + st * H64_STG), "l"(bg));
        asm volatile("cp.async.cg.shared.global [%0], [%1], 16;" :: "r"(b_s + st * H64_STG + 16), "l"(bg + 8));
        asm volatile("cp.async.commit_group;");
    };

    uint32_t aoff[2], boff[2];
    #pragma unroll
    for (int mi = 0; mi < 2; ++mi)
        aoff[mi] = (wm + mi * 16 + (lane & 15)) * PASTR + (lane >> 4) * 16;
    int tile = lane >> 3;
    #pragma unroll
    for (int ni = 0; ni < 2; ++ni)
        boff[ni] = H64_A + ((tile & 1) * 8 + (lane & 7)) * PBSTR
                 + (wn + ni * 16 + (tile >> 1) * 8) * 2;

    float acc[2][4][4];
    #pragma unroll
    for (int mi = 0; mi < 2; ++mi)
        #pragma unroll
        for (int nj = 0; nj < 4; ++nj)
            #pragma unroll
            for (int r = 0; r < 4; ++r) acc[mi][nj][r] = 0.f;

    int niter = K / PBK;
    prefetch(0); prefetch(1);

    for (int it = 0; it < niter; ++it) {
        if (it + 1 < niter) asm volatile("cp.async.wait_group 1;");
        else                asm volatile("cp.async.wait_group 0;");
        __syncthreads();
        if (it + 2 < niter) prefetch(it + 2);

        uint32_t Sb = S0 + (it % 3) * H64_STG;
        #pragma unroll
        for (int kk = 0; kk < 2; ++kk) {
            uint32_t a[2][4];
            #pragma unroll
            for (int mi = 0; mi < 2; ++mi) {
                uint32_t addr = Sb + aoff[mi] + kk * 32;
                asm volatile("ldmatrix.sync.aligned.m8n8.x4.shared.b16 {%0,%1,%2,%3}, [%4];"
                    : "=r"(a[mi][0]), "=r"(a[mi][1]), "=r"(a[mi][2]), "=r"(a[mi][3]) : "r"(addr));
            }
            uint32_t bq[2][4];
            #pragma unroll
            for (int ni = 0; ni < 2; ++ni) {
                uint32_t addr = Sb + boff[ni] + kk * 16 * PBSTR;
                asm volatile("ldmatrix.sync.aligned.m8n8.x4.trans.shared.b16 {%0,%1,%2,%3}, [%4];"
                    : "=r"(bq[ni][0]), "=r"(bq[ni][1]), "=r"(bq[ni][2]), "=r"(bq[ni][3]) : "r"(addr));
            }
            #pragma unroll
            for (int mi = 0; mi < 2; ++mi)
                #pragma unroll
                for (int nj = 0; nj < 4; ++nj) {
                    uint32_t b0 = bq[nj >> 1][(nj & 1) * 2];
                    uint32_t b1 = bq[nj >> 1][(nj & 1) * 2 + 1];
                    asm volatile(
                        "mma.sync.aligned.m16n8k16.row.col.f32.bf16.bf16.f32 "
                        "{%0,%1,%2,%3}, {%4,%5,%6,%7}, {%8,%9}, {%0,%1,%2,%3};"
                        : "+f"(acc[mi][nj][0]), "+f"(acc[mi][nj][1]),
                          "+f"(acc[mi][nj][2]), "+f"(acc[mi][nj][3])
                        : "r"(a[mi][0]), "r"(a[mi][1]), "r"(a[mi][2]), "r"(a[mi][3]),
                          "r"(b0), "r"(b1));
                }
        }
    }

    int r_base = m0 + wm + (lane >> 2);
    int c_base = n0 + wn + (lane & 3) * 2;
    #pragma unroll
    for (int mi = 0; mi < 2; ++mi) {
        #pragma unroll
        for (int nj = 0; nj < 4; ++nj) {
            int r = r_base + mi * 16;
            int c = c_base + nj * 8;
            float bx2 = bias[c], by2 = bias[c + 1];
            float o00 = acc[mi][nj][0] + bx2;
            float o01 = acc[mi][nj][1] + by2;
            float o10 = acc[mi][nj][2] + bx2;
            float o11 = acc[mi][nj][3] + by2;
            if (EPI == 2) {
                const float* rp0 = resid + (size_t)r * N + c;
                const float* rp1 = resid + (size_t)(r + 8) * N + c;
                float* Cf = (float*)Cp;
                float2 v0 = {o00 + rp0[0], o01 + rp0[1]};
                float2 v1 = {o10 + rp1[0], o11 + rp1[1]};
                *(float2*)(Cf + (size_t)r * N + c) = v0;
                *(float2*)(Cf + (size_t)(r + 8) * N + c) = v1;
            } else {
                bf16* Cb = (bf16*)Cp;
                __nv_bfloat162 v0 = {__float2bfloat16(o00), __float2bfloat16(o01)};
                __nv_bfloat162 v1 = {__float2bfloat16(o10), __float2bfloat16(o11)};
                *(__nv_bfloat162*)(Cb + (size_t)r * N + c) = v0;
                *(__nv_bfloat162*)(Cb + (size_t)(r + 8) * N + c) = v1;
            }
        }
    }
}

// ========== K2: fused v-proj (bf16, 64x128) || off/attn (tf32, 64x128) =======
__global__ __launch_bounds__(256)
void fused_k2(const bf16* __restrict__ xnb, const bf16* __restrict__ wvb,
              const float* __restrict__ b_v, bf16* __restrict__ vb,
              const float* __restrict__ xn, const float* __restrict__ wcat,
              const float* __restrict__ bcat, float* __restrict__ offattn) {
    extern __shared__ char sm_[];
    if (blockIdx.z == 0)
        hgemm64_dev<0>(sm_, blockIdx.x, blockIdx.y, xnb, wvb, b_v, nullptr, vb, 256, 256);
    else
        tgemm64_dev(sm_, blockIdx.x, blockIdx.y, xn, wcat, bcat, offattn);
}

// ---------------- bf16 GEMM 128x128x32 (fc1, fc2), 3-stage -------------------
#define PBM 128
#define PBN 128
#define PA_ST (PBM * PASTR)
#define PB_ST (PBK * PBSTR)
#define PSTG  (PA_ST + PB_ST)
#define PSMEM (3 * PSTG)

template<int EPI>
__global__ __launch_bounds__(256)
void hgemm_kernel(const bf16* __restrict__ A, const bf16* __restrict__ B,
                  const float* __restrict__ bias, const float* __restrict__ resid,
                  void* __restrict__ Cp, int N, int K) {
    extern __shared__ char sm_[];
    uint32_t S0 = smem_u32(sm_);

    int t = threadIdx.x;
    int lane = t & 31, warp = t >> 5;
    int wm = (warp & 3) * 32;
    int wn = (warp >> 2) * 64;
    int m0 = blockIdx.y * PBM;
    int n0 = blockIdx.x * PBN;

    int a_row = t >> 1;
    int a_c16 = (t & 1) * 2;
    const bf16* Ag = A + (size_t)(m0 + a_row) * K + a_c16 * 8;
    uint32_t a_s = S0 + a_row * PASTR + a_c16 * 16;
    int b_row = t >> 3;
    int b_c16 = (t & 7) * 2;
    const bf16* Bg = B + (size_t)b_row * N + n0 + b_c16 * 8;
    uint32_t b_s = S0 + PA_ST + b_row * PBSTR + b_c16 * 16;

    auto prefetch = [&](int chunk) {
        int st = chunk % 3;
        const bf16* ag = Ag + chunk * PBK;
        const bf16* bg = Bg + (size_t)chunk * PBK * N;
        uint32_t sa = a_s + st * PSTG;
        uint32_t sb = b_s + st * PSTG;
        asm volatile("cp.async.cg.shared.global [%0], [%1], 16;" :: "r"(sa), "l"(ag));
        asm volatile("cp.async.cg.shared.global [%0], [%1], 16;" :: "r"(sa + 16), "l"(ag + 8));
        asm volatile("cp.async.cg.shared.global [%0], [%1], 16;" :: "r"(sb), "l"(bg));
        asm volatile("cp.async.cg.shared.global [%0], [%1], 16;" :: "r"(sb + 16), "l"(bg + 8));
        asm volatile("cp.async.commit_group;");
    };

    uint32_t aoff[2], boff[4];
    #pragma unroll
    for (int mi = 0; mi < 2; ++mi)
        aoff[mi] = (wm + mi * 16 + (lane & 15)) * PASTR + (lane >> 4) * 16;
    int tile = lane >> 3;
    #pragma unroll
    for (int ni = 0; ni < 4; ++ni)
        boff[ni] = PA_ST + ((tile & 1) * 8 + (lane & 7)) * PBSTR
                 + (wn + ni * 16 + (tile >> 1) * 8) * 2;

    float acc[2][8][4];
    #pragma unroll
    for (int mi = 0; mi < 2; ++mi)
        #pragma unroll
        for (int nj = 0; nj < 8; ++nj)
            #pragma unroll
            for (int r = 0; r < 4; ++r) acc[mi][nj][r] = 0.f;

    int niter = K / PBK;
    prefetch(0);
    prefetch(1);

    for (int it = 0; it < niter; ++it) {
        if (it + 1 < niter) asm volatile("cp.async.wait_group 1;");
        else                asm volatile("cp.async.wait_group 0;");
        __syncthreads();
        if (it + 2 < niter) prefetch(it + 2);

        uint32_t Sb = S0 + (it % 3) * PSTG;
        #pragma unroll
        for (int kk = 0; kk < 2; ++kk) {
            uint32_t a[2][4];
            #pragma unroll
            for (int mi = 0; mi < 2; ++mi) {
                uint32_t addr = Sb + aoff[mi] + kk * 32;
                asm volatile("ldmatrix.sync.aligned.m8n8.x4.shared.b16 {%0,%1,%2,%3}, [%4];"
                    : "=r"(a[mi][0]), "=r"(a[mi][1]), "=r"(a[mi][2]), "=r"(a[mi][3]) : "r"(addr));
            }
            uint32_t bq[4][4];
            #pragma unroll
            for (int ni = 0; ni < 4; ++ni) {
                uint32_t addr = Sb + boff[ni] + kk * 16 * PBSTR;
                asm volatile("ldmatrix.sync.aligned.m8n8.x4.trans.shared.b16 {%0,%1,%2,%3}, [%4];"
                    : "=r"(bq[ni][0]), "=r"(bq[ni][1]), "=r"(bq[ni][2]), "=r"(bq[ni][3]) : "r"(addr));
            }
            #pragma unroll
            for (int mi = 0; mi < 2; ++mi)
                #pragma unroll
                for (int nj = 0; nj < 8; ++nj) {
                    uint32_t b0 = bq[nj >> 1][(nj & 1) * 2];
                    uint32_t b1 = bq[nj >> 1][(nj & 1) * 2 + 1];
                    asm volatile(
                        "mma.sync.aligned.m16n8k16.row.col.f32.bf16.bf16.f32 "
                        "{%0,%1,%2,%3}, {%4,%5,%6,%7}, {%8,%9}, {%0,%1,%2,%3};"
                        : "+f"(acc[mi][nj][0]), "+f"(acc[mi][nj][1]),
                          "+f"(acc[mi][nj][2]), "+f"(acc[mi][nj][3])
                        : "r"(a[mi][0]), "r"(a[mi][1]), "r"(a[mi][2]), "r"(a[mi][3]),
                          "r"(b0), "r"(b1));
                }
        }
    }

    int r_base = m0 + wm + (lane >> 2);
    int c_base = n0 + wn + (lane & 3) * 2;
    #pragma unroll
    for (int mi = 0; mi < 2; ++mi) {
        #pragma unroll
        for (int nj = 0; nj < 8; ++nj) {
            int r = r_base + mi * 16;
            int c = c_base + nj * 8;
            float bx = bias[c], by = bias[c + 1];
            float o00 = acc[mi][nj][0] + bx;
            float o01 = acc[mi][nj][1] + by;
            float o10 = acc[mi][nj][2] + bx;
            float o11 = acc[mi][nj][3] + by;
            if (EPI == 1) {
                o00 = gelu_f(o00); o01 = gelu_f(o01);
                o10 = gelu_f(o10); o11 = gelu_f(o11);
            }
            if (EPI == 2) {
                const float* rp0 = resid + (size_t)r * N + c;
                const float* rp1 = resid + (size_t)(r + 8) * N + c;
                float* Cf = (float*)Cp;
                float2 v0 = {o00 + rp0[0], o01 + rp0[1]};
                float2 v1 = {o10 + rp1[0], o11 + rp1[1]};
                *(float2*)(Cf + (size_t)r * N + c) = v0;
                *(float2*)(Cf + (size_t)(r + 8) * N + c) = v1;
            } else {
                bf16* Cb = (bf16*)Cp;
                __nv_bfloat162 v0 = {__float2bfloat16(o00), __float2bfloat16(o01)};
                __nv_bfloat162 v1 = {__float2bfloat16(o10), __float2bfloat16(o11)};
                *(__nv_bfloat162*)(Cb + (size_t)r * N + c) = v0;
                *(__nv_bfloat162*)(Cb + (size_t)(r + 8) * N + c) = v1;
            }
        }
    }
}

// ======== fused wout GEMM + residual + LN2: register-resident LN epilogue ====
// __launch_bounds__(256, 2) caps regs at 128 -> 2 CTAs/SM (was 136 regs, 1 CTA).
#define QBM 64
#define QASTR 80
#define QBSTR 528
#define QA_SZ (QBM * QASTR)
#define QB_SZ (32 * QBSTR)
#define QSTG  (QA_SZ + QB_SZ)
#define QSMEM (3 * QSTG)

__global__ __launch_bounds__(256, 2)
void hgemm_wout_ln(const bf16* __restrict__ A, const bf16* __restrict__ B,
                   const float* __restrict__ bias, const float* __restrict__ resid,
                   float* __restrict__ xres, const float* __restrict__ g2,
                   const float* __restrict__ b2g, bf16* __restrict__ yb) {
    extern __shared__ char sm_[];
    uint32_t S0 = smem_u32(sm_);
    int t = threadIdx.x;
    int lane = t & 31, warp = t >> 5;
    int wm = (warp & 1) * 32;
    int wn = (warp >> 1) * 64;
    int wng = warp >> 1;
    int m0 = blockIdx.x * QBM;

    int a_row = t >> 2, a_c16 = t & 3;
    const bf16* Ag = A + (size_t)(m0 + a_row) * 256 + a_c16 * 8;
    uint32_t a_s = S0 + a_row * QASTR + a_c16 * 16;

    auto prefetch = [&](int ck) {
        int st = ck % 3;
        asm volatile("cp.async.cg.shared.global [%0], [%1], 16;"
                     :: "r"(a_s + st * QSTG), "l"(Ag + ck * 32));
        #pragma unroll
        for (int i = 0; i < 4; ++i) {
            int idx = t + i * 256;
            int row = idx >> 5, c16 = idx & 31;
            const bf16* bg = B + (size_t)(ck * 32 + row) * 256 + c16 * 8;
            uint32_t dst = S0 + st * QSTG + QA_SZ + row * QBSTR + c16 * 16;
            asm volatile("cp.async.cg.shared.global [%0], [%1], 16;" :: "r"(dst), "l"(bg));
        }
        asm volatile("cp.async.commit_group;");
    };

    uint32_t aoff[2], boff[4];
    #pragma unroll
    for (int mi = 0; mi < 2; ++mi)
        aoff[mi] = (wm + mi * 16 + (lane & 15)) * QASTR + (lane >> 4) * 16;
    int tile = lane >> 3;
    #pragma unroll
    for (int ni = 0; ni < 4; ++ni)
        boff[ni] = QA_SZ + ((tile & 1) * 8 + (lane & 7)) * QBSTR
                 + (wn + ni * 16 + (tile >> 1) * 8) * 2;

    float acc[2][8][4];
    #pragma unroll
    for (int mi = 0; mi < 2; ++mi)
        #pragma unroll
        for (int nj = 0; nj < 8; ++nj)
            #pragma unroll
            for (int r = 0; r < 4; ++r) acc[mi][nj][r] = 0.f;

    const int niter = 8;
    prefetch(0); prefetch(1);

    for (int it = 0; it < niter; ++it) {
        if (it + 1 < niter) asm volatile("cp.async.wait_group 1;");
        else                asm volatile("cp.async.wait_group 0;");
        __syncthreads();
        if (it + 2 < niter) prefetch(it + 2);

        uint32_t Sb = S0 + (it % 3) * QSTG;
        #pragma unroll
        for (int kk = 0; kk < 2; ++kk) {
            uint32_t a[2][4];
            #pragma unroll
            for (int mi = 0; mi < 2; ++mi) {
                uint32_t addr = Sb + aoff[mi] + kk * 32;
                asm volatile("ldmatrix.sync.aligned.m8n8.x4.shared.b16 {%0,%1,%2,%3}, [%4];"
                    : "=r"(a[mi][0]), "=r"(a[mi][1]), "=r"(a[mi][2]), "=r"(a[mi][3]) : "r"(addr));
            }
            uint32_t bq[4][4];
            #pragma unroll
            for (int ni = 0; ni < 4; ++ni) {
                uint32_t addr = Sb + boff[ni] + kk * 16 * QBSTR;
                asm volatile("ldmatrix.sync.aligned.m8n8.x4.trans.shared.b16 {%0,%1,%2,%3}, [%4];"
                    : "=r"(bq[ni][0]), "=r"(bq[ni][1]), "=r"(bq[ni][2]), "=r"(bq[ni][3]) : "r"(addr));
            }
            #pragma unroll
            for (int mi = 0; mi < 2; ++mi)
                #pragma unroll
                for (int nj = 0; nj < 8; ++nj) {
                    uint32_t b0 = bq[nj >> 1][(nj & 1) * 2];
                    uint32_t b1 = bq[nj >> 1][(nj & 1) * 2 + 1];
                    asm volatile(
                        "mma.sync.aligned.m16n8k16.row.col.f32.bf16.bf16.f32 "
                        "{%0,%1,%2,%3}, {%4,%5,%6,%7}, {%8,%9}, {%0,%1,%2,%3};"
                        : "+f"(acc[mi][nj][0]), "+f"(acc[mi][nj][1]),
                          "+f"(acc[mi][nj][2]), "+f"(acc[mi][nj][3])
                        : "r"(a[mi][0]), "r"(a[mi][1]), "r"(a[mi][2]), "r"(a[mi][3]),
                          "r"(b0), "r"(b1));
                }
        }
    }

    // ---- fold bias + residual into acc; write xres ----
    int lr0 = wm + (lane >> 2);
    int cb = wn + (lane & 3) * 2;
    #pragma unroll
    for (int mi = 0; mi < 2; ++mi) {
        #pragma unroll
        for (int nj = 0; nj < 8; ++nj) {
            int rl = lr0 + mi * 16;
            int c = cb + nj * 8;
            float bx = bias[c], by = bias[c + 1];
            const float* rp0 = resid + (size_t)(m0 + rl) * 256 + c;
            const float* rp1 = resid + (size_t)(m0 + rl + 8) * 256 + c;
            acc[mi][nj][0] += bx + rp0[0];
            acc[mi][nj][1] += by + rp0[1];
            acc[mi][nj][2] += bx + rp1[0];
            acc[mi][nj][3] += by + rp1[1];
            float2 v0 = {acc[mi][nj][0], acc[mi][nj][1]};
            float2 v1 = {acc[mi][nj][2], acc[mi][nj][3]};
            *(float2*)(xres + (size_t)(m0 + rl) * 256 + c) = v0;
            *(float2*)(xres + (size_t)(m0 + rl + 8) * 256 + c) = v1;
        }
    }

    // ---- per-thread partial sums for its 4 rows ----
    float ls[4], lq[4];
    #pragma unroll
    for (int i = 0; i < 4; ++i) { ls[i] = 0.f; lq[i] = 0.f; }
    #pragma unroll
    for (int mi = 0; mi < 2; ++mi) {
        #pragma unroll
        for (int nj = 0; nj < 8; ++nj) {
            float a0 = acc[mi][nj][0], a1 = acc[mi][nj][1];
            float a2 = acc[mi][nj][2], a3 = acc[mi][nj][3];
            ls[mi * 2]     += a0 + a1;  lq[mi * 2]     += a0 * a0 + a1 * a1;
            ls[mi * 2 + 1] += a2 + a3;  lq[mi * 2 + 1] += a2 * a2 + a3 * a3;
        }
    }
    #pragma unroll
    for (int o = 1; o <= 2; o <<= 1) {
        #pragma unroll
        for (int i = 0; i < 4; ++i) {
            ls[i] += __shfl_xor_sync(0xffffffffu, ls[i], o);
            lq[i] += __shfl_xor_sync(0xffffffffu, lq[i], o);
        }
    }
    __syncthreads();
    float* part = (float*)sm_;   // [64][4][2] = 2048 B
    if ((lane & 3) == 0) {
        int rbase = wm + (lane >> 2);
        #pragma unroll
        for (int i = 0; i < 4; ++i) {
            int rl = rbase + (i >> 1) * 16 + (i & 1) * 8;
            part[(rl * 4 + wng) * 2 + 0] = ls[i];
            part[(rl * 4 + wng) * 2 + 1] = lq[i];
        }
    }
    __syncthreads();

    float mean[4], inv[4];
    #pragma unroll
    for (int i = 0; i < 4; ++i) {
        int rl = lr0 + (i >> 1) * 16 + (i & 1) * 8;
        float s = 0.f, q = 0.f;
        #pragma unroll
        for (int gIdx = 0; gIdx < 4; ++gIdx) {
            s += part[(rl * 4 + gIdx) * 2 + 0];
            q += part[(rl * 4 + gIdx) * 2 + 1];
        }
        float m = s * (1.0f / 256.0f);
        float var = q * (1.0f / 256.0f) - m * m;
        mean[i] = m;
        inv[i] = rsqrtf(var + 1e-5f);
    }

    #pragma unroll
    for (int mi = 0; mi < 2; ++mi) {
        #pragma unroll
        for (int nj = 0; nj < 8; ++nj) {
            int rl = lr0 + mi * 16;
            int c = cb + nj * 8;
            float gx = g2[c], gy = g2[c + 1];
            float bbx = b2g[c], bby = b2g[c + 1];
            int i0 = mi * 2, i1 = mi * 2 + 1;
            float o00 = (acc[mi][nj][0] - mean[i0]) * inv[i0] * gx + bbx;
            float o01 = (acc[mi][nj][1] - mean[i0]) * inv[i0] * gy + bby;
            float o10 = (acc[mi][nj][2] - mean[i1]) * inv[i1] * gx + bbx;
            float o11 = (acc[mi][nj][3] - mean[i1]) * inv[i1] * gy + bby;
            __nv_bfloat162 y0 = {__float2bfloat16(o00), __float2bfloat16(o01)};
            __nv_bfloat162 y1 = {__float2bfloat16(o10), __float2bfloat16(o11)};
            *(__nv_bfloat162*)(yb + (size_t)(m0 + rl) * 256 + c) = y0;
            *(__nv_bfloat162*)(yb + (size_t)(m0 + rl + 8) * 256 + c) = y1;
        }
    }
}

// ---------------- Deformable sampling: one warp = (token, head-pair) ---------
__global__ void sample_kernel(const bf16* __restrict__ v, const float* __restrict__ offattn,
                              const float* __restrict__ rp, bf16* __restrict__ agg) {
    int gw = blockIdx.x * 8 + (threadIdx.x >> 5);
    int lane = threadIdx.x & 31;
    int tg = gw >> 2;
    int head = ((gw & 3) << 1) + (lane >> 4);
    int l16 = lane & 15;
    int bb = tg >> 13;
    int pos = tg & 8191;

    const float* lg = offattn + (size_t)tg * 256 + 144 + head * 9;
    float w[9];
    float mx = -1e30f;
    #pragma unroll
    for (int k = 0; k < 9; ++k) { w[k] = lg[k]; mx = fmaxf(mx, w[k]); }
    float sum = 0.f;
    #pragma unroll
    for (int k = 0; k < 9; ++k) { w[k] = expf(w[k] - mx); sum += w[k]; }
    float inv = 1.0f / sum;

    const float* rpp  = rp + (size_t)pos * 18;
    const float* offp = offattn + (size_t)tg * 256 + head * 18;
    const __nv_bfloat162* vc = (const __nv_bfloat162*)v + head * 16 + l16;
    int base = bb << 13;
    float a0 = 0.f, a1 = 0.f;
    #pragma unroll
    for (int k = 0; k < 9; ++k) {
        float cx = (rpp[k * 2 + 0] + offp[k * 2 + 0] + 1.0f) * 0.5f * 127.0f;
        float cy = (rpp[k * 2 + 1] + offp[k * 2 + 1] + 1.0f) * 0.5f * 63.0f;
        float fx = floorf(cx), fy = floorf(cy);
        float wx = cx - fx, wy = cy - fy;
        int x0 = min(max((int)fx, 0), 127);
        int x1 = min(max((int)fx + 1, 0), 127);
        int y0 = min(max((int)fy, 0), 63);
        int y1 = min(max((int)fy + 1, 0), 63);
        float2 v00 = __bfloat1622float2(vc[(size_t)(base + y0 * 128 + x0) * 128]);
        float2 v01 = __bfloat1622float2(vc[(size_t)(base + y0 * 128 + x1) * 128]);
        float2 v10 = __bfloat1622float2(vc[(size_t)(base + y1 * 128 + x0) * 128]);
        float2 v11 = __bfloat1622float2(vc[(size_t)(base + y1 * 128 + x1) * 128]);
        float w00 = (1.f - wy) * (1.f - wx), w01 = (1.f - wy) * wx;
        float w10 = wy * (1.f - wx),         w11 = wy * wx;
        float wk = w[k] * inv;
        a0 += (v00.x * w00 + v01.x * w01 + v10.x * w10 + v11.x * w11) * wk;
        a1 += (v00.y * w00 + v01.y * w01 + v10.y * w10 + v11.y * w11) * wk;
    }
    __nv_bfloat162 ov = {__float2bfloat16(a0), __float2bfloat16(a1)};
    *(__nv_bfloat162*)(agg + (size_t)tg * 256 + head * 32 + l16 * 2) = ov;
}

// ---------------- Depthwise 3x3 conv: sliding window, 4-way x-split ----------
__global__ void dwconv_kernel(const bf16* __restrict__ h, const float* __restrict__ wdw,
                              const float* __restrict__ bdw, bf16* __restrict__ o) {
    int c2 = blockIdx.x * 256 + threadIdx.x;
    int y = blockIdx.y & 63;
    int seg = blockIdx.y >> 6;
    int bb = blockIdx.z;
    int c = c2 * 2;
    int x0 = seg * 32;

    float w0[9], w1[9];
    #pragma unroll
    for (int i = 0; i < 9; ++i) { w0[i] = wdw[c * 9 + i]; w1[i] = wdw[(c + 1) * 9 + i]; }
    float bb0 = bdw[c], bb1 = bdw[c + 1];

    const __nv_bfloat162* hp = (const __nv_bfloat162*)h;
    size_t base = ((size_t)(bb << 13) + y * 128) * 512 + c2;
    bool hu = (y > 0), hd = (y < 63);
    __nv_bfloat162 zero = __float2bfloat162_rn(0.f);

    __nv_bfloat162 cm[3], cc[3], cn[3];
    {
        size_t p = base + ((x0 + 127) & 127) * 512;
        cm[0] = hu ? hp[p - 65536] : zero; cm[1] = hp[p]; cm[2] = hd ? hp[p + 65536] : zero;
        p = base + x0 * 512;
        cc[0] = hu ? hp[p - 65536] : zero; cc[1] = hp[p]; cc[2] = hd ? hp[p + 65536] : zero;
    }
    bf16* op = o + ((size_t)(bb << 13) + y * 128) * 1024 + c;

    for (int x = x0; x < x0 + 32; ++x) {
        size_t p = base + ((x + 1) & 127) * 512;
        cn[0] = hu ? hp[p - 65536] : zero; cn[1] = hp[p]; cn[2] = hd ? hp[p + 65536] : zero;

        float a0 = bb0, a1 = bb1;
        #pragma unroll
        for (int dy = 0; dy < 3; ++dy) {
            float2 vm = __bfloat1622float2(cm[dy]);
            float2 vc = __bfloat1622float2(cc[dy]);
            float2 vp = __bfloat1622float2(cn[dy]);
            a0 += vm.x * w0[dy * 3 + 0] + vc.x * w0[dy * 3 + 1] + vp.x * w0[dy * 3 + 2];
            a1 += vm.y * w1[dy * 3 + 0] + vc.y * w1[dy * 3 + 1] + vp.y * w1[dy * 3 + 2];
        }
        __nv_bfloat162 ov = {__float2bfloat16(gelu_f(a0)), __float2bfloat16(gelu_f(a1))};
        *(__nv_bfloat162*)(op + (size_t)x * 1024) = ov;

        #pragma unroll
        for (int i = 0; i < 3; ++i) { cm[i] = cc[i]; cc[i] = cn[i]; }
    }
}

// ---------------- launch ----------------
extern "C" void kernel_launch(void* const* d_in, const int* in_sizes, int n_in,
                              void* d_out, int out_size) {
    const float* x      = (const float*)d_in[0];
    const float* rp     = (const float*)d_in[1];
    const float* ln1_g  = (const float*)d_in[2];
    const float* ln1_b  = (const float*)d_in[3];
    const float* w_v    = (const float*)d_in[4];
    const float* b_v    = (const float*)d_in[5];
    const float* w_off  = (const float*)d_in[6];
    const float* b_off  = (const float*)d_in[7];
    const float* w_attn = (const float*)d_in[8];
    const float* b_attn = (const float*)d_in[9];
    const float* w_out  = (const float*)d_in[10];
    const float* b_out  = (const float*)d_in[11];
    const float* ln2_g  = (const float*)d_in[12];
    const float* ln2_b  = (const float*)d_in[13];
    const float* w1     = (const float*)d_in[14];
    const float* b1     = (const float*)d_in[15];
    const float* w_dw   = (const float*)d_in[16];
    const float* b_dw   = (const float*)d_in[17];
    const float* w2     = (const float*)d_in[18];
    const float* b2     = (const float*)d_in[19];
    float* out = (float*)d_out;

    float *xn, *offattn, *xres, *wcat, *bcat;
    bf16 *xnb, *vb, *aggb, *yb, *hb, *h2b, *wvb, *woutb, *w1b, *w2b;
    cudaGetSymbolAddress((void**)&xn,      g_xn);
    cudaGetSymbolAddress((void**)&offattn, g_offattn);
    cudaGetSymbolAddress((void**)&xres,    g_xres);
    cudaGetSymbolAddress((void**)&wcat,    g_wcat);
    cudaGetSymbolAddress((void**)&bcat,    g_bcat);
    cudaGetSymbolAddress((void**)&xnb,     g_xnb);
    cudaGetSymbolAddress((void**)&vb,      g_vb);
    cudaGetSymbolAddress((void**)&aggb,    g_aggb);
    cudaGetSymbolAddress((void**)&yb,      g_yb);
    cudaGetSymbolAddress((void**)&hb,      g_hb);
    cudaGetSymbolAddress((void**)&h2b,     g_h2b);
    cudaGetSymbolAddress((void**)&wvb,     g_wvb);
    cudaGetSymbolAddress((void**)&woutb,   g_woutb);
    cudaGetSymbolAddress((void**)&w1b,     g_w1b);
    cudaGetSymbolAddress((void**)&w2b,     g_w2b);

    cudaFuncSetAttribute(hgemm_kernel<1>, cudaFuncAttributeMaxDynamicSharedMemorySize, PSMEM);
    cudaFuncSetAttribute(hgemm_kernel<2>, cudaFuncAttributeMaxDynamicSharedMemorySize, PSMEM);
    cudaFuncSetAttribute(fused_k2,        cudaFuncAttributeMaxDynamicSharedMemorySize, H64_SMEM);
    cudaFuncSetAttribute(hgemm_wout_ln,   cudaFuncAttributeMaxDynamicSharedMemorySize, QSMEM);

    // K1: LN1 || weight prep
    prep_ln_kernel<<<NTOK + 2816, 256>>>(
        x, ln1_g, ln1_b, xn, xnb,
        w_v, w_out, w1, w2, w_off, w_attn, b_off, b_attn,
        wvb, woutb, w1b, w2b, wcat, bcat);
    // K2: v projection || offsets+attn (resource-matched 64x128 bodies)
    fused_k2<<<dim3(2, NTOK / 64, 2), 256, H64_SMEM>>>(
        xnb, wvb, b_v, vb, xn, wcat, bcat, offattn);
    // K3: softmax + bilinear sampling + aggregation
    sample_kernel<<<NTOK / 2, 256>>>(vb, offattn, rp, aggb);
    // K4: output proj + residual + LN2 fused (register-resident LN, 2 CTA/SM)
    hgemm_wout_ln<<<NTOK / QBM, 256, QSMEM>>>(aggb, woutb, b_out, x, xres, ln2_g, ln2_b, yb);
    // K5: fc1 + GELU (bf16 TC, 128x128)
    hgemm_kernel<1><<<dim3(HID / PBN, NTOK / PBM), 256, PSMEM>>>(yb, w1b, b1, nullptr, hb, HID, 256);
    // K6: depthwise conv + GELU
    dwconv_kernel<<<dim3(2, 256, 2), 256>>>(hb, w_dw, b_dw, h2b);
    // K7: fc2 + residual -> out (f32, 128x128)
    hgemm_kernel<2><<<dim3(256 / PBN, NTOK / PBM), 256, PSMEM>>>(h2b, w2b, b2, xres, out, 256, 1024);
}

// round 15
// speedup vs baseline: 1.0962x; 1.0607x over previous
#include <cuda_runtime.h>
#include <cuda_bf16.h>
#include <math.h>
#include <stdint.h>

typedef __nv_bfloat16 bf16;

#define NTOK 16384
#define CDIM 256
#define HID  1024

// -------- scratch (__device__ globals; no allocations allowed) --------
__device__ float g_xn     [NTOK * CDIM];
__device__ float g_offattn[NTOK * 256];
__device__ float g_xres   [NTOK * CDIM];
__device__ bf16  g_xnb    [NTOK * CDIM];
__device__ bf16  g_vb     [NTOK * CDIM];
__device__ bf16  g_aggb   [NTOK * CDIM];
__device__ bf16  g_yb     [NTOK * CDIM];
__device__ bf16  g_hb     [NTOK * HID];
__device__ bf16  g_h2b    [NTOK * HID];
__device__ bf16  g_wvb    [256 * 256];
__device__ bf16  g_woutb  [256 * 256];
__device__ bf16  g_w1b    [256 * 1024];
__device__ bf16  g_w2b    [1024 * 256];
__device__ float g_wcat   [256 * 256];
__device__ float g_bcat   [256];

__device__ __forceinline__ float gelu_f(float v) {
    return 0.5f * v * (1.0f + erff(v * 0.7071067811865476f));
}

__device__ __forceinline__ uint32_t smem_u32(const void* p) {
    uint32_t a;
    asm("{ .reg .u64 t; cvta.to.shared.u64 t, %1; cvt.u32.u64 %0, t; }" : "=r"(a) : "l"(p));
    return a;
}

__device__ __forceinline__ uint32_t f2tf32(float f) {
    uint32_t r;
    asm("cvt.rna.tf32.f32 %0, %1;" : "=r"(r) : "f"(f));
    return r;
}

// ================= K1: fused prep + LN1 (block-range dispatch) =================
__global__ void prep_ln_kernel(
    const float* __restrict__ x, const float* __restrict__ g, const float* __restrict__ b,
    float* __restrict__ xn, bf16* __restrict__ xnb,
    const float* wv, const float* wout, const float* w1, const float* w2,
    const float* w_off, const float* w_attn, const float* b_off, const float* b_attn,
    bf16* wvb, bf16* woutb, bf16* w1b, bf16* w2b, float* wcat, float* bcat) {
    if (blockIdx.x < NTOK) {
        int tok = blockIdx.x;
        int c = threadIdx.x;
        float v = x[(size_t)tok * CDIM + c];
        __shared__ float sh[8];
        float s = v;
        #pragma unroll
        for (int o = 16; o; o >>= 1) s += __shfl_xor_sync(0xffffffffu, s, o);
        if ((c & 31) == 0) sh[c >> 5] = s;
        __syncthreads();
        float tot = 0.f;
        #pragma unroll
        for (int i = 0; i < 8; ++i) tot += sh[i];
        float mean = tot * (1.0f / CDIM);
        __syncthreads();
        float d = v - mean;
        float s2 = d * d;
        #pragma unroll
        for (int o = 16; o; o >>= 1) s2 += __shfl_xor_sync(0xffffffffu, s2, o);
        if ((c & 31) == 0) sh[c >> 5] = s2;
        __syncthreads();
        float v2 = 0.f;
        #pragma unroll
        for (int i = 0; i < 8; ++i) v2 += sh[i];
        float var = v2 * (1.0f / CDIM);
        float out = d * rsqrtf(var + 1e-5f) * g[c] + b[c];
        xn[(size_t)tok * CDIM + c]  = __uint_as_float(f2tf32(out));
        xnb[(size_t)tok * CDIM + c] = __float2bfloat16(out);
        return;
    }
    int i = (blockIdx.x - NTOK) * 256 + threadIdx.x;
    if (i < 65536) { wvb[i] = __float2bfloat16(wv[i]); return; }
    i -= 65536;
    if (i < 65536) { woutb[i] = __float2bfloat16(wout[i]); return; }
    i -= 65536;
    if (i < 262144) { w1b[i] = __float2bfloat16(w1[i]); return; }
    i -= 262144;
    if (i < 262144) { w2b[i] = __float2bfloat16(w2[i]); return; }
    i -= 262144;
    if (i < 65536) {
        int k = i >> 8, col = i & 255;
        float v = (col < 144) ? w_off[k * 144 + col]
                : (col < 216) ? w_attn[k * 72 + (col - 144)] : 0.f;
        wcat[i] = __uint_as_float(f2tf32(v));
        if (k == 0)
            bcat[col] = (col < 144) ? b_off[col]
                      : (col < 216) ? b_attn[col - 144] : 0.f;
    }
}

// ---------------- shared GEMM geometry constants ----------------
#define PBK 32
#define PASTR 80
#define PBSTR 272
#define H64_A  (64 * PASTR)
#define H64_B  (PBK * PBSTR)
#define H64_STG (H64_A + H64_B)
#define H64_SMEM (3 * H64_STG)
#define TFA_STR 20
#define TFB_STR 136
#define TFA_SZ  (64 * TFA_STR * 4)
#define TFB_SZ  (16 * TFB_STR * 4)
#define TF_STG  (TFA_SZ + TFB_SZ)

// ---------------- tf32 GEMM device body: 64x128x16, 3-stage ------------------
__device__ void tgemm64_dev(char* sm_, int bx, int by,
                            const float* __restrict__ A, const float* __restrict__ Bw,
                            const float* __restrict__ bias, float* __restrict__ C) {
    uint32_t S0 = smem_u32(sm_);
    int t = threadIdx.x;
    int lane = t & 31, warp = t >> 5;
    int wm = (warp & 1) * 32;
    int wn = (warp >> 1) * 32;
    int m0 = by * 64;
    int n0 = bx * 128;

    int a_row = t >> 2, a_c4 = (t & 3) * 4;
    const float* Ag = A + (size_t)(m0 + a_row) * 256 + a_c4;
    uint32_t a_s = S0 + (a_row * TFA_STR + a_c4) * 4;

    auto prefetch = [&](int it) {
        int st = it % 3;
        asm volatile("cp.async.cg.shared.global [%0], [%1], 16;"
                     :: "r"(a_s + st * TF_STG), "l"(Ag + it * 16));
        #pragma unroll
        for (int i = 0; i < 2; ++i) {
            int idx = t + i * 256;
            int row = idx >> 5, c4 = (idx & 31) * 4;
            const float* bg = Bw + (size_t)(it * 16 + row) * 256 + n0 + c4;
            uint32_t dst = S0 + TFA_SZ + (row * TFB_STR + c4) * 4 + st * TF_STG;
            asm volatile("cp.async.cg.shared.global [%0], [%1], 16;" :: "r"(dst), "l"(bg));
        }
        asm volatile("cp.async.commit_group;");
    };

    float acc[2][4][4];
    #pragma unroll
    for (int mi = 0; mi < 2; ++mi)
        #pragma unroll
        for (int nj = 0; nj < 4; ++nj)
            #pragma unroll
            for (int r = 0; r < 4; ++r) acc[mi][nj][r] = 0.f;

    const int niter = 16;
    prefetch(0); prefetch(1);

    int lr = lane >> 2, lc = lane & 3;
    for (int it = 0; it < niter; ++it) {
        if (it + 1 < niter) asm volatile("cp.async.wait_group 1;");
        else                asm volatile("cp.async.wait_group 0;");
        __syncthreads();
        if (it + 2 < niter) prefetch(it + 2);

        const uint32_t* As = (const uint32_t*)(sm_ + (it % 3) * TF_STG);
        const uint32_t* Bs = (const uint32_t*)(sm_ + (it % 3) * TF_STG + TFA_SZ);

        #pragma unroll
        for (int kk = 0; kk < 2; ++kk) {
            uint32_t af[2][4];
            #pragma unroll
            for (int mi = 0; mi < 2; ++mi) {
                int rb = wm + mi * 16 + lr;
                af[mi][0] = As[rb * TFA_STR + kk * 8 + lc];
                af[mi][1] = As[(rb + 8) * TFA_STR + kk * 8 + lc];
                af[mi][2] = As[rb * TFA_STR + kk * 8 + lc + 4];
                af[mi][3] = As[(rb + 8) * TFA_STR + kk * 8 + lc + 4];
            }
            #pragma unroll
            for (int nj = 0; nj < 4; ++nj) {
                uint32_t b0 = Bs[(kk * 8 + lc) * TFB_STR + wn + nj * 8 + lr];
                uint32_t b1 = Bs[(kk * 8 + lc + 4) * TFB_STR + wn + nj * 8 + lr];
                #pragma unroll
                for (int mi = 0; mi < 2; ++mi)
                    asm volatile(
                        "mma.sync.aligned.m16n8k8.row.col.f32.tf32.tf32.f32 "
                        "{%0,%1,%2,%3}, {%4,%5,%6,%7}, {%8,%9}, {%0,%1,%2,%3};"
                        : "+f"(acc[mi][nj][0]), "+f"(acc[mi][nj][1]),
                          "+f"(acc[mi][nj][2]), "+f"(acc[mi][nj][3])
                        : "r"(af[mi][0]), "r"(af[mi][1]), "r"(af[mi][2]), "r"(af[mi][3]),
                          "r"(b0), "r"(b1));
            }
        }
    }

    #pragma unroll
    for (int mi = 0; mi < 2; ++mi) {
        #pragma unroll
        for (int nj = 0; nj < 4; ++nj) {
            int r = m0 + wm + mi * 16 + lr;
            int c = n0 + wn + nj * 8 + lc * 2;
            float bx2 = bias[c], by2 = bias[c + 1];
            float2 v0 = {acc[mi][nj][0] + bx2, acc[mi][nj][1] + by2};
            float2 v1 = {acc[mi][nj][2] + bx2, acc[mi][nj][3] + by2};
            *(float2*)(C + (size_t)r * 256 + c) = v0;
            *(float2*)(C + (size_t)(r + 8) * 256 + c) = v1;
        }
    }
}

// ---------------- bf16 GEMM device body: 64x128x32, 3-stage ------------------
template<int EPI>
__device__ void hgemm64_dev(char* sm_, int bx, int by,
                            const bf16* __restrict__ A, const bf16* __restrict__ B,
                            const float* __restrict__ bias, const float* __restrict__ resid,
                            void* __restrict__ Cp, int N, int K) {
    uint32_t S0 = smem_u32(sm_);
    int t = threadIdx.x;
    int lane = t & 31, warp = t >> 5;
    int wm = (warp & 1) * 32;
    int wn = (warp >> 1) * 32;
    int m0 = by * 64;
    int n0 = bx * 128;

    int a_row = t >> 2, a_c16 = t & 3;
    const bf16* Ag = A + (size_t)(m0 + a_row) * K + a_c16 * 8;
    uint32_t a_s = S0 + a_row * PASTR + a_c16 * 16;
    int b_row = t >> 3;
    int b_c16 = (t & 7) * 2;
    const bf16* Bg = B + (size_t)b_row * N + n0 + b_c16 * 8;
    uint32_t b_s = S0 + H64_A + b_row * PBSTR + b_c16 * 16;

    auto prefetch = [&](int chunk) {
        int st = chunk % 3;
        const bf16* bg = Bg + (size_t)chunk * PBK * N;
        asm volatile("cp.async.cg.shared.global [%0], [%1], 16;"
                     :: "r"(a_s + st * H64_STG), "l"(Ag + chunk * PBK));
        asm volatile("cp.async.cg.shared.global [%0], [%1], 16;" :: "r"(b_s + st * H64_STG), "l"(bg));
        asm volatile("cp.async.cg.shared.global [%0], [%1], 16;" :: "r"(b_s + st * H64_STG + 16), "l"(bg + 8));
        asm volatile("cp.async.commit_group;");
    };

    uint32_t aoff[2], boff[2];
    #pragma unroll
    for (int mi = 0; mi < 2; ++mi)
        aoff[mi] = (wm + mi * 16 + (lane & 15)) * PASTR + (lane >> 4) * 16;
    int tile = lane >> 3;
    #pragma unroll
    for (int ni = 0; ni < 2; ++ni)
        boff[ni] = H64_A + ((tile & 1) * 8 + (lane & 7)) * PBSTR
                 + (wn + ni * 16 + (tile >> 1) * 8) * 2;

    float acc[2][4][4];
    #pragma unroll
    for (int mi = 0; mi < 2; ++mi)
        #pragma unroll
        for (int nj = 0; nj < 4; ++nj)
            #pragma unroll
            for (int r = 0; r < 4; ++r) acc[mi][nj][r] = 0.f;

    int niter = K / PBK;
    prefetch(0); prefetch(1);

    for (int it = 0; it < niter; ++it) {
        if (it + 1 < niter) asm volatile("cp.async.wait_group 1;");
        else                asm volatile("cp.async.wait_group 0;");
        __syncthreads();
        if (it + 2 < niter) prefetch(it + 2);

        uint32_t Sb = S0 + (it % 3) * H64_STG;
        #pragma unroll
        for (int kk = 0; kk < 2; ++kk) {
            uint32_t a[2][4];
            #pragma unroll
            for (int mi = 0; mi < 2; ++mi) {
                uint32_t addr = Sb + aoff[mi] + kk * 32;
                asm volatile("ldmatrix.sync.aligned.m8n8.x4.shared.b16 {%0,%1,%2,%3}, [%4];"
                    : "=r"(a[mi][0]), "=r"(a[mi][1]), "=r"(a[mi][2]), "=r"(a[mi][3]) : "r"(addr));
            }
            uint32_t bq[2][4];
            #pragma unroll
            for (int ni = 0; ni < 2; ++ni) {
                uint32_t addr = Sb + boff[ni] + kk * 16 * PBSTR;
                asm volatile("ldmatrix.sync.aligned.m8n8.x4.trans.shared.b16 {%0,%1,%2,%3}, [%4];"
                    : "=r"(bq[ni][0]), "=r"(bq[ni][1]), "=r"(bq[ni][2]), "=r"(bq[ni][3]) : "r"(addr));
            }
            #pragma unroll
            for (int mi = 0; mi < 2; ++mi)
                #pragma unroll
                for (int nj = 0; nj < 4; ++nj) {
                    uint32_t b0 = bq[nj >> 1][(nj & 1) * 2];
                    uint32_t b1 = bq[nj >> 1][(nj & 1) * 2 + 1];
                    asm volatile(
                        "mma.sync.aligned.m16n8k16.row.col.f32.bf16.bf16.f32 "
                        "{%0,%1,%2,%3}, {%4,%5,%6,%7}, {%8,%9}, {%0,%1,%2,%3};"
                        : "+f"(acc[mi][nj][0]), "+f"(acc[mi][nj][1]),
                          "+f"(acc[mi][nj][2]), "+f"(acc[mi][nj][3])
                        : "r"(a[mi][0]), "r"(a[mi][1]), "r"(a[mi][2]), "r"(a[mi][3]),
                          "r"(b0), "r"(b1));
                }
        }
    }

    int r_base = m0 + wm + (lane >> 2);
    int c_base = n0 + wn + (lane & 3) * 2;
    #pragma unroll
    for (int mi = 0; mi < 2; ++mi) {
        #pragma unroll
        for (int nj = 0; nj < 4; ++nj) {
            int r = r_base + mi * 16;
            int c = c_base + nj * 8;
            float bx2 = bias[c], by2 = bias[c + 1];
            float o00 = acc[mi][nj][0] + bx2;
            float o01 = acc[mi][nj][1] + by2;
            float o10 = acc[mi][nj][2] + bx2;
            float o11 = acc[mi][nj][3] + by2;
            if (EPI == 2) {
                const float* rp0 = resid + (size_t)r * N + c;
                const float* rp1 = resid + (size_t)(r + 8) * N + c;
                float* Cf = (float*)Cp;
                float2 v0 = {o00 + rp0[0], o01 + rp0[1]};
                float2 v1 = {o10 + rp1[0], o11 + rp1[1]};
                *(float2*)(Cf + (size_t)r * N + c) = v0;
                *(float2*)(Cf + (size_t)(r + 8) * N + c) = v1;
            } else {
                bf16* Cb = (bf16*)Cp;
                __nv_bfloat162 v0 = {__float2bfloat16(o00), __float2bfloat16(o01)};
                __nv_bfloat162 v1 = {__float2bfloat16(o10), __float2bfloat16(o11)};
                *(__nv_bfloat162*)(Cb + (size_t)r * N + c) = v0;
                *(__nv_bfloat162*)(Cb + (size_t)(r + 8) * N + c) = v1;
            }
        }
    }
}

// ========== K2: fused v-proj (bf16, 64x128) || off/attn (tf32, 64x128) =======
__global__ __launch_bounds__(256)
void fused_k2(const bf16* __restrict__ xnb, const bf16* __restrict__ wvb,
              const float* __restrict__ b_v, bf16* __restrict__ vb,
              const float* __restrict__ xn, const float* __restrict__ wcat,
              const float* __restrict__ bcat, float* __restrict__ offattn) {
    extern __shared__ char sm_[];
    if (blockIdx.z == 0)
        hgemm64_dev<0>(sm_, blockIdx.x, blockIdx.y, xnb, wvb, b_v, nullptr, vb, 256, 256);
    else
        tgemm64_dev(sm_, blockIdx.x, blockIdx.y, xn, wcat, bcat, offattn);
}

// ---------------- bf16 GEMM 128x128x32 (fc1, fc2), 3-stage -------------------
#define PBM 128
#define PBN 128
#define PA_ST (PBM * PASTR)
#define PB_ST (PBK * PBSTR)
#define PSTG  (PA_ST + PB_ST)
#define PSMEM (3 * PSTG)

template<int EPI>
__global__ __launch_bounds__(256)
void hgemm_kernel(const bf16* __restrict__ A, const bf16* __restrict__ B,
                  const float* __restrict__ bias, const float* __restrict__ resid,
                  void* __restrict__ Cp, int N, int K) {
    extern __shared__ char sm_[];
    uint32_t S0 = smem_u32(sm_);

    int t = threadIdx.x;
    int lane = t & 31, warp = t >> 5;
    int wm = (warp & 3) * 32;
    int wn = (warp >> 2) * 64;
    int m0 = blockIdx.y * PBM;
    int n0 = blockIdx.x * PBN;

    int a_row = t >> 1;
    int a_c16 = (t & 1) * 2;
    const bf16* Ag = A + (size_t)(m0 + a_row) * K + a_c16 * 8;
    uint32_t a_s = S0 + a_row * PASTR + a_c16 * 16;
    int b_row = t >> 3;
    int b_c16 = (t & 7) * 2;
    const bf16* Bg = B + (size_t)b_row * N + n0 + b_c16 * 8;
    uint32_t b_s = S0 + PA_ST + b_row * PBSTR + b_c16 * 16;

    auto prefetch = [&](int chunk) {
        int st = chunk % 3;
        const bf16* ag = Ag + chunk * PBK;
        const bf16* bg = Bg + (size_t)chunk * PBK * N;
        uint32_t sa = a_s + st * PSTG;
        uint32_t sb = b_s + st * PSTG;
        asm volatile("cp.async.cg.shared.global [%0], [%1], 16;" :: "r"(sa), "l"(ag));
        asm volatile("cp.async.cg.shared.global [%0], [%1], 16;" :: "r"(sa + 16), "l"(ag + 8));
        asm volatile("cp.async.cg.shared.global [%0], [%1], 16;" :: "r"(sb), "l"(bg));
        asm volatile("cp.async.cg.shared.global [%0], [%1], 16;" :: "r"(sb + 16), "l"(bg + 8));
        asm volatile("cp.async.commit_group;");
    };

    uint32_t aoff[2], boff[4];
    #pragma unroll
    for (int mi = 0; mi < 2; ++mi)
        aoff[mi] = (wm + mi * 16 + (lane & 15)) * PASTR + (lane >> 4) * 16;
    int tile = lane >> 3;
    #pragma unroll
    for (int ni = 0; ni < 4; ++ni)
        boff[ni] = PA_ST + ((tile & 1) * 8 + (lane & 7)) * PBSTR
                 + (wn + ni * 16 + (tile >> 1) * 8) * 2;

    float acc[2][8][4];
    #pragma unroll
    for (int mi = 0; mi < 2; ++mi)
        #pragma unroll
        for (int nj = 0; nj < 8; ++nj)
            #pragma unroll
            for (int r = 0; r < 4; ++r) acc[mi][nj][r] = 0.f;

    int niter = K / PBK;
    prefetch(0);
    prefetch(1);

    for (int it = 0; it < niter; ++it) {
        if (it + 1 < niter) asm volatile("cp.async.wait_group 1;");
        else                asm volatile("cp.async.wait_group 0;");
        __syncthreads();
        if (it + 2 < niter) prefetch(it + 2);

        uint32_t Sb = S0 + (it % 3) * PSTG;
        #pragma unroll
        for (int kk = 0; kk < 2; ++kk) {
            uint32_t a[2][4];
            #pragma unroll
            for (int mi = 0; mi < 2; ++mi) {
                uint32_t addr = Sb + aoff[mi] + kk * 32;
                asm volatile("ldmatrix.sync.aligned.m8n8.x4.shared.b16 {%0,%1,%2,%3}, [%4];"
                    : "=r"(a[mi][0]), "=r"(a[mi][1]), "=r"(a[mi][2]), "=r"(a[mi][3]) : "r"(addr));
            }
            uint32_t bq[4][4];
            #pragma unroll
            for (int ni = 0; ni < 4; ++ni) {
                uint32_t addr = Sb + boff[ni] + kk * 16 * PBSTR;
                asm volatile("ldmatrix.sync.aligned.m8n8.x4.trans.shared.b16 {%0,%1,%2,%3}, [%4];"
                    : "=r"(bq[ni][0]), "=r"(bq[ni][1]), "=r"(bq[ni][2]), "=r"(bq[ni][3]) : "r"(addr));
            }
            #pragma unroll
            for (int mi = 0; mi < 2; ++mi)
                #pragma unroll
                for (int nj = 0; nj < 8; ++nj) {
                    uint32_t b0 = bq[nj >> 1][(nj & 1) * 2];
                    uint32_t b1 = bq[nj >> 1][(nj & 1) * 2 + 1];
                    asm volatile(
                        "mma.sync.aligned.m16n8k16.row.col.f32.bf16.bf16.f32 "
                        "{%0,%1,%2,%3}, {%4,%5,%6,%7}, {%8,%9}, {%0,%1,%2,%3};"
                        : "+f"(acc[mi][nj][0]), "+f"(acc[mi][nj][1]),
                          "+f"(acc[mi][nj][2]), "+f"(acc[mi][nj][3])
                        : "r"(a[mi][0]), "r"(a[mi][1]), "r"(a[mi][2]), "r"(a[mi][3]),
                          "r"(b0), "r"(b1));
                }
        }
    }

    int r_base = m0 + wm + (lane >> 2);
    int c_base = n0 + wn + (lane & 3) * 2;
    #pragma unroll
    for (int mi = 0; mi < 2; ++mi) {
        #pragma unroll
        for (int nj = 0; nj < 8; ++nj) {
            int r = r_base + mi * 16;
            int c = c_base + nj * 8;
            float bx = bias[c], by = bias[c + 1];
            float o00 = acc[mi][nj][0] + bx;
            float o01 = acc[mi][nj][1] + by;
            float o10 = acc[mi][nj][2] + bx;
            float o11 = acc[mi][nj][3] + by;
            if (EPI == 1) {
                o00 = gelu_f(o00); o01 = gelu_f(o01);
                o10 = gelu_f(o10); o11 = gelu_f(o11);
            }
            if (EPI == 2) {
                const float* rp0 = resid + (size_t)r * N + c;
                const float* rp1 = resid + (size_t)(r + 8) * N + c;
                float* Cf = (float*)Cp;
                float2 v0 = {o00 + rp0[0], o01 + rp0[1]};
                float2 v1 = {o10 + rp1[0], o11 + rp1[1]};
                *(float2*)(Cf + (size_t)r * N + c) = v0;
                *(float2*)(Cf + (size_t)(r + 8) * N + c) = v1;
            } else {
                bf16* Cb = (bf16*)Cp;
                __nv_bfloat162 v0 = {__float2bfloat16(o00), __float2bfloat16(o01)};
                __nv_bfloat162 v1 = {__float2bfloat16(o10), __float2bfloat16(o11)};
                *(__nv_bfloat162*)(Cb + (size_t)r * N + c) = v0;
                *(__nv_bfloat162*)(Cb + (size_t)(r + 8) * N + c) = v1;
            }
        }
    }
}

// ======== fused wout GEMM + residual + LN2: register-resident LN epilogue ====
#define QBM 64
#define QASTR 80
#define QBSTR 528
#define QA_SZ (QBM * QASTR)
#define QB_SZ (32 * QBSTR)
#define QSTG  (QA_SZ + QB_SZ)
#define QSMEM (3 * QSTG)

__global__ __launch_bounds__(256, 2)
void hgemm_wout_ln(const bf16* __restrict__ A, const bf16* __restrict__ B,
                   const float* __restrict__ bias, const float* __restrict__ resid,
                   float* __restrict__ xres, const float* __restrict__ g2,
                   const float* __restrict__ b2g, bf16* __restrict__ yb) {
    extern __shared__ char sm_[];
    uint32_t S0 = smem_u32(sm_);
    int t = threadIdx.x;
    int lane = t & 31, warp = t >> 5;
    int wm = (warp & 1) * 32;
    int wn = (warp >> 1) * 64;
    int wng = warp >> 1;
    int m0 = blockIdx.x * QBM;

    int a_row = t >> 2, a_c16 = t & 3;
    const bf16* Ag = A + (size_t)(m0 + a_row) * 256 + a_c16 * 8;
    uint32_t a_s = S0 + a_row * QASTR + a_c16 * 16;

    auto prefetch = [&](int ck) {
        int st = ck % 3;
        asm volatile("cp.async.cg.shared.global [%0], [%1], 16;"
                     :: "r"(a_s + st * QSTG), "l"(Ag + ck * 32));
        #pragma unroll
        for (int i = 0; i < 4; ++i) {
            int idx = t + i * 256;
            int row = idx >> 5, c16 = idx & 31;
            const bf16* bg = B + (size_t)(ck * 32 + row) * 256 + c16 * 8;
            uint32_t dst = S0 + st * QSTG + QA_SZ + row * QBSTR + c16 * 16;
            asm volatile("cp.async.cg.shared.global [%0], [%1], 16;" :: "r"(dst), "l"(bg));
        }
        asm volatile("cp.async.commit_group;");
    };

    uint32_t aoff[2], boff[4];
    #pragma unroll
    for (int mi = 0; mi < 2; ++mi)
        aoff[mi] = (wm + mi * 16 + (lane & 15)) * QASTR + (lane >> 4) * 16;
    int tile = lane >> 3;
    #pragma unroll
    for (int ni = 0; ni < 4; ++ni)
        boff[ni] = QA_SZ + ((tile & 1) * 8 + (lane & 7)) * QBSTR
                 + (wn + ni * 16 + (tile >> 1) * 8) * 2;

    float acc[2][8][4];
    #pragma unroll
    for (int mi = 0; mi < 2; ++mi)
        #pragma unroll
        for (int nj = 0; nj < 8; ++nj)
            #pragma unroll
            for (int r = 0; r < 4; ++r) acc[mi][nj][r] = 0.f;

    const int niter = 8;
    prefetch(0); prefetch(1);

    for (int it = 0; it < niter; ++it) {
        if (it + 1 < niter) asm volatile("cp.async.wait_group 1;");
        else                asm volatile("cp.async.wait_group 0;");
        __syncthreads();
        if (it + 2 < niter) prefetch(it + 2);

        uint32_t Sb = S0 + (it % 3) * QSTG;
        #pragma unroll
        for (int kk = 0; kk < 2; ++kk) {
            uint32_t a[2][4];
            #pragma unroll
            for (int mi = 0; mi < 2; ++mi) {
                uint32_t addr = Sb + aoff[mi] + kk * 32;
                asm volatile("ldmatrix.sync.aligned.m8n8.x4.shared.b16 {%0,%1,%2,%3}, [%4];"
                    : "=r"(a[mi][0]), "=r"(a[mi][1]), "=r"(a[mi][2]), "=r"(a[mi][3]) : "r"(addr));
            }
            uint32_t bq[4][4];
            #pragma unroll
            for (int ni = 0; ni < 4; ++ni) {
                uint32_t addr = Sb + boff[ni] + kk * 16 * QBSTR;
                asm volatile("ldmatrix.sync.aligned.m8n8.x4.trans.shared.b16 {%0,%1,%2,%3}, [%4];"
                    : "=r"(bq[ni][0]), "=r"(bq[ni][1]), "=r"(bq[ni][2]), "=r"(bq[ni][3]) : "r"(addr));
            }
            #pragma unroll
            for (int mi = 0; mi < 2; ++mi)
                #pragma unroll
                for (int nj = 0; nj < 8; ++nj) {
                    uint32_t b0 = bq[nj >> 1][(nj & 1) * 2];
                    uint32_t b1 = bq[nj >> 1][(nj & 1) * 2 + 1];
                    asm volatile(
                        "mma.sync.aligned.m16n8k16.row.col.f32.bf16.bf16.f32 "
                        "{%0,%1,%2,%3}, {%4,%5,%6,%7}, {%8,%9}, {%0,%1,%2,%3};"
                        : "+f"(acc[mi][nj][0]), "+f"(acc[mi][nj][1]),
                          "+f"(acc[mi][nj][2]), "+f"(acc[mi][nj][3])
                        : "r"(a[mi][0]), "r"(a[mi][1]), "r"(a[mi][2]), "r"(a[mi][3]),
                          "r"(b0), "r"(b1));
                }
        }
    }

    int lr0 = wm + (lane >> 2);
    int cb = wn + (lane & 3) * 2;
    #pragma unroll
    for (int mi = 0; mi < 2; ++mi) {
        #pragma unroll
        for (int nj = 0; nj < 8; ++nj) {
            int rl = lr0 + mi * 16;
            int c = cb + nj * 8;
            float bx = bias[c], by = bias[c + 1];
            const float* rp0 = resid + (size_t)(m0 + rl) * 256 + c;
            const float* rp1 = resid + (size_t)(m0 + rl + 8) * 256 + c;
            acc[mi][nj][0] += bx + rp0[0];
            acc[mi][nj][1] += by + rp0[1];
            acc[mi][nj][2] += bx + rp1[0];
            acc[mi][nj][3] += by + rp1[1];
            float2 v0 = {acc[mi][nj][0], acc[mi][nj][1]};
            float2 v1 = {acc[mi][nj][2], acc[mi][nj][3]};
            *(float2*)(xres + (size_t)(m0 + rl) * 256 + c) = v0;
            *(float2*)(xres + (size_t)(m0 + rl + 8) * 256 + c) = v1;
        }
    }

    float ls[4], lq[4];
    #pragma unroll
    for (int i = 0; i < 4; ++i) { ls[i] = 0.f; lq[i] = 0.f; }
    #pragma unroll
    for (int mi = 0; mi < 2; ++mi) {
        #pragma unroll
        for (int nj = 0; nj < 8; ++nj) {
            float a0 = acc[mi][nj][0], a1 = acc[mi][nj][1];
            float a2 = acc[mi][nj][2], a3 = acc[mi][nj][3];
            ls[mi * 2]     += a0 + a1;  lq[mi * 2]     += a0 * a0 + a1 * a1;
            ls[mi * 2 + 1] += a2 + a3;  lq[mi * 2 + 1] += a2 * a2 + a3 * a3;
        }
    }
    #pragma unroll
    for (int o = 1; o <= 2; o <<= 1) {
        #pragma unroll
        for (int i = 0; i < 4; ++i) {
            ls[i] += __shfl_xor_sync(0xffffffffu, ls[i], o);
            lq[i] += __shfl_xor_sync(0xffffffffu, lq[i], o);
        }
    }
    __syncthreads();
    float* part = (float*)sm_;
    if ((lane & 3) == 0) {
        int rbase = wm + (lane >> 2);
        #pragma unroll
        for (int i = 0; i < 4; ++i) {
            int rl = rbase + (i >> 1) * 16 + (i & 1) * 8;
            part[(rl * 4 + wng) * 2 + 0] = ls[i];
            part[(rl * 4 + wng) * 2 + 1] = lq[i];
        }
    }
    __syncthreads();

    float mean[4], inv[4];
    #pragma unroll
    for (int i = 0; i < 4; ++i) {
        int rl = lr0 + (i >> 1) * 16 + (i & 1) * 8;
        float s = 0.f, q = 0.f;
        #pragma unroll
        for (int gIdx = 0; gIdx < 4; ++gIdx) {
            s += part[(rl * 4 + gIdx) * 2 + 0];
            q += part[(rl * 4 + gIdx) * 2 + 1];
        }
        float m = s * (1.0f / 256.0f);
        float var = q * (1.0f / 256.0f) - m * m;
        mean[i] = m;
        inv[i] = rsqrtf(var + 1e-5f);
    }

    #pragma unroll
    for (int mi = 0; mi < 2; ++mi) {
        #pragma unroll
        for (int nj = 0; nj < 8; ++nj) {
            int rl = lr0 + mi * 16;
            int c = cb + nj * 8;
            float gx = g2[c], gy = g2[c + 1];
            float bbx = b2g[c], bby = b2g[c + 1];
            int i0 = mi * 2, i1 = mi * 2 + 1;
            float o00 = (acc[mi][nj][0] - mean[i0]) * inv[i0] * gx + bbx;
            float o01 = (acc[mi][nj][1] - mean[i0]) * inv[i0] * gy + bby;
            float o10 = (acc[mi][nj][2] - mean[i1]) * inv[i1] * gx + bbx;
            float o11 = (acc[mi][nj][3] - mean[i1]) * inv[i1] * gy + bby;
            __nv_bfloat162 y0 = {__float2bfloat16(o00), __float2bfloat16(o01)};
            __nv_bfloat162 y1 = {__float2bfloat16(o10), __float2bfloat16(o11)};
            *(__nv_bfloat162*)(yb + (size_t)(m0 + rl) * 256 + c) = y0;
            *(__nv_bfloat162*)(yb + (size_t)(m0 + rl + 8) * 256 + c) = y1;
        }
    }
}

// ---------------- Deformable sampling: one warp = (token, 4 heads) -----------
// lane>>3 selects head within half, lane&7 = channel quad (4 channels via 8B load)
__global__ void sample_kernel(const bf16* __restrict__ v, const float* __restrict__ offattn,
                              const float* __restrict__ rp, bf16* __restrict__ agg) {
    int gw = blockIdx.x * 8 + (threadIdx.x >> 5);
    int lane = threadIdx.x & 31;
    int tg = gw >> 1;                               // token
    int head = ((gw & 1) << 2) + (lane >> 3);       // 0..7
    int l8 = lane & 7;                              // channel quad within head
    int bb = tg >> 13;
    int pos = tg & 8191;

    const float* lg = offattn + (size_t)tg * 256 + 144 + head * 9;
    float w[9];
    float mx = -1e30f;
    #pragma unroll
    for (int k = 0; k < 9; ++k) { w[k] = lg[k]; mx = fmaxf(mx, w[k]); }
    float sum = 0.f;
    #pragma unroll
    for (int k = 0; k < 9; ++k) { w[k] = expf(w[k] - mx); sum += w[k]; }
    float inv = 1.0f / sum;

    const float* rpp  = rp + (size_t)pos * 18;
    const float* offp = offattn + (size_t)tg * 256 + head * 18;
    // v viewed as float2 (4 bf16 channels): row stride = 256/4 = 64
    const float2* vp = (const float2*)v;
    int chq = head * 8 + l8;                        // quad index within row
    int base = bb << 13;
    float a0 = 0.f, a1 = 0.f, a2 = 0.f, a3 = 0.f;
    #pragma unroll
    for (int k = 0; k < 9; ++k) {
        float cx = (rpp[k * 2 + 0] + offp[k * 2 + 0] + 1.0f) * 0.5f * 127.0f;
        float cy = (rpp[k * 2 + 1] + offp[k * 2 + 1] + 1.0f) * 0.5f * 63.0f;
        float fx = floorf(cx), fy = floorf(cy);
        float wx = cx - fx, wy = cy - fy;
        int x0 = min(max((int)fx, 0), 127);
        int x1 = min(max((int)fx + 1, 0), 127);
        int y0 = min(max((int)fy, 0), 63);
        int y1 = min(max((int)fy + 1, 0), 63);
        float2 q00 = vp[(size_t)(base + y0 * 128 + x0) * 64 + chq];
        float2 q01 = vp[(size_t)(base + y0 * 128 + x1) * 64 + chq];
        float2 q10 = vp[(size_t)(base + y1 * 128 + x0) * 64 + chq];
        float2 q11 = vp[(size_t)(base + y1 * 128 + x1) * 64 + chq];
        __nv_bfloat162 b00a = *(__nv_bfloat162*)&q00.x, b00b = *(__nv_bfloat162*)&q00.y;
        __nv_bfloat162 b01a = *(__nv_bfloat162*)&q01.x, b01b = *(__nv_bfloat162*)&q01.y;
        __nv_bfloat162 b10a = *(__nv_bfloat162*)&q10.x, b10b = *(__nv_bfloat162*)&q10.y;
        __nv_bfloat162 b11a = *(__nv_bfloat162*)&q11.x, b11b = *(__nv_bfloat162*)&q11.y;
        float2 v00a = __bfloat1622float2(b00a), v00b = __bfloat1622float2(b00b);
        float2 v01a = __bfloat1622float2(b01a), v01b = __bfloat1622float2(b01b);
        float2 v10a = __bfloat1622float2(b10a), v10b = __bfloat1622float2(b10b);
        float2 v11a = __bfloat1622float2(b11a), v11b = __bfloat1622float2(b11b);
        float w00 = (1.f - wy) * (1.f - wx), w01 = (1.f - wy) * wx;
        float w10 = wy * (1.f - wx),         w11 = wy * wx;
        float wk = w[k] * inv;
        a0 += (v00a.x * w00 + v01a.x * w01 + v10a.x * w10 + v11a.x * w11) * wk;
        a1 += (v00a.y * w00 + v01a.y * w01 + v10a.y * w10 + v11a.y * w11) * wk;
        a2 += (v00b.x * w00 + v01b.x * w01 + v10b.x * w10 + v11b.x * w11) * wk;
        a3 += (v00b.y * w00 + v01b.y * w01 + v10b.y * w10 + v11b.y * w11) * wk;
    }
    __nv_bfloat162 o0 = {__float2bfloat16(a0), __float2bfloat16(a1)};
    __nv_bfloat162 o1 = {__float2bfloat16(a2), __float2bfloat16(a3)};
    uint2 ov = {*(uint32_t*)&o0, *(uint32_t*)&o1};
    *(uint2*)(agg + (size_t)tg * 256 + chq * 4) = ov;
}

// ---------------- Depthwise 3x3 conv: sliding window, 4-way x-split ----------
__global__ void dwconv_kernel(const bf16* __restrict__ h, const float* __restrict__ wdw,
                              const float* __restrict__ bdw, bf16* __restrict__ o) {
    int c2 = blockIdx.x * 256 + threadIdx.x;
    int y = blockIdx.y & 63;
    int seg = blockIdx.y >> 6;
    int bb = blockIdx.z;
    int c = c2 * 2;
    int x0 = seg * 32;

    float w0[9], w1[9];
    #pragma unroll
    for (int i = 0; i < 9; ++i) { w0[i] = wdw[c * 9 + i]; w1[i] = wdw[(c + 1) * 9 + i]; }
    float bb0 = bdw[c], bb1 = bdw[c + 1];

    const __nv_bfloat162* hp = (const __nv_bfloat162*)h;
    size_t base = ((size_t)(bb << 13) + y * 128) * 512 + c2;
    bool hu = (y > 0), hd = (y < 63);
    __nv_bfloat162 zero = __float2bfloat162_rn(0.f);

    __nv_bfloat162 cm[3], cc[3], cn[3];
    {
        size_t p = base + ((x0 + 127) & 127) * 512;
        cm[0] = hu ? hp[p - 65536] : zero; cm[1] = hp[p]; cm[2] = hd ? hp[p + 65536] : zero;
        p = base + x0 * 512;
        cc[0] = hu ? hp[p - 65536] : zero; cc[1] = hp[p]; cc[2] = hd ? hp[p + 65536] : zero;
    }
    bf16* op = o + ((size_t)(bb << 13) + y * 128) * 1024 + c;

    for (int x = x0; x < x0 + 32; ++x) {
        size_t p = base + ((x + 1) & 127) * 512;
        cn[0] = hu ? hp[p - 65536] : zero; cn[1] = hp[p]; cn[2] = hd ? hp[p + 65536] : zero;

        float a0 = bb0, a1 = bb1;
        #pragma unroll
        for (int dy = 0; dy < 3; ++dy) {
            float2 vm = __bfloat1622float2(cm[dy]);
            float2 vc = __bfloat1622float2(cc[dy]);
            float2 vp = __bfloat1622float2(cn[dy]);
            a0 += vm.x * w0[dy * 3 + 0] + vc.x * w0[dy * 3 + 1] + vp.x * w0[dy * 3 + 2];
            a1 += vm.y * w1[dy * 3 + 0] + vc.y * w1[dy * 3 + 1] + vp.y * w1[dy * 3 + 2];
        }
        __nv_bfloat162 ov = {__float2bfloat16(gelu_f(a0)), __float2bfloat16(gelu_f(a1))};
        *(__nv_bfloat162*)(op + (size_t)x * 1024) = ov;

        #pragma unroll
        for (int i = 0; i < 3; ++i) { cm[i] = cc[i]; cc[i] = cn[i]; }
    }
}

// ---------------- launch ----------------
extern "C" void kernel_launch(void* const* d_in, const int* in_sizes, int n_in,
                              void* d_out, int out_size) {
    const float* x      = (const float*)d_in[0];
    const float* rp     = (const float*)d_in[1];
    const float* ln1_g  = (const float*)d_in[2];
    const float* ln1_b  = (const float*)d_in[3];
    const float* w_v    = (const float*)d_in[4];
    const float* b_v    = (const float*)d_in[5];
    const float* w_off  = (const float*)d_in[6];
    const float* b_off  = (const float*)d_in[7];
    const float* w_attn = (const float*)d_in[8];
    const float* b_attn = (const float*)d_in[9];
    const float* w_out  = (const float*)d_in[10];
    const float* b_out  = (const float*)d_in[11];
    const float* ln2_g  = (const float*)d_in[12];
    const float* ln2_b  = (const float*)d_in[13];
    const float* w1     = (const float*)d_in[14];
    const float* b1     = (const float*)d_in[15];
    const float* w_dw   = (const float*)d_in[16];
    const float* b_dw   = (const float*)d_in[17];
    const float* w2     = (const float*)d_in[18];
    const float* b2     = (const float*)d_in[19];
    float* out = (float*)d_out;

    float *xn, *offattn, *xres, *wcat, *bcat;
    bf16 *xnb, *vb, *aggb, *yb, *hb, *h2b, *wvb, *woutb, *w1b, *w2b;
    cudaGetSymbolAddress((void**)&xn,      g_xn);
    cudaGetSymbolAddress((void**)&offattn, g_offattn);
    cudaGetSymbolAddress((void**)&xres,    g_xres);
    cudaGetSymbolAddress((void**)&wcat,    g_wcat);
    cudaGetSymbolAddress((void**)&bcat,    g_bcat);
    cudaGetSymbolAddress((void**)&xnb,     g_xnb);
    cudaGetSymbolAddress((void**)&vb,      g_vb);
    cudaGetSymbolAddress((void**)&aggb,    g_aggb);
    cudaGetSymbolAddress((void**)&yb,      g_yb);
    cudaGetSymbolAddress((void**)&hb,      g_hb);
    cudaGetSymbolAddress((void**)&h2b,     g_h2b);
    cudaGetSymbolAddress((void**)&wvb,     g_wvb);
    cudaGetSymbolAddress((void**)&woutb,   g_woutb);
    cudaGetSymbolAddress((void**)&w1b,     g_w1b);
    cudaGetSymbolAddress((void**)&w2b,     g_w2b);

    cudaFuncSetAttribute(hgemm_kernel<1>, cudaFuncAttributeMaxDynamicSharedMemorySize, PSMEM);
    cudaFuncSetAttribute(hgemm_kernel<2>, cudaFuncAttributeMaxDynamicSharedMemorySize, PSMEM);
    cudaFuncSetAttribute(fused_k2,        cudaFuncAttributeMaxDynamicSharedMemorySize, H64_SMEM);
    cudaFuncSetAttribute(hgemm_wout_ln,   cudaFuncAttributeMaxDynamicSharedMemorySize, QSMEM);

    // K1: LN1 || weight prep
    prep_ln_kernel<<<NTOK + 2816, 256>>>(
        x, ln1_g, ln1_b, xn, xnb,
        w_v, w_out, w1, w2, w_off, w_attn, b_off, b_attn,
        wvb, woutb, w1b, w2b, wcat, bcat);
    // K2: v projection || offsets+attn (resource-matched 64x128 bodies)
    fused_k2<<<dim3(2, NTOK / 64, 2), 256, H64_SMEM>>>(
        xnb, wvb, b_v, vb, xn, wcat, bcat, offattn);
    // K3: softmax + bilinear sampling + aggregation (4 heads/warp, 8B gathers)
    sample_kernel<<<NTOK / 4, 256>>>(vb, offattn, rp, aggb);
    // K4: output proj + residual + LN2 fused (register-resident LN)
    hgemm_wout_ln<<<NTOK / QBM, 256, QSMEM>>>(aggb, woutb, b_out, x, xres, ln2_g, ln2_b, yb);
    // K5: fc1 + GELU (bf16 TC, 128x128)
    hgemm_kernel<1><<<dim3(HID / PBN, NTOK / PBM), 256, PSMEM>>>(yb, w1b, b1, nullptr, hb, HID, 256);
    // K6: depthwise conv + GELU
    dwconv_kernel<<<dim3(2, 256, 2), 256>>>(hb, w_dw, b_dw, h2b);
    // K7: fc2 + residual -> out (f32, 128x128)
    hgemm_kernel<2><<<dim3(256 / PBN, NTOK / PBM), 256, PSMEM>>>(h2b, w2b, b2, xres, out, 256, 1024);
}

// round 16
// speedup vs baseline: 1.1504x; 1.0495x over previous
#include <cuda_runtime.h>
#include <cuda_bf16.h>
#include <math.h>
#include <stdint.h>

typedef __nv_bfloat16 bf16;

#define NTOK 16384
#define CDIM 256
#define HID  1024

// -------- scratch (__device__ globals; no allocations allowed) --------
__device__ float g_xn     [NTOK * CDIM];
__device__ float g_offattn[NTOK * 256];
__device__ float g_xres   [NTOK * CDIM];
__device__ bf16  g_xnb    [NTOK * CDIM];
__device__ bf16  g_vb     [NTOK * CDIM];
__device__ bf16  g_aggb   [NTOK * CDIM];
__device__ bf16  g_yb     [NTOK * CDIM];
__device__ bf16  g_hb     [NTOK * HID];
__device__ bf16  g_h2b    [NTOK * HID];
__device__ bf16  g_wvb    [256 * 256];
__device__ bf16  g_woutb  [256 * 256];
__device__ bf16  g_w1b    [256 * 1024];
__device__ bf16  g_w2b    [1024 * 256];
__device__ float g_wcat   [256 * 256];
__device__ float g_bcat   [256];

__device__ __forceinline__ float gelu_f(float v) {
    return 0.5f * v * (1.0f + erff(v * 0.7071067811865476f));
}

__device__ __forceinline__ uint32_t smem_u32(const void* p) {
    uint32_t a;
    asm("{ .reg .u64 t; cvta.to.shared.u64 t, %1; cvt.u32.u64 %0, t; }" : "=r"(a) : "l"(p));
    return a;
}

__device__ __forceinline__ uint32_t f2tf32(float f) {
    uint32_t r;
    asm("cvt.rna.tf32.f32 %0, %1;" : "=r"(r) : "f"(f));
    return r;
}

// ================= K1: fused prep + LN1 (block-range dispatch) =================
__global__ void prep_ln_kernel(
    const float* __restrict__ x, const float* __restrict__ g, const float* __restrict__ b,
    float* __restrict__ xn, bf16* __restrict__ xnb,
    const float* wv, const float* wout, const float* w1, const float* w2,
    const float* w_off, const float* w_attn, const float* b_off, const float* b_attn,
    bf16* wvb, bf16* woutb, bf16* w1b, bf16* w2b, float* wcat, float* bcat) {
    if (blockIdx.x < NTOK) {
        int tok = blockIdx.x;
        int c = threadIdx.x;
        float v = x[(size_t)tok * CDIM + c];
        __shared__ float sh[8];
        float s = v;
        #pragma unroll
        for (int o = 16; o; o >>= 1) s += __shfl_xor_sync(0xffffffffu, s, o);
        if ((c & 31) == 0) sh[c >> 5] = s;
        __syncthreads();
        float tot = 0.f;
        #pragma unroll
        for (int i = 0; i < 8; ++i) tot += sh[i];
        float mean = tot * (1.0f / CDIM);
        __syncthreads();
        float d = v - mean;
        float s2 = d * d;
        #pragma unroll
        for (int o = 16; o; o >>= 1) s2 += __shfl_xor_sync(0xffffffffu, s2, o);
        if ((c & 31) == 0) sh[c >> 5] = s2;
        __syncthreads();
        float v2 = 0.f;
        #pragma unroll
        for (int i = 0; i < 8; ++i) v2 += sh[i];
        float var = v2 * (1.0f / CDIM);
        float out = d * rsqrtf(var + 1e-5f) * g[c] + b[c];
        xn[(size_t)tok * CDIM + c]  = __uint_as_float(f2tf32(out));
        xnb[(size_t)tok * CDIM + c] = __float2bfloat16(out);
        return;
    }
    int i = (blockIdx.x - NTOK) * 256 + threadIdx.x;
    if (i < 65536) { wvb[i] = __float2bfloat16(wv[i]); return; }
    i -= 65536;
    if (i < 65536) { woutb[i] = __float2bfloat16(wout[i]); return; }
    i -= 65536;
    if (i < 262144) { w1b[i] = __float2bfloat16(w1[i]); return; }
    i -= 262144;
    if (i < 262144) { w2b[i] = __float2bfloat16(w2[i]); return; }
    i -= 262144;
    if (i < 65536) {
        int k = i >> 8, col = i & 255;
        float v = (col < 144) ? w_off[k * 144 + col]
                : (col < 216) ? w_attn[k * 72 + (col - 144)] : 0.f;
        wcat[i] = __uint_as_float(f2tf32(v));
        if (k == 0)
            bcat[col] = (col < 144) ? b_off[col]
                      : (col < 216) ? b_attn[col - 144] : 0.f;
    }
}

// ---------------- shared GEMM geometry constants ----------------
#define PBK 32
#define PASTR 80
#define PBSTR 272
#define H64_A  (64 * PASTR)
#define H64_B  (PBK * PBSTR)
#define H64_STG (H64_A + H64_B)
#define H64_SMEM (3 * H64_STG)
#define TFA_STR 20
#define TFB_STR 136
#define TFA_SZ  (64 * TFA_STR * 4)
#define TFB_SZ  (16 * TFB_STR * 4)
#define TF_STG  (TFA_SZ + TFB_SZ)

// ---------------- tf32 GEMM device body: 64x128x16, 3-stage ------------------
__device__ void tgemm64_dev(char* sm_, int bx, int by,
                            const float* __restrict__ A, const float* __restrict__ Bw,
                            const float* __restrict__ bias, float* __restrict__ C) {
    uint32_t S0 = smem_u32(sm_);
    int t = threadIdx.x;
    int lane = t & 31, warp = t >> 5;
    int wm = (warp & 1) * 32;
    int wn = (warp >> 1) * 32;
    int m0 = by * 64;
    int n0 = bx * 128;

    int a_row = t >> 2, a_c4 = (t & 3) * 4;
    const float* Ag = A + (size_t)(m0 + a_row) * 256 + a_c4;
    uint32_t a_s = S0 + (a_row * TFA_STR + a_c4) * 4;

    auto prefetch = [&](int it) {
        int st = it % 3;
        asm volatile("cp.async.cg.shared.global [%0], [%1], 16;"
                     :: "r"(a_s + st * TF_STG), "l"(Ag + it * 16));
        #pragma unroll
        for (int i = 0; i < 2; ++i) {
            int idx = t + i * 256;
            int row = idx >> 5, c4 = (idx & 31) * 4;
            const float* bg = Bw + (size_t)(it * 16 + row) * 256 + n0 + c4;
            uint32_t dst = S0 + TFA_SZ + (row * TFB_STR + c4) * 4 + st * TF_STG;
            asm volatile("cp.async.cg.shared.global [%0], [%1], 16;" :: "r"(dst), "l"(bg));
        }
        asm volatile("cp.async.commit_group;");
    };

    float acc[2][4][4];
    #pragma unroll
    for (int mi = 0; mi < 2; ++mi)
        #pragma unroll
        for (int nj = 0; nj < 4; ++nj)
            #pragma unroll
            for (int r = 0; r < 4; ++r) acc[mi][nj][r] = 0.f;

    const int niter = 16;
    prefetch(0); prefetch(1);

    int lr = lane >> 2, lc = lane & 3;
    for (int it = 0; it < niter; ++it) {
        if (it + 1 < niter) asm volatile("cp.async.wait_group 1;");
        else                asm volatile("cp.async.wait_group 0;");
        __syncthreads();
        if (it + 2 < niter) prefetch(it + 2);

        const uint32_t* As = (const uint32_t*)(sm_ + (it % 3) * TF_STG);
        const uint32_t* Bs = (const uint32_t*)(sm_ + (it % 3) * TF_STG + TFA_SZ);

        #pragma unroll
        for (int kk = 0; kk < 2; ++kk) {
            uint32_t af[2][4];
            #pragma unroll
            for (int mi = 0; mi < 2; ++mi) {
                int rb = wm + mi * 16 + lr;
                af[mi][0] = As[rb * TFA_STR + kk * 8 + lc];
                af[mi][1] = As[(rb + 8) * TFA_STR + kk * 8 + lc];
                af[mi][2] = As[rb * TFA_STR + kk * 8 + lc + 4];
                af[mi][3] = As[(rb + 8) * TFA_STR + kk * 8 + lc + 4];
            }
            #pragma unroll
            for (int nj = 0; nj < 4; ++nj) {
                uint32_t b0 = Bs[(kk * 8 + lc) * TFB_STR + wn + nj * 8 + lr];
                uint32_t b1 = Bs[(kk * 8 + lc + 4) * TFB_STR + wn + nj * 8 + lr];
                #pragma unroll
                for (int mi = 0; mi < 2; ++mi)
                    asm volatile(
                        "mma.sync.aligned.m16n8k8.row.col.f32.tf32.tf32.f32 "
                        "{%0,%1,%2,%3}, {%4,%5,%6,%7}, {%8,%9}, {%0,%1,%2,%3};"
                        : "+f"(acc[mi][nj][0]), "+f"(acc[mi][nj][1]),
                          "+f"(acc[mi][nj][2]), "+f"(acc[mi][nj][3])
                        : "r"(af[mi][0]), "r"(af[mi][1]), "r"(af[mi][2]), "r"(af[mi][3]),
                          "r"(b0), "r"(b1));
            }
        }
    }

    #pragma unroll
    for (int mi = 0; mi < 2; ++mi) {
        #pragma unroll
        for (int nj = 0; nj < 4; ++nj) {
            int r = m0 + wm + mi * 16 + lr;
            int c = n0 + wn + nj * 8 + lc * 2;
            float bx2 = bias[c], by2 = bias[c + 1];
            float2 v0 = {acc[mi][nj][0] + bx2, acc[mi][nj][1] + by2};
            float2 v1 = {acc[mi][nj][2] + bx2, acc[mi][nj][3] + by2};
            *(float2*)(C + (size_t)r * 256 + c) = v0;
            *(float2*)(C + (size_t)(r + 8) * 256 + c) = v1;
        }
    }
}

// ---------------- bf16 GEMM device body: 64x128x32, 3-stage ------------------
template<int EPI>
__device__ void hgemm64_dev(char* sm_, int bx, int by,
                            const bf16* __restrict__ A, const bf16* __restrict__ B,
                            const float* __restrict__ bias, const float* __restrict__ resid,
                            void* __restrict__ Cp, int N, int K) {
    uint32_t S0 = smem_u32(sm_);
    int t = threadIdx.x;
    int lane = t & 31, warp = t >> 5;
    int wm = (warp & 1) * 32;
    int wn = (warp >> 1) * 32;
    int m0 = by * 64;
    int n0 = bx * 128;

    int a_row = t >> 2, a_c16 = t & 3;
    const bf16* Ag = A + (size_t)(m0 + a_row) * K + a_c16 * 8;
    uint32_t a_s = S0 + a_row * PASTR + a_c16 * 16;
    int b_row = t >> 3;
    int b_c16 = (t & 7) * 2;
    const bf16* Bg = B + (size_t)b_row * N + n0 + b_c16 * 8;
    uint32_t b_s = S0 + H64_A + b_row * PBSTR + b_c16 * 16;

    auto prefetch = [&](int chunk) {
        int st = chunk % 3;
        const bf16* bg = Bg + (size_t)chunk * PBK * N;
        asm volatile("cp.async.cg.shared.global [%0], [%1], 16;"
                     :: "r"(a_s + st * H64_STG), "l"(Ag + chunk * PBK));
        asm volatile("cp.async.cg.shared.global [%0], [%1], 16;" :: "r"(b_s + st * H64_STG), "l"(bg));
        asm volatile("cp.async.cg.shared.global [%0], [%1], 16;" :: "r"(b_s + st * H64_STG + 16), "l"(bg + 8));
        asm volatile("cp.async.commit_group;");
    };

    uint32_t aoff[2], boff[2];
    #pragma unroll
    for (int mi = 0; mi < 2; ++mi)
        aoff[mi] = (wm + mi * 16 + (lane & 15)) * PASTR + (lane >> 4) * 16;
    int tile = lane >> 3;
    #pragma unroll
    for (int ni = 0; ni < 2; ++ni)
        boff[ni] = H64_A + ((tile & 1) * 8 + (lane & 7)) * PBSTR
                 + (wn + ni * 16 + (tile >> 1) * 8) * 2;

    float acc[2][4][4];
    #pragma unroll
    for (int mi = 0; mi < 2; ++mi)
        #pragma unroll
        for (int nj = 0; nj < 4; ++nj)
            #pragma unroll
            for (int r = 0; r < 4; ++r) acc[mi][nj][r] = 0.f;

    int niter = K / PBK;
    prefetch(0); prefetch(1);

    for (int it = 0; it < niter; ++it) {
        if (it + 1 < niter) asm volatile("cp.async.wait_group 1;");
        else                asm volatile("cp.async.wait_group 0;");
        __syncthreads();
        if (it + 2 < niter) prefetch(it + 2);

        uint32_t Sb = S0 + (it % 3) * H64_STG;
        #pragma unroll
        for (int kk = 0; kk < 2; ++kk) {
            uint32_t a[2][4];
            #pragma unroll
            for (int mi = 0; mi < 2; ++mi) {
                uint32_t addr = Sb + aoff[mi] + kk * 32;
                asm volatile("ldmatrix.sync.aligned.m8n8.x4.shared.b16 {%0,%1,%2,%3}, [%4];"
                    : "=r"(a[mi][0]), "=r"(a[mi][1]), "=r"(a[mi][2]), "=r"(a[mi][3]) : "r"(addr));
            }
            uint32_t bq[2][4];
            #pragma unroll
            for (int ni = 0; ni < 2; ++ni) {
                uint32_t addr = Sb + boff[ni] + kk * 16 * PBSTR;
                asm volatile("ldmatrix.sync.aligned.m8n8.x4.trans.shared.b16 {%0,%1,%2,%3}, [%4];"
                    : "=r"(bq[ni][0]), "=r"(bq[ni][1]), "=r"(bq[ni][2]), "=r"(bq[ni][3]) : "r"(addr));
            }
            #pragma unroll
            for (int mi = 0; mi < 2; ++mi)
                #pragma unroll
                for (int nj = 0; nj < 4; ++nj) {
                    uint32_t b0 = bq[nj >> 1][(nj & 1) * 2];
                    uint32_t b1 = bq[nj >> 1][(nj & 1) * 2 + 1];
                    asm volatile(
                        "mma.sync.aligned.m16n8k16.row.col.f32.bf16.bf16.f32 "
                        "{%0,%1,%2,%3}, {%4,%5,%6,%7}, {%8,%9}, {%0,%1,%2,%3};"
                        : "+f"(acc[mi][nj][0]), "+f"(acc[mi][nj][1]),
                          "+f"(acc[mi][nj][2]), "+f"(acc[mi][nj][3])
                        : "r"(a[mi][0]), "r"(a[mi][1]), "r"(a[mi][2]), "r"(a[mi][3]),
                          "r"(b0), "r"(b1));
                }
        }
    }

    int r_base = m0 + wm + (lane >> 2);
    int c_base = n0 + wn + (lane & 3) * 2;
    #pragma unroll
    for (int mi = 0; mi < 2; ++mi) {
        #pragma unroll
        for (int nj = 0; nj < 4; ++nj) {
            int r = r_base + mi * 16;
            int c = c_base + nj * 8;
            float bx2 = bias[c], by2 = bias[c + 1];
            float o00 = acc[mi][nj][0] + bx2;
            float o01 = acc[mi][nj][1] + by2;
            float o10 = acc[mi][nj][2] + bx2;
            float o11 = acc[mi][nj][3] + by2;
            if (EPI == 2) {
                const float* rp0 = resid + (size_t)r * N + c;
                const float* rp1 = resid + (size_t)(r + 8) * N + c;
                float* Cf = (float*)Cp;
                float2 v0 = {o00 + rp0[0], o01 + rp0[1]};
                float2 v1 = {o10 + rp1[0], o11 + rp1[1]};
                *(float2*)(Cf + (size_t)r * N + c) = v0;
                *(float2*)(Cf + (size_t)(r + 8) * N + c) = v1;
            } else {
                bf16* Cb = (bf16*)Cp;
                __nv_bfloat162 v0 = {__float2bfloat16(o00), __float2bfloat16(o01)};
                __nv_bfloat162 v1 = {__float2bfloat16(o10), __float2bfloat16(o11)};
                *(__nv_bfloat162*)(Cb + (size_t)r * N + c) = v0;
                *(__nv_bfloat162*)(Cb + (size_t)(r + 8) * N + c) = v1;
            }
        }
    }
}

// ========== K2: fused v-proj (bf16, 64x128) || off/attn (tf32, 64x128) =======
__global__ __launch_bounds__(256)
void fused_k2(const bf16* __restrict__ xnb, const bf16* __restrict__ wvb,
              const float* __restrict__ b_v, bf16* __restrict__ vb,
              const float* __restrict__ xn, const float* __restrict__ wcat,
              const float* __restrict__ bcat, float* __restrict__ offattn) {
    extern __shared__ char sm_[];
    if (blockIdx.z == 0)
        hgemm64_dev<0>(sm_, blockIdx.x, blockIdx.y, xnb, wvb, b_v, nullptr, vb, 256, 256);
    else
        tgemm64_dev(sm_, blockIdx.x, blockIdx.y, xn, wcat, bcat, offattn);
}

// ---------------- bf16 GEMM 128x128x32 (fc1, fc2), 3-stage -------------------
#define PBM 128
#define PBN 128
#define PA_ST (PBM * PASTR)
#define PB_ST (PBK * PBSTR)
#define PSTG  (PA_ST + PB_ST)
#define PSMEM (3 * PSTG)

template<int EPI>
__global__ __launch_bounds__(256)
void hgemm_kernel(const bf16* __restrict__ A, const bf16* __restrict__ B,
                  const float* __restrict__ bias, const float* __restrict__ resid,
                  void* __restrict__ Cp, int N, int K) {
    extern __shared__ char sm_[];
    uint32_t S0 = smem_u32(sm_);

    int t = threadIdx.x;
    int lane = t & 31, warp = t >> 5;
    int wm = (warp & 3) * 32;
    int wn = (warp >> 2) * 64;
    int m0 = blockIdx.y * PBM;
    int n0 = blockIdx.x * PBN;

    int a_row = t >> 1;
    int a_c16 = (t & 1) * 2;
    const bf16* Ag = A + (size_t)(m0 + a_row) * K + a_c16 * 8;
    uint32_t a_s = S0 + a_row * PASTR + a_c16 * 16;
    int b_row = t >> 3;
    int b_c16 = (t & 7) * 2;
    const bf16* Bg = B + (size_t)b_row * N + n0 + b_c16 * 8;
    uint32_t b_s = S0 + PA_ST + b_row * PBSTR + b_c16 * 16;

    auto prefetch = [&](int chunk) {
        int st = chunk % 3;
        const bf16* ag = Ag + chunk * PBK;
        const bf16* bg = Bg + (size_t)chunk * PBK * N;
        uint32_t sa = a_s + st * PSTG;
        uint32_t sb = b_s + st * PSTG;
        asm volatile("cp.async.cg.shared.global [%0], [%1], 16;" :: "r"(sa), "l"(ag));
        asm volatile("cp.async.cg.shared.global [%0], [%1], 16;" :: "r"(sa + 16), "l"(ag + 8));
        asm volatile("cp.async.cg.shared.global [%0], [%1], 16;" :: "r"(sb), "l"(bg));
        asm volatile("cp.async.cg.shared.global [%0], [%1], 16;" :: "r"(sb + 16), "l"(bg + 8));
        asm volatile("cp.async.commit_group;");
    };

    uint32_t aoff[2], boff[4];
    #pragma unroll
    for (int mi = 0; mi < 2; ++mi)
        aoff[mi] = (wm + mi * 16 + (lane & 15)) * PASTR + (lane >> 4) * 16;
    int tile = lane >> 3;
    #pragma unroll
    for (int ni = 0; ni < 4; ++ni)
        boff[ni] = PA_ST + ((tile & 1) * 8 + (lane & 7)) * PBSTR
                 + (wn + ni * 16 + (tile >> 1) * 8) * 2;

    float acc[2][8][4];
    #pragma unroll
    for (int mi = 0; mi < 2; ++mi)
        #pragma unroll
        for (int nj = 0; nj < 8; ++nj)
            #pragma unroll
            for (int r = 0; r < 4; ++r) acc[mi][nj][r] = 0.f;

    int niter = K / PBK;
    prefetch(0);
    prefetch(1);

    for (int it = 0; it < niter; ++it) {
        if (it + 1 < niter) asm volatile("cp.async.wait_group 1;");
        else                asm volatile("cp.async.wait_group 0;");
        __syncthreads();
        if (it + 2 < niter) prefetch(it + 2);

        uint32_t Sb = S0 + (it % 3) * PSTG;
        #pragma unroll
        for (int kk = 0; kk < 2; ++kk) {
            uint32_t a[2][4];
            #pragma unroll
            for (int mi = 0; mi < 2; ++mi) {
                uint32_t addr = Sb + aoff[mi] + kk * 32;
                asm volatile("ldmatrix.sync.aligned.m8n8.x4.shared.b16 {%0,%1,%2,%3}, [%4];"
                    : "=r"(a[mi][0]), "=r"(a[mi][1]), "=r"(a[mi][2]), "=r"(a[mi][3]) : "r"(addr));
            }
            uint32_t bq[4][4];
            #pragma unroll
            for (int ni = 0; ni < 4; ++ni) {
                uint32_t addr = Sb + boff[ni] + kk * 16 * PBSTR;
                asm volatile("ldmatrix.sync.aligned.m8n8.x4.trans.shared.b16 {%0,%1,%2,%3}, [%4];"
                    : "=r"(bq[ni][0]), "=r"(bq[ni][1]), "=r"(bq[ni][2]), "=r"(bq[ni][3]) : "r"(addr));
            }
            #pragma unroll
            for (int mi = 0; mi < 2; ++mi)
                #pragma unroll
                for (int nj = 0; nj < 8; ++nj) {
                    uint32_t b0 = bq[nj >> 1][(nj & 1) * 2];
                    uint32_t b1 = bq[nj >> 1][(nj & 1) * 2 + 1];
                    asm volatile(
                        "mma.sync.aligned.m16n8k16.row.col.f32.bf16.bf16.f32 "
                        "{%0,%1,%2,%3}, {%4,%5,%6,%7}, {%8,%9}, {%0,%1,%2,%3};"
                        : "+f"(acc[mi][nj][0]), "+f"(acc[mi][nj][1]),
                          "+f"(acc[mi][nj][2]), "+f"(acc[mi][nj][3])
                        : "r"(a[mi][0]), "r"(a[mi][1]), "r"(a[mi][2]), "r"(a[mi][3]),
                          "r"(b0), "r"(b1));
                }
        }
    }

    int r_base = m0 + wm + (lane >> 2);
    int c_base = n0 + wn + (lane & 3) * 2;
    #pragma unroll
    for (int mi = 0; mi < 2; ++mi) {
        #pragma unroll
        for (int nj = 0; nj < 8; ++nj) {
            int r = r_base + mi * 16;
            int c = c_base + nj * 8;
            float bx = bias[c], by = bias[c + 1];
            float o00 = acc[mi][nj][0] + bx;
            float o01 = acc[mi][nj][1] + by;
            float o10 = acc[mi][nj][2] + bx;
            float o11 = acc[mi][nj][3] + by;
            if (EPI == 1) {
                o00 = gelu_f(o00); o01 = gelu_f(o01);
                o10 = gelu_f(o10); o11 = gelu_f(o11);
            }
            if (EPI == 2) {
                const float* rp0 = resid + (size_t)r * N + c;
                const float* rp1 = resid + (size_t)(r + 8) * N + c;
                float* Cf = (float*)Cp;
                float2 v0 = {o00 + rp0[0], o01 + rp0[1]};
                float2 v1 = {o10 + rp1[0], o11 + rp1[1]};
                *(float2*)(Cf + (size_t)r * N + c) = v0;
                *(float2*)(Cf + (size_t)(r + 8) * N + c) = v1;
            } else {
                bf16* Cb = (bf16*)Cp;
                __nv_bfloat162 v0 = {__float2bfloat16(o00), __float2bfloat16(o01)};
                __nv_bfloat162 v1 = {__float2bfloat16(o10), __float2bfloat16(o11)};
                *(__nv_bfloat162*)(Cb + (size_t)r * N + c) = v0;
                *(__nv_bfloat162*)(Cb + (size_t)(r + 8) * N + c) = v1;
            }
        }
    }
}

// ======== fused wout GEMM + residual + LN2: register-resident LN epilogue ====
#define QBM 64
#define QASTR 80
#define QBSTR 528
#define QA_SZ (QBM * QASTR)
#define QB_SZ (32 * QBSTR)
#define QSTG  (QA_SZ + QB_SZ)
#define QSMEM (3 * QSTG)

__global__ __launch_bounds__(256, 2)
void hgemm_wout_ln(const bf16* __restrict__ A, const bf16* __restrict__ B,
                   const float* __restrict__ bias, const float* __restrict__ resid,
                   float* __restrict__ xres, const float* __restrict__ g2,
                   const float* __restrict__ b2g, bf16* __restrict__ yb) {
    extern __shared__ char sm_[];
    uint32_t S0 = smem_u32(sm_);
    int t = threadIdx.x;
    int lane = t & 31, warp = t >> 5;
    int wm = (warp & 1) * 32;
    int wn = (warp >> 1) * 64;
    int wng = warp >> 1;
    int m0 = blockIdx.x * QBM;

    int a_row = t >> 2, a_c16 = t & 3;
    const bf16* Ag = A + (size_t)(m0 + a_row) * 256 + a_c16 * 8;
    uint32_t a_s = S0 + a_row * QASTR + a_c16 * 16;

    auto prefetch = [&](int ck) {
        int st = ck % 3;
        asm volatile("cp.async.cg.shared.global [%0], [%1], 16;"
                     :: "r"(a_s + st * QSTG), "l"(Ag + ck * 32));
        #pragma unroll
        for (int i = 0; i < 4; ++i) {
            int idx = t + i * 256;
            int row = idx >> 5, c16 = idx & 31;
            const bf16* bg = B + (size_t)(ck * 32 + row) * 256 + c16 * 8;
            uint32_t dst = S0 + st * QSTG + QA_SZ + row * QBSTR + c16 * 16;
            asm volatile("cp.async.cg.shared.global [%0], [%1], 16;" :: "r"(dst), "l"(bg));
        }
        asm volatile("cp.async.commit_group;");
    };

    uint32_t aoff[2], boff[4];
    #pragma unroll
    for (int mi = 0; mi < 2; ++mi)
        aoff[mi] = (wm + mi * 16 + (lane & 15)) * QASTR + (lane >> 4) * 16;
    int tile = lane >> 3;
    #pragma unroll
    for (int ni = 0; ni < 4; ++ni)
        boff[ni] = QA_SZ + ((tile & 1) * 8 + (lane & 7)) * QBSTR
                 + (wn + ni * 16 + (tile >> 1) * 8) * 2;

    float acc[2][8][4];
    #pragma unroll
    for (int mi = 0; mi < 2; ++mi)
        #pragma unroll
        for (int nj = 0; nj < 8; ++nj)
            #pragma unroll
            for (int r = 0; r < 4; ++r) acc[mi][nj][r] = 0.f;

    const int niter = 8;
    prefetch(0); prefetch(1);

    for (int it = 0; it < niter; ++it) {
        if (it + 1 < niter) asm volatile("cp.async.wait_group 1;");
        else                asm volatile("cp.async.wait_group 0;");
        __syncthreads();
        if (it + 2 < niter) prefetch(it + 2);

        uint32_t Sb = S0 + (it % 3) * QSTG;
        #pragma unroll
        for (int kk = 0; kk < 2; ++kk) {
            uint32_t a[2][4];
            #pragma unroll
            for (int mi = 0; mi < 2; ++mi) {
                uint32_t addr = Sb + aoff[mi] + kk * 32;
                asm volatile("ldmatrix.sync.aligned.m8n8.x4.shared.b16 {%0,%1,%2,%3}, [%4];"
                    : "=r"(a[mi][0]), "=r"(a[mi][1]), "=r"(a[mi][2]), "=r"(a[mi][3]) : "r"(addr));
            }
            uint32_t bq[4][4];
            #pragma unroll
            for (int ni = 0; ni < 4; ++ni) {
                uint32_t addr = Sb + boff[ni] + kk * 16 * QBSTR;
                asm volatile("ldmatrix.sync.aligned.m8n8.x4.trans.shared.b16 {%0,%1,%2,%3}, [%4];"
                    : "=r"(bq[ni][0]), "=r"(bq[ni][1]), "=r"(bq[ni][2]), "=r"(bq[ni][3]) : "r"(addr));
            }
            #pragma unroll
            for (int mi = 0; mi < 2; ++mi)
                #pragma unroll
                for (int nj = 0; nj < 8; ++nj) {
                    uint32_t b0 = bq[nj >> 1][(nj & 1) * 2];
                    uint32_t b1 = bq[nj >> 1][(nj & 1) * 2 + 1];
                    asm volatile(
                        "mma.sync.aligned.m16n8k16.row.col.f32.bf16.bf16.f32 "
                        "{%0,%1,%2,%3}, {%4,%5,%6,%7}, {%8,%9}, {%0,%1,%2,%3};"
                        : "+f"(acc[mi][nj][0]), "+f"(acc[mi][nj][1]),
                          "+f"(acc[mi][nj][2]), "+f"(acc[mi][nj][3])
                        : "r"(a[mi][0]), "r"(a[mi][1]), "r"(a[mi][2]), "r"(a[mi][3]),
                          "r"(b0), "r"(b1));
                }
        }
    }

    int lr0 = wm + (lane >> 2);
    int cb = wn + (lane & 3) * 2;
    #pragma unroll
    for (int mi = 0; mi < 2; ++mi) {
        #pragma unroll
        for (int nj = 0; nj < 8; ++nj) {
            int rl = lr0 + mi * 16;
            int c = cb + nj * 8;
            float bx = bias[c], by = bias[c + 1];
            const float* rp0 = resid + (size_t)(m0 + rl) * 256 + c;
            const float* rp1 = resid + (size_t)(m0 + rl + 8) * 256 + c;
            acc[mi][nj][0] += bx + rp0[0];
            acc[mi][nj][1] += by + rp0[1];
            acc[mi][nj][2] += bx + rp1[0];
            acc[mi][nj][3] += by + rp1[1];
            float2 v0 = {acc[mi][nj][0], acc[mi][nj][1]};
            float2 v1 = {acc[mi][nj][2], acc[mi][nj][3]};
            *(float2*)(xres + (size_t)(m0 + rl) * 256 + c) = v0;
            *(float2*)(xres + (size_t)(m0 + rl + 8) * 256 + c) = v1;
        }
    }

    float ls[4], lq[4];
    #pragma unroll
    for (int i = 0; i < 4; ++i) { ls[i] = 0.f; lq[i] = 0.f; }
    #pragma unroll
    for (int mi = 0; mi < 2; ++mi) {
        #pragma unroll
        for (int nj = 0; nj < 8; ++nj) {
            float a0 = acc[mi][nj][0], a1 = acc[mi][nj][1];
            float a2 = acc[mi][nj][2], a3 = acc[mi][nj][3];
            ls[mi * 2]     += a0 + a1;  lq[mi * 2]     += a0 * a0 + a1 * a1;
            ls[mi * 2 + 1] += a2 + a3;  lq[mi * 2 + 1] += a2 * a2 + a3 * a3;
        }
    }
    #pragma unroll
    for (int o = 1; o <= 2; o <<= 1) {
        #pragma unroll
        for (int i = 0; i < 4; ++i) {
            ls[i] += __shfl_xor_sync(0xffffffffu, ls[i], o);
            lq[i] += __shfl_xor_sync(0xffffffffu, lq[i], o);
        }
    }
    __syncthreads();
    float* part = (float*)sm_;
    if ((lane & 3) == 0) {
        int rbase = wm + (lane >> 2);
        #pragma unroll
        for (int i = 0; i < 4; ++i) {
            int rl = rbase + (i >> 1) * 16 + (i & 1) * 8;
            part[(rl * 4 + wng) * 2 + 0] = ls[i];
            part[(rl * 4 + wng) * 2 + 1] = lq[i];
        }
    }
    __syncthreads();

    float mean[4], inv[4];
    #pragma unroll
    for (int i = 0; i < 4; ++i) {
        int rl = lr0 + (i >> 1) * 16 + (i & 1) * 8;
        float s = 0.f, q = 0.f;
        #pragma unroll
        for (int gIdx = 0; gIdx < 4; ++gIdx) {
            s += part[(rl * 4 + gIdx) * 2 + 0];
            q += part[(rl * 4 + gIdx) * 2 + 1];
        }
        float m = s * (1.0f / 256.0f);
        float var = q * (1.0f / 256.0f) - m * m;
        mean[i] = m;
        inv[i] = rsqrtf(var + 1e-5f);
    }

    #pragma unroll
    for (int mi = 0; mi < 2; ++mi) {
        #pragma unroll
        for (int nj = 0; nj < 8; ++nj) {
            int rl = lr0 + mi * 16;
            int c = cb + nj * 8;
            float gx = g2[c], gy = g2[c + 1];
            float bbx = b2g[c], bby = b2g[c + 1];
            int i0 = mi * 2, i1 = mi * 2 + 1;
            float o00 = (acc[mi][nj][0] - mean[i0]) * inv[i0] * gx + bbx;
            float o01 = (acc[mi][nj][1] - mean[i0]) * inv[i0] * gy + bby;
            float o10 = (acc[mi][nj][2] - mean[i1]) * inv[i1] * gx + bbx;
            float o11 = (acc[mi][nj][3] - mean[i1]) * inv[i1] * gy + bby;
            __nv_bfloat162 y0 = {__float2bfloat16(o00), __float2bfloat16(o01)};
            __nv_bfloat162 y1 = {__float2bfloat16(o10), __float2bfloat16(o11)};
            *(__nv_bfloat162*)(yb + (size_t)(m0 + rl) * 256 + c) = y0;
            *(__nv_bfloat162*)(yb + (size_t)(m0 + rl + 8) * 256 + c) = y1;
        }
    }
}

// ---------------- Deformable sampling: one warp = one token (8 heads) --------
// lane>>2 = head (0..7), lane&3 = channel octet (8 channels via 16B load)
__global__ void sample_kernel(const bf16* __restrict__ v, const float* __restrict__ offattn,
                              const float* __restrict__ rp, bf16* __restrict__ agg) {
    int tg = blockIdx.x * 8 + (threadIdx.x >> 5);    // token
    int lane = threadIdx.x & 31;
    int head = lane >> 2;                            // 0..7
    int l4 = lane & 3;                               // channel octet within head
    int bb = tg >> 13;
    int pos = tg & 8191;

    const float* lg = offattn + (size_t)tg * 256 + 144 + head * 9;
    float w[9];
    float mx = -1e30f;
    #pragma unroll
    for (int k = 0; k < 9; ++k) { w[k] = lg[k]; mx = fmaxf(mx, w[k]); }
    float sum = 0.f;
    #pragma unroll
    for (int k = 0; k < 9; ++k) { w[k] = expf(w[k] - mx); sum += w[k]; }
    float inv = 1.0f / sum;

    const float* rpp  = rp + (size_t)pos * 18;
    const float* offp = offattn + (size_t)tg * 256 + head * 18;
    // v viewed as float4 (8 bf16 channels): row stride = 256/8 = 32
    const float4* vp = (const float4*)v;
    int cho = head * 4 + l4;                         // octet index within row
    int base = bb << 13;
    float a0 = 0.f, a1 = 0.f, a2 = 0.f, a3 = 0.f;
    float a4 = 0.f, a5 = 0.f, a6 = 0.f, a7 = 0.f;
    #pragma unroll
    for (int k = 0; k < 9; ++k) {
        float cx = (rpp[k * 2 + 0] + offp[k * 2 + 0] + 1.0f) * 0.5f * 127.0f;
        float cy = (rpp[k * 2 + 1] + offp[k * 2 + 1] + 1.0f) * 0.5f * 63.0f;
        float fx = floorf(cx), fy = floorf(cy);
        float wx = cx - fx, wy = cy - fy;
        int x0 = min(max((int)fx, 0), 127);
        int x1 = min(max((int)fx + 1, 0), 127);
        int y0 = min(max((int)fy, 0), 63);
        int y1 = min(max((int)fy + 1, 0), 63);
        float4 q00 = vp[(size_t)(base + y0 * 128 + x0) * 32 + cho];
        float4 q01 = vp[(size_t)(base + y0 * 128 + x1) * 32 + cho];
        float4 q10 = vp[(size_t)(base + y1 * 128 + x0) * 32 + cho];
        float4 q11 = vp[(size_t)(base + y1 * 128 + x1) * 32 + cho];
        float w00 = (1.f - wy) * (1.f - wx), w01 = (1.f - wy) * wx;
        float w10 = wy * (1.f - wx),         w11 = wy * wx;
        float wk = w[k] * inv;
        #pragma unroll
        for (int q = 0; q < 4; ++q) {
            float c00 = ((const float*)&q00)[q];
            float c01 = ((const float*)&q01)[q];
            float c10 = ((const float*)&q10)[q];
            float c11 = ((const float*)&q11)[q];
            float2 v00 = __bfloat1622float2(*(__nv_bfloat162*)&c00);
            float2 v01 = __bfloat1622float2(*(__nv_bfloat162*)&c01);
            float2 v10 = __bfloat1622float2(*(__nv_bfloat162*)&c10);
            float2 v11 = __bfloat1622float2(*(__nv_bfloat162*)&c11);
            float sx = (v00.x * w00 + v01.x * w01 + v10.x * w10 + v11.x * w11) * wk;
            float sy = (v00.y * w00 + v01.y * w01 + v10.y * w10 + v11.y * w11) * wk;
            if (q == 0) { a0 += sx; a1 += sy; }
            else if (q == 1) { a2 += sx; a3 += sy; }
            else if (q == 2) { a4 += sx; a5 += sy; }
            else { a6 += sx; a7 += sy; }
        }
    }
    __nv_bfloat162 o0 = {__float2bfloat16(a0), __float2bfloat16(a1)};
    __nv_bfloat162 o1 = {__float2bfloat16(a2), __float2bfloat16(a3)};
    __nv_bfloat162 o2 = {__float2bfloat16(a4), __float2bfloat16(a5)};
    __nv_bfloat162 o3 = {__float2bfloat16(a6), __float2bfloat16(a7)};
    uint4 ov = {*(uint32_t*)&o0, *(uint32_t*)&o1, *(uint32_t*)&o2, *(uint32_t*)&o3};
    *(uint4*)(agg + (size_t)tg * 256 + cho * 8) = ov;
}

// ---------------- Depthwise 3x3 conv: sliding window, 4-way x-split ----------
__global__ void dwconv_kernel(const bf16* __restrict__ h, const float* __restrict__ wdw,
                              const float* __restrict__ bdw, bf16* __restrict__ o) {
    int c2 = blockIdx.x * 256 + threadIdx.x;
    int y = blockIdx.y & 63;
    int seg = blockIdx.y >> 6;
    int bb = blockIdx.z;
    int c = c2 * 2;
    int x0 = seg * 32;

    float w0[9], w1[9];
    #pragma unroll
    for (int i = 0; i < 9; ++i) { w0[i] = wdw[c * 9 + i]; w1[i] = wdw[(c + 1) * 9 + i]; }
    float bb0 = bdw[c], bb1 = bdw[c + 1];

    const __nv_bfloat162* hp = (const __nv_bfloat162*)h;
    size_t base = ((size_t)(bb << 13) + y * 128) * 512 + c2;
    bool hu = (y > 0), hd = (y < 63);
    __nv_bfloat162 zero = __float2bfloat162_rn(0.f);

    __nv_bfloat162 cm[3], cc[3], cn[3];
    {
        size_t p = base + ((x0 + 127) & 127) * 512;
        cm[0] = hu ? hp[p - 65536] : zero; cm[1] = hp[p]; cm[2] = hd ? hp[p + 65536] : zero;
        p = base + x0 * 512;
        cc[0] = hu ? hp[p - 65536] : zero; cc[1] = hp[p]; cc[2] = hd ? hp[p + 65536] : zero;
    }
    bf16* op = o + ((size_t)(bb << 13) + y * 128) * 1024 + c;

    for (int x = x0; x < x0 + 32; ++x) {
        size_t p = base + ((x + 1) & 127) * 512;
        cn[0] = hu ? hp[p - 65536] : zero; cn[1] = hp[p]; cn[2] = hd ? hp[p + 65536] : zero;

        float a0 = bb0, a1 = bb1;
        #pragma unroll
        for (int dy = 0; dy < 3; ++dy) {
            float2 vm = __bfloat1622float2(cm[dy]);
            float2 vc = __bfloat1622float2(cc[dy]);
            float2 vp = __bfloat1622float2(cn[dy]);
            a0 += vm.x * w0[dy * 3 + 0] + vc.x * w0[dy * 3 + 1] + vp.x * w0[dy * 3 + 2];
            a1 += vm.y * w1[dy * 3 + 0] + vc.y * w1[dy * 3 + 1] + vp.y * w1[dy * 3 + 2];
        }
        __nv_bfloat162 ov = {__float2bfloat16(gelu_f(a0)), __float2bfloat16(gelu_f(a1))};
        *(__nv_bfloat162*)(op + (size_t)x * 1024) = ov;

        #pragma unroll
        for (int i = 0; i < 3; ++i) { cm[i] = cc[i]; cc[i] = cn[i]; }
    }
}

// ---------------- launch ----------------
extern "C" void kernel_launch(void* const* d_in, const int* in_sizes, int n_in,
                              void* d_out, int out_size) {
    const float* x      = (const float*)d_in[0];
    const float* rp     = (const float*)d_in[1];
    const float* ln1_g  = (const float*)d_in[2];
    const float* ln1_b  = (const float*)d_in[3];
    const float* w_v    = (const float*)d_in[4];
    const float* b_v    = (const float*)d_in[5];
    const float* w_off  = (const float*)d_in[6];
    const float* b_off  = (const float*)d_in[7];
    const float* w_attn = (const float*)d_in[8];
    const float* b_attn = (const float*)d_in[9];
    const float* w_out  = (const float*)d_in[10];
    const float* b_out  = (const float*)d_in[11];
    const float* ln2_g  = (const float*)d_in[12];
    const float* ln2_b  = (const float*)d_in[13];
    const float* w1     = (const float*)d_in[14];
    const float* b1     = (const float*)d_in[15];
    const float* w_dw   = (const float*)d_in[16];
    const float* b_dw   = (const float*)d_in[17];
    const float* w2     = (const float*)d_in[18];
    const float* b2     = (const float*)d_in[19];
    float* out = (float*)d_out;

    float *xn, *offattn, *xres, *wcat, *bcat;
    bf16 *xnb, *vb, *aggb, *yb, *hb, *h2b, *wvb, *woutb, *w1b, *w2b;
    cudaGetSymbolAddress((void**)&xn,      g_xn);
    cudaGetSymbolAddress((void**)&offattn, g_offattn);
    cudaGetSymbolAddress((void**)&xres,    g_xres);
    cudaGetSymbolAddress((void**)&wcat,    g_wcat);
    cudaGetSymbolAddress((void**)&bcat,    g_bcat);
    cudaGetSymbolAddress((void**)&xnb,     g_xnb);
    cudaGetSymbolAddress((void**)&vb,      g_vb);
    cudaGetSymbolAddress((void**)&aggb,    g_aggb);
    cudaGetSymbolAddress((void**)&yb,      g_yb);
    cudaGetSymbolAddress((void**)&hb,      g_hb);
    cudaGetSymbolAddress((void**)&h2b,     g_h2b);
    cudaGetSymbolAddress((void**)&wvb,     g_wvb);
    cudaGetSymbolAddress((void**)&woutb,   g_woutb);
    cudaGetSymbolAddress((void**)&w1b,     g_w1b);
    cudaGetSymbolAddress((void**)&w2b,     g_w2b);

    cudaFuncSetAttribute(hgemm_kernel<1>, cudaFuncAttributeMaxDynamicSharedMemorySize, PSMEM);
    cudaFuncSetAttribute(hgemm_kernel<2>, cudaFuncAttributeMaxDynamicSharedMemorySize, PSMEM);
    cudaFuncSetAttribute(fused_k2,        cudaFuncAttributeMaxDynamicSharedMemorySize, H64_SMEM);
    cudaFuncSetAttribute(hgemm_wout_ln,   cudaFuncAttributeMaxDynamicSharedMemorySize, QSMEM);

    // K1: LN1 || weight prep
    prep_ln_kernel<<<NTOK + 2816, 256>>>(
        x, ln1_g, ln1_b, xn, xnb,
        w_v, w_out, w1, w2, w_off, w_attn, b_off, b_attn,
        wvb, woutb, w1b, w2b, wcat, bcat);
    // K2: v projection || offsets+attn (resource-matched 64x128 bodies)
    fused_k2<<<dim3(2, NTOK / 64, 2), 256, H64_SMEM>>>(
        xnb, wvb, b_v, vb, xn, wcat, bcat, offattn);
    // K3: softmax + bilinear sampling + aggregation (1 token/warp, 16B gathers)
    sample_kernel<<<NTOK / 8, 256>>>(vb, offattn, rp, aggb);
    // K4: output proj + residual + LN2 fused (register-resident LN)
    hgemm_wout_ln<<<NTOK / QBM, 256, QSMEM>>>(aggb, woutb, b_out, x, xres, ln2_g, ln2_b, yb);
    // K5: fc1 + GELU (bf16 TC, 128x128)
    hgemm_kernel<1><<<dim3(HID / PBN, NTOK / PBM), 256, PSMEM>>>(yb, w1b, b1, nullptr, hb, HID, 256);
    // K6: depthwise conv + GELU
    dwconv_kernel<<<dim3(2, 256, 2), 256>>>(hb, w_dw, b_dw, h2b);
    // K7: fc2 + residual -> out (f32, 128x128)
    hgemm_kernel<2><<<dim3(256 / PBN, NTOK / PBM), 256, PSMEM>>>(h2b, w2b, b2, xres, out, 256, 1024);
}

// round 17
// speedup vs baseline: 1.1807x; 1.0263x over previous
#include <cuda_runtime.h>
#include <cuda_bf16.h>
#include <math.h>
#include <stdint.h>

typedef __nv_bfloat16 bf16;

#define NTOK 16384
#define CDIM 256
#define HID  1024

// -------- scratch (__device__ globals; no allocations allowed) --------
__device__ float g_xn     [NTOK * CDIM];
__device__ float g_offattn[NTOK * 256];
__device__ float g_xres   [NTOK * CDIM];
__device__ bf16  g_xnb    [NTOK * CDIM];
__device__ bf16  g_vb     [NTOK * CDIM];
__device__ bf16  g_aggb   [NTOK * CDIM];
__device__ bf16  g_yb     [NTOK * CDIM];
__device__ bf16  g_hb     [NTOK * HID];
__device__ bf16  g_h2b    [NTOK * HID];
__device__ bf16  g_wvb    [256 * 256];
__device__ bf16  g_woutb  [256 * 256];
__device__ bf16  g_w1b    [256 * 1024];
__device__ bf16  g_w2b    [1024 * 256];
__device__ float g_wcat   [256 * 256];
__device__ float g_bcat   [256];

__device__ __forceinline__ float gelu_f(float v) {
    return 0.5f * v * (1.0f + erff(v * 0.7071067811865476f));
}

__device__ __forceinline__ uint32_t smem_u32(const void* p) {
    uint32_t a;
    asm("{ .reg .u64 t; cvta.to.shared.u64 t, %1; cvt.u32.u64 %0, t; }" : "=r"(a) : "l"(p));
    return a;
}

__device__ __forceinline__ uint32_t f2tf32(float f) {
    uint32_t r;
    asm("cvt.rna.tf32.f32 %0, %1;" : "=r"(r) : "f"(f));
    return r;
}

// ================= K1: fused prep + LN1 (block-range dispatch) =================
// LN1: 2 tokens per block, 128 threads/token, float2 per thread.
#define LN_BLOCKS (NTOK / 2)
__global__ void prep_ln_kernel(
    const float* __restrict__ x, const float* __restrict__ g, const float* __restrict__ b,
    float* __restrict__ xn, bf16* __restrict__ xnb,
    const float* wv, const float* wout, const float* w1, const float* w2,
    const float* w_off, const float* w_attn, const float* b_off, const float* b_attn,
    bf16* wvb, bf16* woutb, bf16* w1b, bf16* w2b, float* wcat, float* bcat) {
    if (blockIdx.x < LN_BLOCKS) {
        int tok = blockIdx.x * 2 + (threadIdx.x >> 7);
        int tid = threadIdx.x & 127;
        int warp = threadIdx.x >> 5;        // 0..7 (0-3 token A, 4-7 token B)
        int c = tid * 2;
        float2 v = *(const float2*)(x + (size_t)tok * CDIM + c);
        __shared__ float sh[8];
        float s = v.x + v.y;
        #pragma unroll
        for (int o = 16; o; o >>= 1) s += __shfl_xor_sync(0xffffffffu, s, o);
        if ((threadIdx.x & 31) == 0) sh[warp] = s;
        __syncthreads();
        int base = (threadIdx.x >> 7) * 4;
        float mean = (sh[base] + sh[base + 1] + sh[base + 2] + sh[base + 3]) * (1.0f / CDIM);
        __syncthreads();
        float dx = v.x - mean, dy = v.y - mean;
        float s2 = dx * dx + dy * dy;
        #pragma unroll
        for (int o = 16; o; o >>= 1) s2 += __shfl_xor_sync(0xffffffffu, s2, o);
        if ((threadIdx.x & 31) == 0) sh[warp] = s2;
        __syncthreads();
        float var = (sh[base] + sh[base + 1] + sh[base + 2] + sh[base + 3]) * (1.0f / CDIM);
        float rinv = rsqrtf(var + 1e-5f);
        float2 gg = *(const float2*)(g + c);
        float2 bb = *(const float2*)(b + c);
        float o0 = dx * rinv * gg.x + bb.x;
        float o1 = dy * rinv * gg.y + bb.y;
        float2 of = {__uint_as_float(f2tf32(o0)), __uint_as_float(f2tf32(o1))};
        *(float2*)(xn + (size_t)tok * CDIM + c) = of;
        __nv_bfloat162 ob = {__float2bfloat16(o0), __float2bfloat16(o1)};
        *(__nv_bfloat162*)(xnb + (size_t)tok * CDIM + c) = ob;
        return;
    }
    int i = (blockIdx.x - LN_BLOCKS) * 256 + threadIdx.x;
    if (i < 65536) { wvb[i] = __float2bfloat16(wv[i]); return; }
    i -= 65536;
    if (i < 65536) { woutb[i] = __float2bfloat16(wout[i]); return; }
    i -= 65536;
    if (i < 262144) { w1b[i] = __float2bfloat16(w1[i]); return; }
    i -= 262144;
    if (i < 262144) { w2b[i] = __float2bfloat16(w2[i]); return; }
    i -= 262144;
    if (i < 65536) {
        int k = i >> 8, col = i & 255;
        float v = (col < 144) ? w_off[k * 144 + col]
                : (col < 216) ? w_attn[k * 72 + (col - 144)] : 0.f;
        wcat[i] = __uint_as_float(f2tf32(v));
        if (k == 0)
            bcat[col] = (col < 144) ? b_off[col]
                      : (col < 216) ? b_attn[col - 144] : 0.f;
    }
}

// ---------------- shared GEMM geometry constants ----------------
#define PBK 32
#define PASTR 80
#define PBSTR 272
#define H64_A  (64 * PASTR)
#define H64_B  (PBK * PBSTR)
#define H64_STG (H64_A + H64_B)
#define H64_SMEM (3 * H64_STG)
#define TFA_STR 20
#define TFB_STR 136
#define TFA_SZ  (64 * TFA_STR * 4)
#define TFB_SZ  (16 * TFB_STR * 4)
#define TF_STG  (TFA_SZ + TFB_SZ)

// ---------------- tf32 GEMM device body: 64x128x16, 3-stage ------------------
__device__ void tgemm64_dev(char* sm_, int bx, int by,
                            const float* __restrict__ A, const float* __restrict__ Bw,
                            const float* __restrict__ bias, float* __restrict__ C) {
    uint32_t S0 = smem_u32(sm_);
    int t = threadIdx.x;
    int lane = t & 31, warp = t >> 5;
    int wm = (warp & 1) * 32;
    int wn = (warp >> 1) * 32;
    int m0 = by * 64;
    int n0 = bx * 128;

    int a_row = t >> 2, a_c4 = (t & 3) * 4;
    const float* Ag = A + (size_t)(m0 + a_row) * 256 + a_c4;
    uint32_t a_s = S0 + (a_row * TFA_STR + a_c4) * 4;

    auto prefetch = [&](int it) {
        int st = it % 3;
        asm volatile("cp.async.cg.shared.global [%0], [%1], 16;"
                     :: "r"(a_s + st * TF_STG), "l"(Ag + it * 16));
        #pragma unroll
        for (int i = 0; i < 2; ++i) {
            int idx = t + i * 256;
            int row = idx >> 5, c4 = (idx & 31) * 4;
            const float* bg = Bw + (size_t)(it * 16 + row) * 256 + n0 + c4;
            uint32_t dst = S0 + TFA_SZ + (row * TFB_STR + c4) * 4 + st * TF_STG;
            asm volatile("cp.async.cg.shared.global [%0], [%1], 16;" :: "r"(dst), "l"(bg));
        }
        asm volatile("cp.async.commit_group;");
    };

    float acc[2][4][4];
    #pragma unroll
    for (int mi = 0; mi < 2; ++mi)
        #pragma unroll
        for (int nj = 0; nj < 4; ++nj)
            #pragma unroll
            for (int r = 0; r < 4; ++r) acc[mi][nj][r] = 0.f;

    const int niter = 16;
    prefetch(0); prefetch(1);

    int lr = lane >> 2, lc = lane & 3;
    for (int it = 0; it < niter; ++it) {
        if (it + 1 < niter) asm volatile("cp.async.wait_group 1;");
        else                asm volatile("cp.async.wait_group 0;");
        __syncthreads();
        if (it + 2 < niter) prefetch(it + 2);

        const uint32_t* As = (const uint32_t*)(sm_ + (it % 3) * TF_STG);
        const uint32_t* Bs = (const uint32_t*)(sm_ + (it % 3) * TF_STG + TFA_SZ);

        #pragma unroll
        for (int kk = 0; kk < 2; ++kk) {
            uint32_t af[2][4];
            #pragma unroll
            for (int mi = 0; mi < 2; ++mi) {
                int rb = wm + mi * 16 + lr;
                af[mi][0] = As[rb * TFA_STR + kk * 8 + lc];
                af[mi][1] = As[(rb + 8) * TFA_STR + kk * 8 + lc];
                af[mi][2] = As[rb * TFA_STR + kk * 8 + lc + 4];
                af[mi][3] = As[(rb + 8) * TFA_STR + kk * 8 + lc + 4];
            }
            #pragma unroll
            for (int nj = 0; nj < 4; ++nj) {
                uint32_t b0 = Bs[(kk * 8 + lc) * TFB_STR + wn + nj * 8 + lr];
                uint32_t b1 = Bs[(kk * 8 + lc + 4) * TFB_STR + wn + nj * 8 + lr];
                #pragma unroll
                for (int mi = 0; mi < 2; ++mi)
                    asm volatile(
                        "mma.sync.aligned.m16n8k8.row.col.f32.tf32.tf32.f32 "
                        "{%0,%1,%2,%3}, {%4,%5,%6,%7}, {%8,%9}, {%0,%1,%2,%3};"
                        : "+f"(acc[mi][nj][0]), "+f"(acc[mi][nj][1]),
                          "+f"(acc[mi][nj][2]), "+f"(acc[mi][nj][3])
                        : "r"(af[mi][0]), "r"(af[mi][1]), "r"(af[mi][2]), "r"(af[mi][3]),
                          "r"(b0), "r"(b1));
            }
        }
    }

    #pragma unroll
    for (int mi = 0; mi < 2; ++mi) {
        #pragma unroll
        for (int nj = 0; nj < 4; ++nj) {
            int r = m0 + wm + mi * 16 + lr;
            int c = n0 + wn + nj * 8 + lc * 2;
            float bx2 = bias[c], by2 = bias[c + 1];
            float2 v0 = {acc[mi][nj][0] + bx2, acc[mi][nj][1] + by2};
            float2 v1 = {acc[mi][nj][2] + bx2, acc[mi][nj][3] + by2};
            *(float2*)(C + (size_t)r * 256 + c) = v0;
            *(float2*)(C + (size_t)(r + 8) * 256 + c) = v1;
        }
    }
}

// ---------------- bf16 GEMM device body: 64x128x32, 3-stage ------------------
template<int EPI>
__device__ void hgemm64_dev(char* sm_, int bx, int by,
                            const bf16* __restrict__ A, const bf16* __restrict__ B,
                            const float* __restrict__ bias, const float* __restrict__ resid,
                            void* __restrict__ Cp, int N, int K) {
    uint32_t S0 = smem_u32(sm_);
    int t = threadIdx.x;
    int lane = t & 31, warp = t >> 5;
    int wm = (warp & 1) * 32;
    int wn = (warp >> 1) * 32;
    int m0 = by * 64;
    int n0 = bx * 128;

    int a_row = t >> 2, a_c16 = t & 3;
    const bf16* Ag = A + (size_t)(m0 + a_row) * K + a_c16 * 8;
    uint32_t a_s = S0 + a_row * PASTR + a_c16 * 16;
    int b_row = t >> 3;
    int b_c16 = (t & 7) * 2;
    const bf16* Bg = B + (size_t)b_row * N + n0 + b_c16 * 8;
    uint32_t b_s = S0 + H64_A + b_row * PBSTR + b_c16 * 16;

    auto prefetch = [&](int chunk) {
        int st = chunk % 3;
        const bf16* bg = Bg + (size_t)chunk * PBK * N;
        asm volatile("cp.async.cg.shared.global [%0], [%1], 16;"
                     :: "r"(a_s + st * H64_STG), "l"(Ag + chunk * PBK));
        asm volatile("cp.async.cg.shared.global [%0], [%1], 16;" :: "r"(b_s + st * H64_STG), "l"(bg));
        asm volatile("cp.async.cg.shared.global [%0], [%1], 16;" :: "r"(b_s + st * H64_STG + 16), "l"(bg + 8));
        asm volatile("cp.async.commit_group;");
    };

    uint32_t aoff[2], boff[2];
    #pragma unroll
    for (int mi = 0; mi < 2; ++mi)
        aoff[mi] = (wm + mi * 16 + (lane & 15)) * PASTR + (lane >> 4) * 16;
    int tile = lane >> 3;
    #pragma unroll
    for (int ni = 0; ni < 2; ++ni)
        boff[ni] = H64_A + ((tile & 1) * 8 + (lane & 7)) * PBSTR
                 + (wn + ni * 16 + (tile >> 1) * 8) * 2;

    float acc[2][4][4];
    #pragma unroll
    for (int mi = 0; mi < 2; ++mi)
        #pragma unroll
        for (int nj = 0; nj < 4; ++nj)
            #pragma unroll
            for (int r = 0; r < 4; ++r) acc[mi][nj][r] = 0.f;

    int niter = K / PBK;
    prefetch(0); prefetch(1);

    for (int it = 0; it < niter; ++it) {
        if (it + 1 < niter) asm volatile("cp.async.wait_group 1;");
        else                asm volatile("cp.async.wait_group 0;");
        __syncthreads();
        if (it + 2 < niter) prefetch(it + 2);

        uint32_t Sb = S0 + (it % 3) * H64_STG;
        #pragma unroll
        for (int kk = 0; kk < 2; ++kk) {
            uint32_t a[2][4];
            #pragma unroll
            for (int mi = 0; mi < 2; ++mi) {
                uint32_t addr = Sb + aoff[mi] + kk * 32;
                asm volatile("ldmatrix.sync.aligned.m8n8.x4.shared.b16 {%0,%1,%2,%3}, [%4];"
                    : "=r"(a[mi][0]), "=r"(a[mi][1]), "=r"(a[mi][2]), "=r"(a[mi][3]) : "r"(addr));
            }
            uint32_t bq[2][4];
            #pragma unroll
            for (int ni = 0; ni < 2; ++ni) {
                uint32_t addr = Sb + boff[ni] + kk * 16 * PBSTR;
                asm volatile("ldmatrix.sync.aligned.m8n8.x4.trans.shared.b16 {%0,%1,%2,%3}, [%4];"
                    : "=r"(bq[ni][0]), "=r"(bq[ni][1]), "=r"(bq[ni][2]), "=r"(bq[ni][3]) : "r"(addr));
            }
            #pragma unroll
            for (int mi = 0; mi < 2; ++mi)
                #pragma unroll
                for (int nj = 0; nj < 4; ++nj) {
                    uint32_t b0 = bq[nj >> 1][(nj & 1) * 2];
                    uint32_t b1 = bq[nj >> 1][(nj & 1) * 2 + 1];
                    asm volatile(
                        "mma.sync.aligned.m16n8k16.row.col.f32.bf16.bf16.f32 "
                        "{%0,%1,%2,%3}, {%4,%5,%6,%7}, {%8,%9}, {%0,%1,%2,%3};"
                        : "+f"(acc[mi][nj][0]), "+f"(acc[mi][nj][1]),
                          "+f"(acc[mi][nj][2]), "+f"(acc[mi][nj][3])
                        : "r"(a[mi][0]), "r"(a[mi][1]), "r"(a[mi][2]), "r"(a[mi][3]),
                          "r"(b0), "r"(b1));
                }
        }
    }

    int r_base = m0 + wm + (lane >> 2);
    int c_base = n0 + wn + (lane & 3) * 2;
    #pragma unroll
    for (int mi = 0; mi < 2; ++mi) {
        #pragma unroll
        for (int nj = 0; nj < 4; ++nj) {
            int r = r_base + mi * 16;
            int c = c_base + nj * 8;
            float bx2 = bias[c], by2 = bias[c + 1];
            float o00 = acc[mi][nj][0] + bx2;
            float o01 = acc[mi][nj][1] + by2;
            float o10 = acc[mi][nj][2] + bx2;
            float o11 = acc[mi][nj][3] + by2;
            if (EPI == 2) {
                const float* rp0 = resid + (size_t)r * N + c;
                const float* rp1 = resid + (size_t)(r + 8) * N + c;
                float* Cf = (float*)Cp;
                float2 v0 = {o00 + rp0[0], o01 + rp0[1]};
                float2 v1 = {o10 + rp1[0], o11 + rp1[1]};
                *(float2*)(Cf + (size_t)r * N + c) = v0;
                *(float2*)(Cf + (size_t)(r + 8) * N + c) = v1;
            } else {
                bf16* Cb = (bf16*)Cp;
                __nv_bfloat162 v0 = {__float2bfloat16(o00), __float2bfloat16(o01)};
                __nv_bfloat162 v1 = {__float2bfloat16(o10), __float2bfloat16(o11)};
                *(__nv_bfloat162*)(Cb + (size_t)r * N + c) = v0;
                *(__nv_bfloat162*)(Cb + (size_t)(r + 8) * N + c) = v1;
            }
        }
    }
}

// ========== K2: fused v-proj (bf16, 64x128) || off/attn (tf32, 64x128) =======
__global__ __launch_bounds__(256)
void fused_k2(const bf16* __restrict__ xnb, const bf16* __restrict__ wvb,
              const float* __restrict__ b_v, bf16* __restrict__ vb,
              const float* __restrict__ xn, const float* __restrict__ wcat,
              const float* __restrict__ bcat, float* __restrict__ offattn) {
    extern __shared__ char sm_[];
    if (blockIdx.z == 0)
        hgemm64_dev<0>(sm_, blockIdx.x, blockIdx.y, xnb, wvb, b_v, nullptr, vb, 256, 256);
    else
        tgemm64_dev(sm_, blockIdx.x, blockIdx.y, xn, wcat, bcat, offattn);
}

// ---------------- bf16 GEMM 128x128x32 (fc1, fc2), 3-stage -------------------
#define PBM 128
#define PBN 128
#define PA_ST (PBM * PASTR)
#define PB_ST (PBK * PBSTR)
#define PSTG  (PA_ST + PB_ST)
#define PSMEM (3 * PSTG)

template<int EPI>
__global__ __launch_bounds__(256)
void hgemm_kernel(const bf16* __restrict__ A, const bf16* __restrict__ B,
                  const float* __restrict__ bias, const float* __restrict__ resid,
                  void* __restrict__ Cp, int N, int K) {
    extern __shared__ char sm_[];
    uint32_t S0 = smem_u32(sm_);

    int t = threadIdx.x;
    int lane = t & 31, warp = t >> 5;
    int wm = (warp & 3) * 32;
    int wn = (warp >> 2) * 64;
    int m0 = blockIdx.y * PBM;
    int n0 = blockIdx.x * PBN;

    int a_row = t >> 1;
    int a_c16 = (t & 1) * 2;
    const bf16* Ag = A + (size_t)(m0 + a_row) * K + a_c16 * 8;
    uint32_t a_s = S0 + a_row * PASTR + a_c16 * 16;
    int b_row = t >> 3;
    int b_c16 = (t & 7) * 2;
    const bf16* Bg = B + (size_t)b_row * N + n0 + b_c16 * 8;
    uint32_t b_s = S0 + PA_ST + b_row * PBSTR + b_c16 * 16;

    auto prefetch = [&](int chunk) {
        int st = chunk % 3;
        const bf16* ag = Ag + chunk * PBK;
        const bf16* bg = Bg + (size_t)chunk * PBK * N;
        uint32_t sa = a_s + st * PSTG;
        uint32_t sb = b_s + st * PSTG;
        asm volatile("cp.async.cg.shared.global [%0], [%1], 16;" :: "r"(sa), "l"(ag));
        asm volatile("cp.async.cg.shared.global [%0], [%1], 16;" :: "r"(sa + 16), "l"(ag + 8));
        asm volatile("cp.async.cg.shared.global [%0], [%1], 16;" :: "r"(sb), "l"(bg));
        asm volatile("cp.async.cg.shared.global [%0], [%1], 16;" :: "r"(sb + 16), "l"(bg + 8));
        asm volatile("cp.async.commit_group;");
    };

    uint32_t aoff[2], boff[4];
    #pragma unroll
    for (int mi = 0; mi < 2; ++mi)
        aoff[mi] = (wm + mi * 16 + (lane & 15)) * PASTR + (lane >> 4) * 16;
    int tile = lane >> 3;
    #pragma unroll
    for (int ni = 0; ni < 4; ++ni)
        boff[ni] = PA_ST + ((tile & 1) * 8 + (lane & 7)) * PBSTR
                 + (wn + ni * 16 + (tile >> 1) * 8) * 2;

    float acc[2][8][4];
    #pragma unroll
    for (int mi = 0; mi < 2; ++mi)
        #pragma unroll
        for (int nj = 0; nj < 8; ++nj)
            #pragma unroll
            for (int r = 0; r < 4; ++r) acc[mi][nj][r] = 0.f;

    int niter = K / PBK;
    prefetch(0);
    prefetch(1);

    for (int it = 0; it < niter; ++it) {
        if (it + 1 < niter) asm volatile("cp.async.wait_group 1;");
        else                asm volatile("cp.async.wait_group 0;");
        __syncthreads();
        if (it + 2 < niter) prefetch(it + 2);

        uint32_t Sb = S0 + (it % 3) * PSTG;
        #pragma unroll
        for (int kk = 0; kk < 2; ++kk) {
            uint32_t a[2][4];
            #pragma unroll
            for (int mi = 0; mi < 2; ++mi) {
                uint32_t addr = Sb + aoff[mi] + kk * 32;
                asm volatile("ldmatrix.sync.aligned.m8n8.x4.shared.b16 {%0,%1,%2,%3}, [%4];"
                    : "=r"(a[mi][0]), "=r"(a[mi][1]), "=r"(a[mi][2]), "=r"(a[mi][3]) : "r"(addr));
            }
            uint32_t bq[4][4];
            #pragma unroll
            for (int ni = 0; ni < 4; ++ni) {
                uint32_t addr = Sb + boff[ni] + kk * 16 * PBSTR;
                asm volatile("ldmatrix.sync.aligned.m8n8.x4.trans.shared.b16 {%0,%1,%2,%3}, [%4];"
                    : "=r"(bq[ni][0]), "=r"(bq[ni][1]), "=r"(bq[ni][2]), "=r"(bq[ni][3]) : "r"(addr));
            }
            #pragma unroll
            for (int mi = 0; mi < 2; ++mi)
                #pragma unroll
                for (int nj = 0; nj < 8; ++nj) {
                    uint32_t b0 = bq[nj >> 1][(nj & 1) * 2];
                    uint32_t b1 = bq[nj >> 1][(nj & 1) * 2 + 1];
                    asm volatile(
                        "mma.sync.aligned.m16n8k16.row.col.f32.bf16.bf16.f32 "
                        "{%0,%1,%2,%3}, {%4,%5,%6,%7}, {%8,%9}, {%0,%1,%2,%3};"
                        : "+f"(acc[mi][nj][0]), "+f"(acc[mi][nj][1]),
                          "+f"(acc[mi][nj][2]), "+f"(acc[mi][nj][3])
                        : "r"(a[mi][0]), "r"(a[mi][1]), "r"(a[mi][2]), "r"(a[mi][3]),
                          "r"(b0), "r"(b1));
                }
        }
    }

    int r_base = m0 + wm + (lane >> 2);
    int c_base = n0 + wn + (lane & 3) * 2;
    #pragma unroll
    for (int mi = 0; mi < 2; ++mi) {
        #pragma unroll
        for (int nj = 0; nj < 8; ++nj) {
            int r = r_base + mi * 16;
            int c = c_base + nj * 8;
            float bx = bias[c], by = bias[c + 1];
            float o00 = acc[mi][nj][0] + bx;
            float o01 = acc[mi][nj][1] + by;
            float o10 = acc[mi][nj][2] + bx;
            float o11 = acc[mi][nj][3] + by;
            if (EPI == 1) {
                o00 = gelu_f(o00); o01 = gelu_f(o01);
                o10 = gelu_f(o10); o11 = gelu_f(o11);
            }
            if (EPI == 2) {
                const float* rp0 = resid + (size_t)r * N + c;
                const float* rp1 = resid + (size_t)(r + 8) * N + c;
                float* Cf = (float*)Cp;
                float2 v0 = {o00 + rp0[0], o01 + rp0[1]};
                float2 v1 = {o10 + rp1[0], o11 + rp1[1]};
                *(float2*)(Cf + (size_t)r * N + c) = v0;
                *(float2*)(Cf + (size_t)(r + 8) * N + c) = v1;
            } else {
                bf16* Cb = (bf16*)Cp;
                __nv_bfloat162 v0 = {__float2bfloat16(o00), __float2bfloat16(o01)};
                __nv_bfloat162 v1 = {__float2bfloat16(o10), __float2bfloat16(o11)};
                *(__nv_bfloat162*)(Cb + (size_t)r * N + c) = v0;
                *(__nv_bfloat162*)(Cb + (size_t)(r + 8) * N + c) = v1;
            }
        }
    }
}

// ======== fused wout GEMM + residual + LN2: register-resident LN epilogue ====
#define QBM 64
#define QASTR 80
#define QBSTR 528
#define QA_SZ (QBM * QASTR)
#define QB_SZ (32 * QBSTR)
#define QSTG  (QA_SZ + QB_SZ)
#define QSMEM (3 * QSTG)

__global__ __launch_bounds__(256, 2)
void hgemm_wout_ln(const bf16* __restrict__ A, const bf16* __restrict__ B,
                   const float* __restrict__ bias, const float* __restrict__ resid,
                   float* __restrict__ xres, const float* __restrict__ g2,
                   const float* __restrict__ b2g, bf16* __restrict__ yb) {
    extern __shared__ char sm_[];
    uint32_t S0 = smem_u32(sm_);
    int t = threadIdx.x;
    int lane = t & 31, warp = t >> 5;
    int wm = (warp & 1) * 32;
    int wn = (warp >> 1) * 64;
    int wng = warp >> 1;
    int m0 = blockIdx.x * QBM;

    int a_row = t >> 2, a_c16 = t & 3;
    const bf16* Ag = A + (size_t)(m0 + a_row) * 256 + a_c16 * 8;
    uint32_t a_s = S0 + a_row * QASTR + a_c16 * 16;

    auto prefetch = [&](int ck) {
        int st = ck % 3;
        asm volatile("cp.async.cg.shared.global [%0], [%1], 16;"
                     :: "r"(a_s + st * QSTG), "l"(Ag + ck * 32));
        #pragma unroll
        for (int i = 0; i < 4; ++i) {
            int idx = t + i * 256;
            int row = idx >> 5, c16 = idx & 31;
            const bf16* bg = B + (size_t)(ck * 32 + row) * 256 + c16 * 8;
            uint32_t dst = S0 + st * QSTG + QA_SZ + row * QBSTR + c16 * 16;
            asm volatile("cp.async.cg.shared.global [%0], [%1], 16;" :: "r"(dst), "l"(bg));
        }
        asm volatile("cp.async.commit_group;");
    };

    uint32_t aoff[2], boff[4];
    #pragma unroll
    for (int mi = 0; mi < 2; ++mi)
        aoff[mi] = (wm + mi * 16 + (lane & 15)) * QASTR + (lane >> 4) * 16;
    int tile = lane >> 3;
    #pragma unroll
    for (int ni = 0; ni < 4; ++ni)
        boff[ni] = QA_SZ + ((tile & 1) * 8 + (lane & 7)) * QBSTR
                 + (wn + ni * 16 + (tile >> 1) * 8) * 2;

    float acc[2][8][4];
    #pragma unroll
    for (int mi = 0; mi < 2; ++mi)
        #pragma unroll
        for (int nj = 0; nj < 8; ++nj)
            #pragma unroll
            for (int r = 0; r < 4; ++r) acc[mi][nj][r] = 0.f;

    const int niter = 8;
    prefetch(0); prefetch(1);

    for (int it = 0; it < niter; ++it) {
        if (it + 1 < niter) asm volatile("cp.async.wait_group 1;");
        else                asm volatile("cp.async.wait_group 0;");
        __syncthreads();
        if (it + 2 < niter) prefetch(it + 2);

        uint32_t Sb = S0 + (it % 3) * QSTG;
        #pragma unroll
        for (int kk = 0; kk < 2; ++kk) {
            uint32_t a[2][4];
            #pragma unroll
            for (int mi = 0; mi < 2; ++mi) {
                uint32_t addr = Sb + aoff[mi] + kk * 32;
                asm volatile("ldmatrix.sync.aligned.m8n8.x4.shared.b16 {%0,%1,%2,%3}, [%4];"
                    : "=r"(a[mi][0]), "=r"(a[mi][1]), "=r"(a[mi][2]), "=r"(a[mi][3]) : "r"(addr));
            }
            uint32_t bq[4][4];
            #pragma unroll
            for (int ni = 0; ni < 4; ++ni) {
                uint32_t addr = Sb + boff[ni] + kk * 16 * QBSTR;
                asm volatile("ldmatrix.sync.aligned.m8n8.x4.trans.shared.b16 {%0,%1,%2,%3}, [%4];"
                    : "=r"(bq[ni][0]), "=r"(bq[ni][1]), "=r"(bq[ni][2]), "=r"(bq[ni][3]) : "r"(addr));
            }
            #pragma unroll
            for (int mi = 0; mi < 2; ++mi)
                #pragma unroll
                for (int nj = 0; nj < 8; ++nj) {
                    uint32_t b0 = bq[nj >> 1][(nj & 1) * 2];
                    uint32_t b1 = bq[nj >> 1][(nj & 1) * 2 + 1];
                    asm volatile(
                        "mma.sync.aligned.m16n8k16.row.col.f32.bf16.bf16.f32 "
                        "{%0,%1,%2,%3}, {%4,%5,%6,%7}, {%8,%9}, {%0,%1,%2,%3};"
                        : "+f"(acc[mi][nj][0]), "+f"(acc[mi][nj][1]),
                          "+f"(acc[mi][nj][2]), "+f"(acc[mi][nj][3])
                        : "r"(a[mi][0]), "r"(a[mi][1]), "r"(a[mi][2]), "r"(a[mi][3]),
                          "r"(b0), "r"(b1));
                }
        }
    }

    int lr0 = wm + (lane >> 2);
    int cb = wn + (lane & 3) * 2;
    #pragma unroll
    for (int mi = 0; mi < 2; ++mi) {
        #pragma unroll
        for (int nj = 0; nj < 8; ++nj) {
            int rl = lr0 + mi * 16;
            int c = cb + nj * 8;
            float bx = bias[c], by = bias[c + 1];
            const float* rp0 = resid + (size_t)(m0 + rl) * 256 + c;
            const float* rp1 = resid + (size_t)(m0 + rl + 8) * 256 + c;
            acc[mi][nj][0] += bx + rp0[0];
            acc[mi][nj][1] += by + rp0[1];
            acc[mi][nj][2] += bx + rp1[0];
            acc[mi][nj][3] += by + rp1[1];
            float2 v0 = {acc[mi][nj][0], acc[mi][nj][1]};
            float2 v1 = {acc[mi][nj][2], acc[mi][nj][3]};
            *(float2*)(xres + (size_t)(m0 + rl) * 256 + c) = v0;
            *(float2*)(xres + (size_t)(m0 + rl + 8) * 256 + c) = v1;
        }
    }

    float ls[4], lq[4];
    #pragma unroll
    for (int i = 0; i < 4; ++i) { ls[i] = 0.f; lq[i] = 0.f; }
    #pragma unroll
    for (int mi = 0; mi < 2; ++mi) {
        #pragma unroll
        for (int nj = 0; nj < 8; ++nj) {
            float a0 = acc[mi][nj][0], a1 = acc[mi][nj][1];
            float a2 = acc[mi][nj][2], a3 = acc[mi][nj][3];
            ls[mi * 2]     += a0 + a1;  lq[mi * 2]     += a0 * a0 + a1 * a1;
            ls[mi * 2 + 1] += a2 + a3;  lq[mi * 2 + 1] += a2 * a2 + a3 * a3;
        }
    }
    #pragma unroll
    for (int o = 1; o <= 2; o <<= 1) {
        #pragma unroll
        for (int i = 0; i < 4; ++i) {
            ls[i] += __shfl_xor_sync(0xffffffffu, ls[i], o);
            lq[i] += __shfl_xor_sync(0xffffffffu, lq[i], o);
        }
    }
    __syncthreads();
    float* part = (float*)sm_;
    if ((lane & 3) == 0) {
        int rbase = wm + (lane >> 2);
        #pragma unroll
        for (int i = 0; i < 4; ++i) {
            int rl = rbase + (i >> 1) * 16 + (i & 1) * 8;
            part[(rl * 4 + wng) * 2 + 0] = ls[i];
            part[(rl * 4 + wng) * 2 + 1] = lq[i];
        }
    }
    __syncthreads();

    float mean[4], inv[4];
    #pragma unroll
    for (int i = 0; i < 4; ++i) {
        int rl = lr0 + (i >> 1) * 16 + (i & 1) * 8;
        float s = 0.f, q = 0.f;
        #pragma unroll
        for (int gIdx = 0; gIdx < 4; ++gIdx) {
            s += part[(rl * 4 + gIdx) * 2 + 0];
            q += part[(rl * 4 + gIdx) * 2 + 1];
        }
        float m = s * (1.0f / 256.0f);
        float var = q * (1.0f / 256.0f) - m * m;
        mean[i] = m;
        inv[i] = rsqrtf(var + 1e-5f);
    }

    #pragma unroll
    for (int mi = 0; mi < 2; ++mi) {
        #pragma unroll
        for (int nj = 0; nj < 8; ++nj) {
            int rl = lr0 + mi * 16;
            int c = cb + nj * 8;
            float gx = g2[c], gy = g2[c + 1];
            float bbx = b2g[c], bby = b2g[c + 1];
            int i0 = mi * 2, i1 = mi * 2 + 1;
            float o00 = (acc[mi][nj][0] - mean[i0]) * inv[i0] * gx + bbx;
            float o01 = (acc[mi][nj][1] - mean[i0]) * inv[i0] * gy + bby;
            float o10 = (acc[mi][nj][2] - mean[i1]) * inv[i1] * gx + bbx;
            float o11 = (acc[mi][nj][3] - mean[i1]) * inv[i1] * gy + bby;
            __nv_bfloat162 y0 = {__float2bfloat16(o00), __float2bfloat16(o01)};
            __nv_bfloat162 y1 = {__float2bfloat16(o10), __float2bfloat16(o11)};
            *(__nv_bfloat162*)(yb + (size_t)(m0 + rl) * 256 + c) = y0;
            *(__nv_bfloat162*)(yb + (size_t)(m0 + rl + 8) * 256 + c) = y1;
        }
    }
}

// ---------------- Deformable sampling: one warp = one token (8 heads) --------
__global__ void sample_kernel(const bf16* __restrict__ v, const float* __restrict__ offattn,
                              const float* __restrict__ rp, bf16* __restrict__ agg) {
    int tg = blockIdx.x * 8 + (threadIdx.x >> 5);
    int lane = threadIdx.x & 31;
    int head = lane >> 2;
    int l4 = lane & 3;
    int bb = tg >> 13;
    int pos = tg & 8191;

    const float* lg = offattn + (size_t)tg * 256 + 144 + head * 9;
    float w[9];
    float mx = -1e30f;
    #pragma unroll
    for (int k = 0; k < 9; ++k) { w[k] = lg[k]; mx = fmaxf(mx, w[k]); }
    float sum = 0.f;
    #pragma unroll
    for (int k = 0; k < 9; ++k) { w[k] = expf(w[k] - mx); sum += w[k]; }
    float inv = 1.0f / sum;

    const float* rpp  = rp + (size_t)pos * 18;
    const float* offp = offattn + (size_t)tg * 256 + head * 18;
    const float4* vp = (const float4*)v;
    int cho = head * 4 + l4;
    int base = bb << 13;
    float a0 = 0.f, a1 = 0.f, a2 = 0.f, a3 = 0.f;
    float a4 = 0.f, a5 = 0.f, a6 = 0.f, a7 = 0.f;
    #pragma unroll
    for (int k = 0; k < 9; ++k) {
        float cx = (rpp[k * 2 + 0] + offp[k * 2 + 0] + 1.0f) * 0.5f * 127.0f;
        float cy = (rpp[k * 2 + 1] + offp[k * 2 + 1] + 1.0f) * 0.5f * 63.0f;
        float fx = floorf(cx), fy = floorf(cy);
        float wx = cx - fx, wy = cy - fy;
        int x0 = min(max((int)fx, 0), 127);
        int x1 = min(max((int)fx + 1, 0), 127);
        int y0 = min(max((int)fy, 0), 63);
        int y1 = min(max((int)fy + 1, 0), 63);
        float4 q00 = vp[(size_t)(base + y0 * 128 + x0) * 32 + cho];
        float4 q01 = vp[(size_t)(base + y0 * 128 + x1) * 32 + cho];
        float4 q10 = vp[(size_t)(base + y1 * 128 + x0) * 32 + cho];
        float4 q11 = vp[(size_t)(base + y1 * 128 + x1) * 32 + cho];
        float w00 = (1.f - wy) * (1.f - wx), w01 = (1.f - wy) * wx;
        float w10 = wy * (1.f - wx),         w11 = wy * wx;
        float wk = w[k] * inv;
        #pragma unroll
        for (int q = 0; q < 4; ++q) {
            float c00 = ((const float*)&q00)[q];
            float c01 = ((const float*)&q01)[q];
            float c10 = ((const float*)&q10)[q];
            float c11 = ((const float*)&q11)[q];
            float2 v00 = __bfloat1622float2(*(__nv_bfloat162*)&c00);
            float2 v01 = __bfloat1622float2(*(__nv_bfloat162*)&c01);
            float2 v10 = __bfloat1622float2(*(__nv_bfloat162*)&c10);
            float2 v11 = __bfloat1622float2(*(__nv_bfloat162*)&c11);
            float sx = (v00.x * w00 + v01.x * w01 + v10.x * w10 + v11.x * w11) * wk;
            float sy = (v00.y * w00 + v01.y * w01 + v10.y * w10 + v11.y * w11) * wk;
            if (q == 0) { a0 += sx; a1 += sy; }
            else if (q == 1) { a2 += sx; a3 += sy; }
            else if (q == 2) { a4 += sx; a5 += sy; }
            else { a6 += sx; a7 += sy; }
        }
    }
    __nv_bfloat162 o0 = {__float2bfloat16(a0), __float2bfloat16(a1)};
    __nv_bfloat162 o1 = {__float2bfloat16(a2), __float2bfloat16(a3)};
    __nv_bfloat162 o2 = {__float2bfloat16(a4), __float2bfloat16(a5)};
    __nv_bfloat162 o3 = {__float2bfloat16(a6), __float2bfloat16(a7)};
    uint4 ov = {*(uint32_t*)&o0, *(uint32_t*)&o1, *(uint32_t*)&o2, *(uint32_t*)&o3};
    *(uint4*)(agg + (size_t)tg * 256 + cho * 8) = ov;
}

// ---------------- Depthwise 3x3 conv: sliding window, 4 ch/thread ------------
__global__ void dwconv_kernel(const bf16* __restrict__ h, const float* __restrict__ wdw,
                              const float* __restrict__ bdw, bf16* __restrict__ o) {
    int c4 = threadIdx.x;              // 0..255 (channel quad)
    int y = blockIdx.y & 63;
    int seg = blockIdx.y >> 6;
    int bb = blockIdx.z;
    int c = c4 * 4;
    int x0 = seg * 32;

    float w0[9], w1[9], w2[9], w3[9];
    #pragma unroll
    for (int i = 0; i < 9; ++i) {
        w0[i] = wdw[c * 9 + i];       w1[i] = wdw[(c + 1) * 9 + i];
        w2[i] = wdw[(c + 2) * 9 + i]; w3[i] = wdw[(c + 3) * 9 + i];
    }
    float bb0 = bdw[c], bb1 = bdw[c + 1], bb2 = bdw[c + 2], bb3 = bdw[c + 3];

    const uint2* hp = (const uint2*)h;            // 4 channels per uint2
    size_t base = ((size_t)(bb << 13) + y * 128) * 256 + c4;   // row stride 256 uint2
    bool hu = (y > 0), hd = (y < 63);
    uint2 zero = {0u, 0u};

    uint2 cm[3], cc[3], cn[3];
    {
        size_t p = base + ((x0 + 127) & 127) * 256;
        cm[0] = hu ? hp[p - 32768] : zero; cm[1] = hp[p]; cm[2] = hd ? hp[p + 32768] : zero;
        p = base + x0 * 256;
        cc[0] = hu ? hp[p - 32768] : zero; cc[1] = hp[p]; cc[2] = hd ? hp[p + 32768] : zero;
    }
    bf16* op = o + ((size_t)(bb << 13) + y * 128) * 1024 + c;

    for (int x = x0; x < x0 + 32; ++x) {
        size_t p = base + ((x + 1) & 127) * 256;
        cn[0] = hu ? hp[p - 32768] : zero; cn[1] = hp[p]; cn[2] = hd ? hp[p + 32768] : zero;

        float a0 = bb0, a1 = bb1, a2 = bb2, a3 = bb3;
        #pragma unroll
        for (int dy = 0; dy < 3; ++dy) {
            float2 ma = __bfloat1622float2(*(__nv_bfloat162*)&cm[dy].x);
            float2 mb = __bfloat1622float2(*(__nv_bfloat162*)&cm[dy].y);
            float2 ca = __bfloat1622float2(*(__nv_bfloat162*)&cc[dy].x);
            float2 cbv = __bfloat1622float2(*(__nv_bfloat162*)&cc[dy].y);
            float2 na = __bfloat1622float2(*(__nv_bfloat162*)&cn[dy].x);
            float2 nb = __bfloat1622float2(*(__nv_bfloat162*)&cn[dy].y);
            a0 += ma.x * w0[dy * 3 + 0] + ca.x  * w0[dy * 3 + 1] + na.x * w0[dy * 3 + 2];
            a1 += ma.y * w1[dy * 3 + 0] + ca.y  * w1[dy * 3 + 1] + na.y * w1[dy * 3 + 2];
            a2 += mb.x * w2[dy * 3 + 0] + cbv.x * w2[dy * 3 + 1] + nb.x * w2[dy * 3 + 2];
            a3 += mb.y * w3[dy * 3 + 0] + cbv.y * w3[dy * 3 + 1] + nb.y * w3[dy * 3 + 2];
        }
        __nv_bfloat162 o0 = {__float2bfloat16(gelu_f(a0)), __float2bfloat16(gelu_f(a1))};
        __nv_bfloat162 o1 = {__float2bfloat16(gelu_f(a2)), __float2bfloat16(gelu_f(a3))};
        uint2 ov = {*(uint32_t*)&o0, *(uint32_t*)&o1};
        *(uint2*)(op + (size_t)x * 1024) = ov;

        #pragma unroll
        for (int i = 0; i < 3; ++i) { cm[i] = cc[i]; cc[i] = cn[i]; }
    }
}

// ---------------- launch ----------------
extern "C" void kernel_launch(void* const* d_in, const int* in_sizes, int n_in,
                              void* d_out, int out_size) {
    const float* x      = (const float*)d_in[0];
    const float* rp     = (const float*)d_in[1];
    const float* ln1_g  = (const float*)d_in[2];
    const float* ln1_b  = (const float*)d_in[3];
    const float* w_v    = (const float*)d_in[4];
    const float* b_v    = (const float*)d_in[5];
    const float* w_off  = (const float*)d_in[6];
    const float* b_off  = (const float*)d_in[7];
    const float* w_attn = (const float*)d_in[8];
    const float* b_attn = (const float*)d_in[9];
    const float* w_out  = (const float*)d_in[10];
    const float* b_out  = (const float*)d_in[11];
    const float* ln2_g  = (const float*)d_in[12];
    const float* ln2_b  = (const float*)d_in[13];
    const float* w1     = (const float*)d_in[14];
    const float* b1     = (const float*)d_in[15];
    const float* w_dw   = (const float*)d_in[16];
    const float* b_dw   = (const float*)d_in[17];
    const float* w2     = (const float*)d_in[18];
    const float* b2     = (const float*)d_in[19];
    float* out = (float*)d_out;

    float *xn, *offattn, *xres, *wcat, *bcat;
    bf16 *xnb, *vb, *aggb, *yb, *hb, *h2b, *wvb, *woutb, *w1b, *w2b;
    cudaGetSymbolAddress((void**)&xn,      g_xn);
    cudaGetSymbolAddress((void**)&offattn, g_offattn);
    cudaGetSymbolAddress((void**)&xres,    g_xres);
    cudaGetSymbolAddress((void**)&wcat,    g_wcat);
    cudaGetSymbolAddress((void**)&bcat,    g_bcat);
    cudaGetSymbolAddress((void**)&xnb,     g_xnb);
    cudaGetSymbolAddress((void**)&vb,      g_vb);
    cudaGetSymbolAddress((void**)&aggb,    g_aggb);
    cudaGetSymbolAddress((void**)&yb,      g_yb);
    cudaGetSymbolAddress((void**)&hb,      g_hb);
    cudaGetSymbolAddress((void**)&h2b,     g_h2b);
    cudaGetSymbolAddress((void**)&wvb,     g_wvb);
    cudaGetSymbolAddress((void**)&woutb,   g_woutb);
    cudaGetSymbolAddress((void**)&w1b,     g_w1b);
    cudaGetSymbolAddress((void**)&w2b,     g_w2b);

    cudaFuncSetAttribute(hgemm_kernel<1>, cudaFuncAttributeMaxDynamicSharedMemorySize, PSMEM);
    cudaFuncSetAttribute(hgemm_kernel<2>, cudaFuncAttributeMaxDynamicSharedMemorySize, PSMEM);
    cudaFuncSetAttribute(fused_k2,        cudaFuncAttributeMaxDynamicSharedMemorySize, H64_SMEM);
    cudaFuncSetAttribute(hgemm_wout_ln,   cudaFuncAttributeMaxDynamicSharedMemorySize, QSMEM);

    // K1: LN1 (2 tok/block, vectorized) || weight prep
    prep_ln_kernel<<<LN_BLOCKS + 2816, 256>>>(
        x, ln1_g, ln1_b, xn, xnb,
        w_v, w_out, w1, w2, w_off, w_attn, b_off, b_attn,
        wvb, woutb, w1b, w2b, wcat, bcat);
    // K2: v projection || offsets+attn
    fused_k2<<<dim3(2, NTOK / 64, 2), 256, H64_SMEM>>>(
        xnb, wvb, b_v, vb, xn, wcat, bcat, offattn);
    // K3: softmax + bilinear sampling + aggregation (1 token/warp, 16B gathers)
    sample_kernel<<<NTOK / 8, 256>>>(vb, offattn, rp, aggb);
    // K4: output proj + residual + LN2 fused
    hgemm_wout_ln<<<NTOK / QBM, 256, QSMEM>>>(aggb, woutb, b_out, x, xres, ln2_g, ln2_b, yb);
    // K5: fc1 + GELU
    hgemm_kernel<1><<<dim3(HID / PBN, NTOK / PBM), 256, PSMEM>>>(yb, w1b, b1, nullptr, hb, HID, 256);
    // K6: depthwise conv + GELU (4 ch/thread, 8B loads)
    dwconv_kernel<<<dim3(1, 256, 2), 256>>>(hb, w_dw, b_dw, h2b);
    // K7: fc2 + residual -> out
    hgemm_kernel<2><<<dim3(256 / PBN, NTOK / PBM), 256, PSMEM>>>(h2b, w2b, b2, xres, out, 256, 1024);
}